// round 5
// baseline (speedup 1.0000x reference)
#include <cuda_runtime.h>
#include <cstdint>

// ---------------- problem constants ----------------
#define BATCH 4
#define SEQ   8192
#define DMODEL 512
#define HEADS 8
#define DH    64
#define LM    256
#define LGRP  32
#define NTOK  (BATCH*SEQ)
#define BH    (BATCH*HEADS)
#define KSZ   33
#define NCHUNK 8

// ---------------- scratch ----------------
__device__ float g_xn   [(size_t)NTOK*DMODEL];
__device__ float g_q    [(size_t)BH*SEQ*DH];
__device__ float g_k    [(size_t)BH*SEQ*DH];
__device__ float g_v    [(size_t)BH*SEQ*DH];
__device__ float g_ql   [(size_t)BH*LM*DH];
__device__ float g_kl   [(size_t)BH*LM*DH];
__device__ float g_attn2[(size_t)BH*LM*LM];
__device__ float g_za   [(size_t)BH*LM*LM];
__device__ float g_zb   [(size_t)BH*LM*LM];
__device__ float g_xz   [(size_t)BH*LM*LM];
__device__ float g_t1   [(size_t)BH*LM*LM];
__device__ float g_t2   [(size_t)BH*LM*LM];
__device__ float g_a3v  [(size_t)BH*LM*DH];
__device__ float g_zav  [(size_t)BH*LM*DH];
__device__ float g_outh [(size_t)BH*SEQ*DH];
__device__ float g_tok  [(size_t)NTOK*DMODEL];
__device__ float g_pacc [(size_t)BH*NCHUNK*LM*DH];
__device__ float g_pmax [(size_t)BH*NCHUNK*LM];
__device__ float g_psum [(size_t)BH*NCHUNK*LM];
__device__ float g_scale[2];

// ---------------- helpers ----------------
__device__ __forceinline__ void mma_tf32(float* c, const unsigned* a, const unsigned* b) {
    asm volatile(
        "mma.sync.aligned.m16n8k8.row.col.f32.tf32.tf32.f32 "
        "{%0,%1,%2,%3},{%4,%5,%6,%7},{%8,%9},{%0,%1,%2,%3};"
        : "+f"(c[0]), "+f"(c[1]), "+f"(c[2]), "+f"(c[3])
        : "r"(a[0]), "r"(a[1]), "r"(a[2]), "r"(a[3]), "r"(b[0]), "r"(b[1]));
}

__device__ __forceinline__ void cpa16(float* s, const float* g) {
    unsigned sa = (unsigned)__cvta_generic_to_shared(s);
    asm volatile("cp.async.cg.shared.global [%0], [%1], 16;" :: "r"(sa), "l"(g));
}
#define CP_COMMIT() asm volatile("cp.async.commit_group;")
#define CP_WAIT1()  asm volatile("cp.async.wait_group 1;")
#define CP_WAIT0()  asm volatile("cp.async.wait_group 0;")

__device__ __forceinline__ unsigned fu(float f) { return __float_as_uint(f); }

// ---------------- LayerNorm ----------------
__global__ void ln_kernel(const float* __restrict__ x, const float* __restrict__ w,
                          const float* __restrict__ b, float* __restrict__ y)
{
    int row = blockIdx.x;
    int tid = threadIdx.x;
    const float* xr = x + (long long)row * DMODEL;
    float4 v = *(const float4*)(xr + tid * 4);
    float s  = v.x + v.y + v.z + v.w;
    float s2 = v.x*v.x + v.y*v.y + v.z*v.z + v.w*v.w;
    __shared__ float r1[128], r2[128];
    r1[tid] = s; r2[tid] = s2; __syncthreads();
    for (int t = 64; t > 0; t >>= 1) {
        if (tid < t) { r1[tid] += r1[tid+t]; r2[tid] += r2[tid+t]; }
        __syncthreads();
    }
    float mean = r1[0] * (1.0f / DMODEL);
    float var  = r2[0] * (1.0f / DMODEL) - mean * mean;
    float inv  = rsqrtf(var + 1e-5f);
    float4 w4 = *(const float4*)(w + tid * 4);
    float4 b4 = *(const float4*)(b + tid * 4);
    float4 o;
    o.x = (v.x - mean) * inv * w4.x + b4.x;
    o.y = (v.y - mean) * inv * w4.y + b4.y;
    o.z = (v.z - mean) * inv * w4.z + b4.z;
    o.w = (v.w - mean) * inv * w4.w + b4.w;
    *(float4*)(y + (long long)row * DMODEL + tid * 4) = o;
}

// ---------------- tensor-core GEMM, cp.async double-buffered ----------------
template<int BM, int BN, int WARPS_M, int WARPS_N, bool TB, int MODE>
__global__ void __launch_bounds__(32*WARPS_M*WARPS_N) gemm_tc(
    const float* __restrict__ A, const float* __restrict__ B, float* __restrict__ C,
    int M, int N, int K, long long sA, long long sB, long long sC,
    float alpha, float betaI, const float* __restrict__ bias, const float* __restrict__ resid,
    float* __restrict__ C2, float beta2,
    float* __restrict__ Qp, float* __restrict__ Kp, float* __restrict__ Vp)
{
    constexpr int BK  = 16;
    constexpr int NTH = 32 * WARPS_M * WARPS_N;
    constexpr int WM  = BM / WARPS_M;
    constexpr int WN  = BN / WARPS_N;
    constexpr int MT  = WM / 16;
    constexpr int NT  = WN / 8;
    constexpr int SA  = BM * 20;
    constexpr int SB  = TB ? BN * 20 : BK * (BN + 8);
    constexpr int AC  = BM * 4 / NTH;
    constexpr int BC  = TB ? BN * 4 / NTH : (BK * BN / 4) / NTH;

    const int z = blockIdx.z;
    A += z * sA; B += z * sB;
    if (C)  C  += z * sC;
    if (C2) C2 += z * sC;
    if (resid) resid += z * sC;

    __shared__ float smem[2 * (SA + SB)];

    const int tid  = threadIdx.x;
    const int w    = tid >> 5, lane = tid & 31;
    const int g    = lane >> 2, t = lane & 3;
    const int wm   = (w / WARPS_N) * WM;
    const int wn   = (w % WARPS_N) * WN;
    const int m0   = blockIdx.y * BM;
    const int n0   = blockIdx.x * BN;

    float acc[MT][NT][4];
#pragma unroll
    for (int i = 0; i < MT; i++)
#pragma unroll
        for (int j = 0; j < NT; j++)
#pragma unroll
            for (int r = 0; r < 4; r++) acc[i][j][r] = 0.f;

    auto load_stage = [&](int st, int k0) {
        float* as = smem + st * (SA + SB);
        float* bs = as + SA;
#pragma unroll
        for (int it = 0; it < AC; ++it) {
            int idx = it * NTH + tid;
            int r = idx >> 2, ch = (idx & 3) << 2;
            cpa16(as + r * 20 + ch, A + (long long)(m0 + r) * K + k0 + ch);
        }
        if (TB) {
#pragma unroll
            for (int it = 0; it < BC; ++it) {
                int idx = it * NTH + tid;
                int r = idx >> 2, ch = (idx & 3) << 2;
                cpa16(bs + r * 20 + ch, B + (long long)(n0 + r) * K + k0 + ch);
            }
        } else {
#pragma unroll
            for (int it = 0; it < BC; ++it) {
                int idx = it * NTH + tid;
                int kr = idx / (BN / 4), c = (idx % (BN / 4)) << 2;
                cpa16(bs + kr * (BN + 8) + c, B + (long long)(k0 + kr) * N + n0 + c);
            }
        }
    };

    const int nk = K / BK;
    load_stage(0, 0);
    CP_COMMIT();

    for (int kt = 0; kt < nk; ++kt) {
        if (kt + 1 < nk) {
            load_stage((kt + 1) & 1, (kt + 1) * BK);
            CP_COMMIT();
            CP_WAIT1();
        } else {
            CP_WAIT0();
        }
        __syncthreads();
        const float* as = smem + (kt & 1) * (SA + SB);
        const float* bs = as + SA;
#pragma unroll
        for (int ks = 0; ks < 2; ++ks) {
            const int kb = ks * 8;
            unsigned af[MT][4], bf[NT][2];
#pragma unroll
            for (int i = 0; i < MT; i++) {
                int mb = wm + i * 16;
                af[i][0] = fu(as[(mb + g) * 20 + kb + t]);
                af[i][1] = fu(as[(mb + 8 + g) * 20 + kb + t]);
                af[i][2] = fu(as[(mb + g) * 20 + kb + t + 4]);
                af[i][3] = fu(as[(mb + 8 + g) * 20 + kb + t + 4]);
            }
#pragma unroll
            for (int j = 0; j < NT; j++) {
                int nb = wn + j * 8 + g;
                if (TB) {
                    bf[j][0] = fu(bs[nb * 20 + kb + t]);
                    bf[j][1] = fu(bs[nb * 20 + kb + t + 4]);
                } else {
                    bf[j][0] = fu(bs[(kb + t) * (BN + 8) + nb]);
                    bf[j][1] = fu(bs[(kb + t + 4) * (BN + 8) + nb]);
                }
            }
#pragma unroll
            for (int i = 0; i < MT; i++)
#pragma unroll
                for (int j = 0; j < NT; j++)
                    mma_tf32(acc[i][j], af[i], bf[j]);
        }
        __syncthreads();
    }

    // epilogue
#pragma unroll
    for (int i = 0; i < MT; i++) {
        int gm = m0 + wm + i * 16 + g;
#pragma unroll
        for (int j = 0; j < NT; j++) {
            int gn = n0 + wn + j * 8 + 2 * t;
            float v00 = alpha * acc[i][j][0];
            float v01 = alpha * acc[i][j][1];
            float v10 = alpha * acc[i][j][2];
            float v11 = alpha * acc[i][j][3];
            if (MODE == 1) {
                int which = gn >> 9;
                int h = (gn >> 6) & 7;
                int c = gn & 63;
                float sc = (which == 0) ? 0.125f : 1.f;
                float* tgt = (which == 0) ? Qp : ((which == 1) ? Kp : Vp);
                int b0i = gm >> 13, i0i = gm & (SEQ - 1);
                int b1i = (gm + 8) >> 13, i1i = (gm + 8) & (SEQ - 1);
                long long d0 = (((long long)(b0i * HEADS + h)) * SEQ + i0i) * DH + c;
                long long d1 = (((long long)(b1i * HEADS + h)) * SEQ + i1i) * DH + c;
                *(float2*)(tgt + d0) = make_float2(v00 * sc, v01 * sc);
                *(float2*)(tgt + d1) = make_float2(v10 * sc, v11 * sc);
            } else {
                if (bias) {
                    v00 += bias[gn]; v01 += bias[gn + 1];
                    v10 += bias[gn]; v11 += bias[gn + 1];
                }
                if (resid) {
                    v00 += resid[(long long)gm * N + gn];
                    v01 += resid[(long long)gm * N + gn + 1];
                    v10 += resid[(long long)(gm + 8) * N + gn];
                    v11 += resid[(long long)(gm + 8) * N + gn + 1];
                }
                if (betaI != 0.f) {
                    if (gm == gn)         v00 += betaI;
                    if (gm == gn + 1)     v01 += betaI;
                    if (gm + 8 == gn)     v10 += betaI;
                    if (gm + 8 == gn + 1) v11 += betaI;
                }
                *(float2*)(C + (long long)gm * N + gn)       = make_float2(v00, v01);
                *(float2*)(C + (long long)(gm + 8) * N + gn) = make_float2(v10, v11);
                if (MODE == 2) {
                    float w00 = ((gm == gn)         ? beta2 : 0.f) - v00;
                    float w01 = ((gm == gn + 1)     ? beta2 : 0.f) - v01;
                    float w10 = ((gm + 8 == gn)     ? beta2 : 0.f) - v10;
                    float w11 = ((gm + 8 == gn + 1) ? beta2 : 0.f) - v11;
                    *(float2*)(C2 + (long long)gm * N + gn)       = make_float2(w00, w01);
                    *(float2*)(C2 + (long long)(gm + 8) * N + gn) = make_float2(w10, w11);
                }
            }
        }
    }
}

// ---------------- fused softmax(A@B^T)@C, cp.async double-buffered ----------
#define SAV_SMEM_FLOATS (64*68 + 2*64*68 + 2*64*72)
template<bool FINAL>
__global__ void __launch_bounds__(256) fused_sav(
    const float* __restrict__ A, const float* __restrict__ B, const float* __restrict__ C,
    float* __restrict__ OUT, float* __restrict__ PMAX, float* __restrict__ PSUM,
    int M_total, int N_total, int chunk_len)
{
    extern __shared__ float fs[];
    float* Qs = fs;
    float* Ks = fs + 64*68;
    float* Vs = Ks + 2*64*68;
    float* macc = Qs;
    float* wmax = Qs + 64*64;
    float* wsum = Qs + 64*64 + 128;

    const int bh = blockIdx.z, mt = blockIdx.x, ck = blockIdx.y;
    const int m0 = mt * 64;
    const int tid = threadIdx.x;
    const int w = tid >> 5, lane = tid & 31;
    const int g = lane >> 2, t = lane & 3;
    const int wm = (w >> 1) * 16;
    const int wni = w & 1;
    const int wn = wni * 32;

    const float* Ap = A + ((long long)bh * M_total + m0) * DH;
    const float* Bb = B + (long long)bh * N_total * DH;
    const float* Cb = C + (long long)bh * N_total * DH;

#pragma unroll
    for (int it = 0; it < 4; ++it) {
        int idx = it * 256 + tid;
        int r = idx >> 4, c = (idx & 15) << 2;
        *(float4*)(Qs + r * 68 + c) = *(const float4*)(Ap + r * DH + c);
    }

    const int n_start = ck * chunk_len;

    auto load_kv = [&](int st, int nb) {
        const float* Kp = Bb + (long long)(n_start + nb) * DH;
        const float* Vp = Cb + (long long)(n_start + nb) * DH;
        float* ks = Ks + st * 64 * 68;
        float* vs = Vs + st * 64 * 72;
#pragma unroll
        for (int it = 0; it < 4; ++it) {
            int idx = it * 256 + tid;
            int r = idx >> 4, c = (idx & 15) << 2;
            cpa16(ks + r * 68 + c, Kp + r * DH + c);
        }
#pragma unroll
        for (int it = 0; it < 4; ++it) {
            int idx = it * 256 + tid;
            int r = idx >> 4, c = (idx & 15) << 2;
            cpa16(vs + r * 72 + c, Vp + r * DH + c);
        }
    };

    float acc2[8][4];
#pragma unroll
    for (int nt = 0; nt < 8; ++nt)
#pragma unroll
        for (int r = 0; r < 4; ++r) acc2[nt][r] = 0.f;
    float rmax0 = -1e30f, rmax1 = -1e30f, rsum0 = 0.f, rsum1 = 0.f;

    const int srcA = (lane & ~3) | (t >> 1);
    const int srcB = srcA + 2;
    const bool hi = t & 1;

    load_kv(0, 0);
    CP_COMMIT();

    const int nt_iters = chunk_len / 64;
    for (int itn = 0; itn < nt_iters; ++itn) {
        if (itn + 1 < nt_iters) {
            load_kv((itn + 1) & 1, (itn + 1) * 64);
            CP_COMMIT();
            CP_WAIT1();
        } else {
            CP_WAIT0();
        }
        __syncthreads();
        const float* ks = Ks + (itn & 1) * 64 * 68;
        const float* vs = Vs + (itn & 1) * 64 * 72;

        float sacc[4][4];
#pragma unroll
        for (int j = 0; j < 4; ++j)
#pragma unroll
            for (int r = 0; r < 4; ++r) sacc[j][r] = 0.f;
#pragma unroll
        for (int kk0 = 0; kk0 < 8; ++kk0) {
            int kb = kk0 * 8;
            unsigned af[4];
            af[0] = fu(Qs[(wm + g) * 68 + kb + t]);
            af[1] = fu(Qs[(wm + 8 + g) * 68 + kb + t]);
            af[2] = fu(Qs[(wm + g) * 68 + kb + t + 4]);
            af[3] = fu(Qs[(wm + 8 + g) * 68 + kb + t + 4]);
#pragma unroll
            for (int j = 0; j < 4; ++j) {
                int nbq = wn + j * 8 + g;
                unsigned bf[2];
                bf[0] = fu(ks[nbq * 68 + kb + t]);
                bf[1] = fu(ks[nbq * 68 + kb + t + 4]);
                mma_tf32(sacc[j], af, bf);
            }
        }
        float tm0 = -1e30f, tm1 = -1e30f;
#pragma unroll
        for (int j = 0; j < 4; ++j) {
            tm0 = fmaxf(tm0, fmaxf(sacc[j][0], sacc[j][1]));
            tm1 = fmaxf(tm1, fmaxf(sacc[j][2], sacc[j][3]));
        }
        tm0 = fmaxf(tm0, __shfl_xor_sync(0xffffffffu, tm0, 1));
        tm0 = fmaxf(tm0, __shfl_xor_sync(0xffffffffu, tm0, 2));
        tm1 = fmaxf(tm1, __shfl_xor_sync(0xffffffffu, tm1, 1));
        tm1 = fmaxf(tm1, __shfl_xor_sync(0xffffffffu, tm1, 2));
        float nm0 = fmaxf(rmax0, tm0), nm1 = fmaxf(rmax1, tm1);
        float sc0 = __expf(rmax0 - nm0), sc1 = __expf(rmax1 - nm1);
        float ts0 = 0.f, ts1 = 0.f;
#pragma unroll
        for (int j = 0; j < 4; ++j) {
            sacc[j][0] = __expf(sacc[j][0] - nm0);
            sacc[j][1] = __expf(sacc[j][1] - nm0);
            sacc[j][2] = __expf(sacc[j][2] - nm1);
            sacc[j][3] = __expf(sacc[j][3] - nm1);
            ts0 += sacc[j][0] + sacc[j][1];
            ts1 += sacc[j][2] + sacc[j][3];
        }
        ts0 += __shfl_xor_sync(0xffffffffu, ts0, 1);
        ts0 += __shfl_xor_sync(0xffffffffu, ts0, 2);
        ts1 += __shfl_xor_sync(0xffffffffu, ts1, 1);
        ts1 += __shfl_xor_sync(0xffffffffu, ts1, 2);
        rsum0 = rsum0 * sc0 + ts0;
        rsum1 = rsum1 * sc1 + ts1;
        rmax0 = nm0; rmax1 = nm1;
#pragma unroll
        for (int nt = 0; nt < 8; ++nt) {
            acc2[nt][0] *= sc0; acc2[nt][1] *= sc0;
            acc2[nt][2] *= sc1; acc2[nt][3] *= sc1;
        }
#pragma unroll
        for (int j2 = 0; j2 < 4; ++j2) {
            unsigned p0 = fu(sacc[j2][0]), p1 = fu(sacc[j2][1]);
            unsigned p2 = fu(sacc[j2][2]), p3 = fu(sacc[j2][3]);
            unsigned a0a = __shfl_sync(0xffffffffu, p0, srcA);
            unsigned a0b = __shfl_sync(0xffffffffu, p1, srcA);
            unsigned a1a = __shfl_sync(0xffffffffu, p2, srcA);
            unsigned a1b = __shfl_sync(0xffffffffu, p3, srcA);
            unsigned a2a = __shfl_sync(0xffffffffu, p0, srcB);
            unsigned a2b = __shfl_sync(0xffffffffu, p1, srcB);
            unsigned a3a = __shfl_sync(0xffffffffu, p2, srcB);
            unsigned a3b = __shfl_sync(0xffffffffu, p3, srcB);
            unsigned af2[4];
            af2[0] = hi ? a0b : a0a;
            af2[1] = hi ? a1b : a1a;
            af2[2] = hi ? a2b : a2a;
            af2[3] = hi ? a3b : a3a;
            int kb = wn + j2 * 8;
#pragma unroll
            for (int nt = 0; nt < 8; ++nt) {
                unsigned bf[2];
                bf[0] = fu(vs[(kb + t) * 72 + nt * 8 + g]);
                bf[1] = fu(vs[(kb + t + 4) * 72 + nt * 8 + g]);
                mma_tf32(acc2[nt], af2, bf);
            }
        }
        __syncthreads();
    }

    if (t == 0) {
        wmax[wni*64 + wm + g]     = rmax0;
        wmax[wni*64 + wm + 8 + g] = rmax1;
        wsum[wni*64 + wm + g]     = rsum0;
        wsum[wni*64 + wm + 8 + g] = rsum1;
    }
    __syncthreads();
    int other = wni ^ 1;
    float om0 = wmax[other*64 + wm + g],     os0 = wsum[other*64 + wm + g];
    float om1 = wmax[other*64 + wm + 8 + g], os1 = wsum[other*64 + wm + 8 + g];
    float gm0 = fmaxf(rmax0, om0), gm1 = fmaxf(rmax1, om1);
    float f0 = __expf(rmax0 - gm0), f1 = __expf(rmax1 - gm1);
    float gs0 = rsum0 * f0 + os0 * __expf(om0 - gm0);
    float gs1 = rsum1 * f1 + os1 * __expf(om1 - gm1);
#pragma unroll
    for (int nt = 0; nt < 8; ++nt) {
        acc2[nt][0] *= f0; acc2[nt][1] *= f0;
        acc2[nt][2] *= f1; acc2[nt][3] *= f1;
    }
    __syncthreads();
    if (wni == 1) {
#pragma unroll
        for (int nt = 0; nt < 8; ++nt) {
            *(float2*)&macc[(wm + g)*64 + nt*8 + 2*t]     = make_float2(acc2[nt][0], acc2[nt][1]);
            *(float2*)&macc[(wm + 8 + g)*64 + nt*8 + 2*t] = make_float2(acc2[nt][2], acc2[nt][3]);
        }
    }
    __syncthreads();
    if (wni == 0) {
        int row0 = m0 + wm + g, row1 = row0 + 8;
        if (FINAL) {
            float inv0 = 1.f / gs0, inv1 = 1.f / gs1;
            float* O = OUT + (long long)bh * M_total * DH;
#pragma unroll
            for (int nt = 0; nt < 8; ++nt) {
                int cc = nt*8 + 2*t;
                float2 m0v = *(float2*)&macc[(wm + g)*64 + cc];
                float2 m1v = *(float2*)&macc[(wm + 8 + g)*64 + cc];
                *(float2*)(O + (long long)row0 * DH + cc) =
                    make_float2((acc2[nt][0] + m0v.x) * inv0, (acc2[nt][1] + m0v.y) * inv0);
                *(float2*)(O + (long long)row1 * DH + cc) =
                    make_float2((acc2[nt][2] + m1v.x) * inv1, (acc2[nt][3] + m1v.y) * inv1);
            }
        } else {
            long long pb = ((long long)bh * NCHUNK + ck) * M_total;
            float* O = OUT + pb * DH;
#pragma unroll
            for (int nt = 0; nt < 8; ++nt) {
                int cc = nt*8 + 2*t;
                float2 m0v = *(float2*)&macc[(wm + g)*64 + cc];
                float2 m1v = *(float2*)&macc[(wm + 8 + g)*64 + cc];
                *(float2*)(O + (long long)row0 * DH + cc) =
                    make_float2(acc2[nt][0] + m0v.x, acc2[nt][1] + m0v.y);
                *(float2*)(O + (long long)row1 * DH + cc) =
                    make_float2(acc2[nt][2] + m1v.x, acc2[nt][3] + m1v.y);
            }
            if (t == 0) {
                PMAX[pb + row0] = gm0; PMAX[pb + row1] = gm1;
                PSUM[pb + row0] = gs0; PSUM[pb + row1] = gs1;
            }
        }
    }
}

// ---------------- combine chunk partials -> a3v ----------------
__global__ void sav_combine(const float* __restrict__ pacc, const float* __restrict__ pmax,
                            const float* __restrict__ psum, float* __restrict__ out)
{
    int idx = blockIdx.x * 256 + threadIdx.x;
    int d = idx & 63;
    int m = (idx >> 6) & (LM - 1);
    int bh = idx >> 14;
    float gmax = -1e30f;
#pragma unroll
    for (int ck = 0; ck < NCHUNK; ++ck)
        gmax = fmaxf(gmax, pmax[((long long)bh * NCHUNK + ck) * LM + m]);
    float gsum = 0.f, val = 0.f;
#pragma unroll
    for (int ck = 0; ck < NCHUNK; ++ck) {
        long long pb = ((long long)bh * NCHUNK + ck) * LM + m;
        float f = __expf(pmax[pb] - gmax);
        gsum += psum[pb] * f;
        val  += pacc[pb * DH + d] * f;
    }
    out[idx] = val / gsum;
}

// ---------------- landmark means (Q and K in one launch) ----------------
__global__ void landmark2(const float* __restrict__ Q, const float* __restrict__ K,
                          float* __restrict__ QL, float* __restrict__ KL)
{
    const float* src = blockIdx.y ? K : Q;
    float* dst = blockIdx.y ? KL : QL;
    int idx = blockIdx.x * 256 + threadIdx.x;
    int c  = idx & 63;
    int m  = (idx >> 6) & 255;
    int bh = idx >> 14;
    const float* p = src + ((long long)bh * SEQ + m * LGRP) * DH + c;
    float s = 0.f;
#pragma unroll
    for (int t = 0; t < LGRP; ++t) s += p[t * DH];
    dst[idx] = s * (1.f / LGRP);
}

// ---------------- row softmax (256-wide rows) ----------------
__global__ void softmax_rows(float* __restrict__ S)
{
    float* row = S + (long long)blockIdx.x * 256;
    int tid = threadIdx.x;
    float v = row[tid];
    __shared__ float red[256];
    red[tid] = v; __syncthreads();
    for (int t = 128; t > 0; t >>= 1) {
        if (tid < t) red[tid] = fmaxf(red[tid], red[tid + t]);
        __syncthreads();
    }
    float mx = red[0]; __syncthreads();
    v = __expf(v - mx);
    red[tid] = v; __syncthreads();
    for (int t = 128; t > 0; t >>= 1) {
        if (tid < t) red[tid] += red[tid + t];
        __syncthreads();
    }
    row[tid] = v / red[0];
}

// ---------------- pinv scale ----------------
__global__ void scale_init(float* s) { s[0] = 0.f; s[1] = 0.f; }

__global__ void colrow_max(const float* __restrict__ A2, float* __restrict__ s)
{
    int bh = blockIdx.x, j = threadIdx.x;
    const float* X = A2 + (long long)bh * LM * LM;
    float cs = 0.f, rs = 0.f;
    for (int i = 0; i < LM; ++i) {
        cs += fabsf(X[i * LM + j]);
        rs += fabsf(X[j * LM + i]);
    }
    __shared__ float r1[256], r2[256];
    r1[j] = cs; r2[j] = rs; __syncthreads();
    for (int t = 128; t > 0; t >>= 1) {
        if (j < t) { r1[j] = fmaxf(r1[j], r1[j+t]); r2[j] = fmaxf(r2[j], r2[j+t]); }
        __syncthreads();
    }
    if (j == 0) {
        atomicMax((int*)&s[0], __float_as_int(r1[0]));
        atomicMax((int*)&s[1], __float_as_int(r2[0]));
    }
}

__global__ void make_z0(const float* __restrict__ A2, const float* __restrict__ s,
                        float* __restrict__ Z)
{
    long long idx = (long long)blockIdx.x * 256 + threadIdx.x;
    int c  = idx & 255;
    int r  = (int)((idx >> 8) & 255);
    int bh = (int)(idx >> 16);
    float inv = 1.f / (s[0] * s[1]);
    Z[idx] = A2[(long long)bh * LM * LM + (long long)c * LM + r] * inv;
}

// ---------------- conv + combine ----------------
__global__ void __launch_bounds__(256) conv_combine(
    const float* __restrict__ V, const float* __restrict__ O,
    const float* __restrict__ cw, float* __restrict__ TOK)
{
    int bh = blockIdx.y;
    int h = bh & 7, b = bh >> 3;
    int i0 = blockIdx.x * 64;
    __shared__ float sv[96][64];
    __shared__ float w[KSZ];
    int tid = threadIdx.x;
    if (tid < KSZ) w[tid] = cw[h * KSZ + tid];
    const float* Vb = V + (long long)bh * SEQ * DH;
    for (int e = tid; e < 96 * 64; e += 256) {
        int rr = e >> 6, c = e & 63;
        int gi = i0 - 16 + rr;
        sv[rr][c] = (gi >= 0 && gi < SEQ) ? Vb[(long long)gi * DH + c] : 0.f;
    }
    __syncthreads();
    int c  = tid & 63;
    int ib = tid >> 6;
#pragma unroll 4
    for (int j = 0; j < 16; ++j) {
        int il = ib * 16 + j;
        float acc = O[((long long)bh * SEQ + i0 + il) * DH + c];
#pragma unroll
        for (int t = 0; t < KSZ; ++t) acc += w[t] * sv[il + t][c];
        long long tok = (long long)b * SEQ + i0 + il;
        TOK[tok * DMODEL + h * DH + c] = acc;
    }
}

// ---------------- host driver ----------------
extern "C" void kernel_launch(void* const* d_in, const int* in_sizes, int n_in,
                              void* d_out, int out_size)
{
    const float* x      = (const float*)d_in[0];
    const float* ln_w   = (const float*)d_in[1];
    const float* ln_b   = (const float*)d_in[2];
    const float* w_qkv  = (const float*)d_in[3];
    const float* w_out  = (const float*)d_in[4];
    const float* b_out  = (const float*)d_in[5];
    const float* conv_w = (const float*)d_in[6];
    float* out = (float*)d_out;

    // one-time stream/event resources (no device memory involved)
    static cudaStream_t s1 = nullptr;
    static cudaEvent_t evFork = nullptr, evJoin = nullptr;
    if (s1 == nullptr) {
        cudaStreamCreateWithFlags(&s1, cudaStreamNonBlocking);
        cudaEventCreateWithFlags(&evFork, cudaEventDisableTiming);
        cudaEventCreateWithFlags(&evJoin, cudaEventDisableTiming);
    }

    void *p;
    cudaGetSymbolAddress(&p, g_xn);    float* xn  = (float*)p;
    cudaGetSymbolAddress(&p, g_q);     float* Q   = (float*)p;
    cudaGetSymbolAddress(&p, g_k);     float* K   = (float*)p;
    cudaGetSymbolAddress(&p, g_v);     float* V   = (float*)p;
    cudaGetSymbolAddress(&p, g_ql);    float* QL  = (float*)p;
    cudaGetSymbolAddress(&p, g_kl);    float* KL  = (float*)p;
    cudaGetSymbolAddress(&p, g_attn2); float* A2  = (float*)p;
    cudaGetSymbolAddress(&p, g_za);    float* ZA  = (float*)p;
    cudaGetSymbolAddress(&p, g_zb);    float* ZB  = (float*)p;
    cudaGetSymbolAddress(&p, g_xz);    float* XZ  = (float*)p;
    cudaGetSymbolAddress(&p, g_t1);    float* T1  = (float*)p;
    cudaGetSymbolAddress(&p, g_t2);    float* T2  = (float*)p;
    cudaGetSymbolAddress(&p, g_a3v);   float* A3V = (float*)p;
    cudaGetSymbolAddress(&p, g_zav);   float* ZAV = (float*)p;
    cudaGetSymbolAddress(&p, g_outh);  float* OH  = (float*)p;
    cudaGetSymbolAddress(&p, g_tok);   float* TOK = (float*)p;
    cudaGetSymbolAddress(&p, g_pacc);  float* PAC = (float*)p;
    cudaGetSymbolAddress(&p, g_pmax);  float* PMX = (float*)p;
    cudaGetSymbolAddress(&p, g_psum);  float* PSM = (float*)p;
    cudaGetSymbolAddress(&p, g_scale); float* S   = (float*)p;

    const long long sL  = (long long)LM * DH;
    const long long sA2 = (long long)LM * LM;

    const int sav_smem = SAV_SMEM_FLOATS * 4;
    cudaFuncSetAttribute(fused_sav<true>,  cudaFuncAttributeMaxDynamicSharedMemorySize, sav_smem);
    cudaFuncSetAttribute(fused_sav<false>, cudaFuncAttributeMaxDynamicSharedMemorySize, sav_smem);

    // ---- common prefix (legacy stream) ----
    ln_kernel<<<NTOK, 128>>>(x, ln_w, ln_b, xn);
    gemm_tc<128,128,2,4,true,1><<<dim3(12, 256, 1), 256>>>(xn, w_qkv, nullptr,
        NTOK, 3*DMODEL, DMODEL, 0, 0, 0, 1.f, 0.f, nullptr, nullptr, nullptr, 0.f, Q, K, V);
    landmark2<<<dim3((BH*LM*DH)/256, 2), 256>>>(Q, K, QL, KL);
    scale_init<<<1, 1>>>(S);

    // ---- fork: branch B (a3v flash) on s1 ----
    cudaEventRecord(evFork, 0);
    cudaStreamWaitEvent(s1, evFork, 0);
    fused_sav<false><<<dim3(LM/64, NCHUNK, BH), 256, sav_smem, s1>>>(QL, K, V,
        PAC, PMX, PSM, LM, SEQ, SEQ/NCHUNK);
    sav_combine<<<(BH*LM*DH)/256, 256, 0, s1>>>(PAC, PMX, PSM, A3V);
    cudaEventRecord(evJoin, s1);

    // ---- branch A (pinv chain) on legacy stream ----
    gemm_tc<64,64,2,2,true,0><<<dim3(4, 4, BH), 128>>>(QL, KL, A2,
        LM, LM, DH, sL, sL, sA2, 1.f, 0.f, nullptr, nullptr, nullptr, 0.f, nullptr, nullptr, nullptr);
    softmax_rows<<<BH*LM, 256>>>(A2);
    colrow_max<<<BH, 256>>>(A2, S);
    make_z0<<<(BH*LM*LM)/256, 256>>>(A2, S, ZA);
    float* Zin = ZA; float* Zout = ZB;
    for (int it = 0; it < 6; ++it) {
        gemm_tc<64,64,2,2,false,2><<<dim3(4,4,BH), 128>>>(A2, Zin, XZ,
            LM, LM, LM, sA2, sA2, sA2, 1.f, 0.f, nullptr, nullptr, T1, 7.f, nullptr, nullptr, nullptr);
        gemm_tc<64,64,2,2,false,0><<<dim3(4,4,BH), 128>>>(XZ, T1, T2,
            LM, LM, LM, sA2, sA2, sA2, -1.f, 15.f, nullptr, nullptr, nullptr, 0.f, nullptr, nullptr, nullptr);
        gemm_tc<64,64,2,2,false,0><<<dim3(4,4,BH), 128>>>(XZ, T2, T1,
            LM, LM, LM, sA2, sA2, sA2, -1.f, 13.f, nullptr, nullptr, nullptr, 0.f, nullptr, nullptr, nullptr);
        gemm_tc<64,64,2,2,false,0><<<dim3(4,4,BH), 128>>>(Zin, T1, Zout,
            LM, LM, LM, sA2, sA2, sA2, 0.25f, 0.f, nullptr, nullptr, nullptr, 0.f, nullptr, nullptr, nullptr);
        float* tmp = Zin; Zin = Zout; Zout = tmp;
    }

    // ---- join ----
    cudaStreamWaitEvent(0, evJoin, 0);
    gemm_tc<64,64,2,2,false,0><<<dim3(1, 4, BH), 128>>>(Zin, A3V, ZAV,
        LM, DH, LM, sA2, sL, sL, 1.f, 0.f, nullptr, nullptr, nullptr, 0.f, nullptr, nullptr, nullptr);
    fused_sav<true><<<dim3(SEQ/64, 1, BH), 256, sav_smem>>>(Q, KL, ZAV,
        OH, nullptr, nullptr, SEQ, LM, LM);
    conv_combine<<<dim3(SEQ/64, BH), 256>>>(V, OH, conv_w, TOK);
    gemm_tc<128,128,2,4,true,0><<<dim3(4, 256, 1), 256>>>(TOK, w_out, out,
        NTOK, DMODEL, DMODEL, 0, 0, 0, 1.f, 0.f, b_out, x, nullptr, 0.f, nullptr, nullptr, nullptr);
}

// round 6
// speedup vs baseline: 1.0524x; 1.0524x over previous
#include <cuda_runtime.h>
#include <cstdint>

// ---------------- problem constants ----------------
#define BATCH 4
#define SEQ   8192
#define DMODEL 512
#define HEADS 8
#define DH    64
#define LM    256
#define LGRP  32
#define NTOK  (BATCH*SEQ)
#define BH    (BATCH*HEADS)
#define KSZ   33
#define NCHUNK 8
#define NGRP  (NTOK/LGRP)      // 1024 landmark groups total

// ---------------- scratch ----------------
__device__ float g_xn   [(size_t)NTOK*DMODEL];
__device__ float g_xnl  [(size_t)NGRP*DMODEL];
__device__ float g_q    [(size_t)BH*SEQ*DH];
__device__ float g_k    [(size_t)BH*SEQ*DH];
__device__ float g_v    [(size_t)BH*SEQ*DH];
__device__ float g_ql   [(size_t)BH*LM*DH];
__device__ float g_kl   [(size_t)BH*LM*DH];
__device__ float g_attn2[(size_t)BH*LM*LM];
__device__ float g_za   [(size_t)BH*LM*LM];
__device__ float g_zb   [(size_t)BH*LM*LM];
__device__ float g_xz   [(size_t)BH*LM*LM];
__device__ float g_t1   [(size_t)BH*LM*LM];
__device__ float g_t2   [(size_t)BH*LM*LM];
__device__ float g_a3v  [(size_t)BH*LM*DH];
__device__ float g_zav  [(size_t)BH*LM*DH];
__device__ float g_outh [(size_t)BH*SEQ*DH];
__device__ float g_tok  [(size_t)NTOK*DMODEL];
__device__ float g_pacc [(size_t)BH*NCHUNK*LM*DH];
__device__ float g_pmax [(size_t)BH*NCHUNK*LM];
__device__ float g_psum [(size_t)BH*NCHUNK*LM];
__device__ float g_scale[64];

// ---------------- helpers ----------------
__device__ __forceinline__ void mma_tf32(float* c, const unsigned* a, const unsigned* b) {
    asm volatile(
        "mma.sync.aligned.m16n8k8.row.col.f32.tf32.tf32.f32 "
        "{%0,%1,%2,%3},{%4,%5,%6,%7},{%8,%9},{%0,%1,%2,%3};"
        : "+f"(c[0]), "+f"(c[1]), "+f"(c[2]), "+f"(c[3])
        : "r"(a[0]), "r"(a[1]), "r"(a[2]), "r"(a[3]), "r"(b[0]), "r"(b[1]));
}

__device__ __forceinline__ void cpa16(float* s, const float* g) {
    unsigned sa = (unsigned)__cvta_generic_to_shared(s);
    asm volatile("cp.async.cg.shared.global [%0], [%1], 16;" :: "r"(sa), "l"(g));
}
#define CP_COMMIT() asm volatile("cp.async.commit_group;")
#define CP_WAIT1()  asm volatile("cp.async.wait_group 1;")
#define CP_WAIT0()  asm volatile("cp.async.wait_group 0;")

__device__ __forceinline__ unsigned fu(float f) { return __float_as_uint(f); }

// ---------------- LayerNorm ----------------
__global__ void ln_kernel(const float* __restrict__ x, const float* __restrict__ w,
                          const float* __restrict__ b, float* __restrict__ y)
{
    int row = blockIdx.x;
    int tid = threadIdx.x;
    const float* xr = x + (long long)row * DMODEL;
    float4 v = *(const float4*)(xr + tid * 4);
    float s  = v.x + v.y + v.z + v.w;
    float s2 = v.x*v.x + v.y*v.y + v.z*v.z + v.w*v.w;
    __shared__ float r1[128], r2[128];
    r1[tid] = s; r2[tid] = s2; __syncthreads();
    for (int t = 64; t > 0; t >>= 1) {
        if (tid < t) { r1[tid] += r1[tid+t]; r2[tid] += r2[tid+t]; }
        __syncthreads();
    }
    float mean = r1[0] * (1.0f / DMODEL);
    float var  = r2[0] * (1.0f / DMODEL) - mean * mean;
    float inv  = rsqrtf(var + 1e-5f);
    float4 w4 = *(const float4*)(w + tid * 4);
    float4 b4 = *(const float4*)(b + tid * 4);
    float4 o;
    o.x = (v.x - mean) * inv * w4.x + b4.x;
    o.y = (v.y - mean) * inv * w4.y + b4.y;
    o.z = (v.z - mean) * inv * w4.z + b4.z;
    o.w = (v.w - mean) * inv * w4.w + b4.w;
    *(float4*)(y + (long long)row * DMODEL + tid * 4) = o;
}

// ---------------- group mean over 32 consecutive tokens ----------------
__global__ void group_mean(const float* __restrict__ xn, float* __restrict__ xnl)
{
    int g = blockIdx.x;                 // 0..NGRP-1
    int tid = threadIdx.x;              // 128 threads x 4 cols
    const float* p = xn + (long long)g * LGRP * DMODEL + tid * 4;
    float4 s = make_float4(0.f, 0.f, 0.f, 0.f);
#pragma unroll
    for (int i = 0; i < LGRP; ++i) {
        float4 v = *(const float4*)(p + (long long)i * DMODEL);
        s.x += v.x; s.y += v.y; s.z += v.z; s.w += v.w;
    }
    const float inv = 1.f / LGRP;
    s.x *= inv; s.y *= inv; s.z *= inv; s.w *= inv;
    *(float4*)(xnl + (long long)g * DMODEL + tid * 4) = s;
}

// ---------------- tensor-core GEMM, cp.async 3-stage pipeline ----------------
// MODE 0: C = alpha*A@op(B) + betaI*I (+bias) (+resid)
// MODE 1: qkv split epilogue -> Qp,Kp,Vp head-major (Q scaled by 0.125)
// MODE 2: C = alpha*A@op(B); C2 = beta2*I - C
// MODE 3: ql/kl split epilogue (N=1024): cols 0-511 -> Qp (x0.125), 512-1023 -> Kp
template<int BM, int BN, int WARPS_M, int WARPS_N, bool TB, int MODE>
__global__ void __launch_bounds__(32*WARPS_M*WARPS_N) gemm_tc(
    const float* __restrict__ A, const float* __restrict__ B, float* __restrict__ C,
    int M, int N, int K, long long sA, long long sB, long long sC,
    float alpha, float betaI, const float* __restrict__ bias, const float* __restrict__ resid,
    float* __restrict__ C2, float beta2,
    float* __restrict__ Qp, float* __restrict__ Kp, float* __restrict__ Vp)
{
    constexpr int BK  = 16;
    constexpr int NTH = 32 * WARPS_M * WARPS_N;
    constexpr int WM  = BM / WARPS_M;
    constexpr int WN  = BN / WARPS_N;
    constexpr int MT  = WM / 16;
    constexpr int NT  = WN / 8;
    constexpr int SA  = BM * 20;
    constexpr int SB  = TB ? BN * 20 : BK * (BN + 8);
    constexpr int AC  = BM * 4 / NTH;
    constexpr int BC  = TB ? BN * 4 / NTH : (BK * BN / 4) / NTH;

    const int z = blockIdx.z;
    A += z * sA; B += z * sB;
    if (C)  C  += z * sC;
    if (C2) C2 += z * sC;
    if (resid) resid += z * sC;

    __shared__ float smem[3 * (SA + SB)];

    const int tid  = threadIdx.x;
    const int w    = tid >> 5, lane = tid & 31;
    const int g    = lane >> 2, t = lane & 3;
    const int wm   = (w / WARPS_N) * WM;
    const int wn   = (w % WARPS_N) * WN;
    const int m0   = blockIdx.y * BM;
    const int n0   = blockIdx.x * BN;

    float acc[MT][NT][4];
#pragma unroll
    for (int i = 0; i < MT; i++)
#pragma unroll
        for (int j = 0; j < NT; j++)
#pragma unroll
            for (int r = 0; r < 4; r++) acc[i][j][r] = 0.f;

    auto load_stage = [&](int st, int k0) {
        float* as = smem + st * (SA + SB);
        float* bs = as + SA;
#pragma unroll
        for (int it = 0; it < AC; ++it) {
            int idx = it * NTH + tid;
            int r = idx >> 2, ch = (idx & 3) << 2;
            cpa16(as + r * 20 + ch, A + (long long)(m0 + r) * K + k0 + ch);
        }
        if (TB) {
#pragma unroll
            for (int it = 0; it < BC; ++it) {
                int idx = it * NTH + tid;
                int r = idx >> 2, ch = (idx & 3) << 2;
                cpa16(bs + r * 20 + ch, B + (long long)(n0 + r) * K + k0 + ch);
            }
        } else {
#pragma unroll
            for (int it = 0; it < BC; ++it) {
                int idx = it * NTH + tid;
                int kr = idx / (BN / 4), c = (idx % (BN / 4)) << 2;
                cpa16(bs + kr * (BN + 8) + c, B + (long long)(k0 + kr) * N + n0 + c);
            }
        }
    };

    const int nk = K / BK;
    load_stage(0, 0);
    CP_COMMIT();
    if (nk > 1) { load_stage(1, BK); CP_COMMIT(); }

    for (int kt = 0; kt < nk; ++kt) {
        if (kt + 2 < nk) {
            CP_WAIT1();
            __syncthreads();
            load_stage((kt + 2) % 3, (kt + 2) * BK);
            CP_COMMIT();
        } else if (kt + 1 < nk) {
            CP_WAIT1();
            __syncthreads();
        } else {
            CP_WAIT0();
            __syncthreads();
        }
        const float* as = smem + (kt % 3) * (SA + SB);
        const float* bs = as + SA;
#pragma unroll
        for (int ks = 0; ks < 2; ++ks) {
            const int kb = ks * 8;
            unsigned af[MT][4], bf[NT][2];
#pragma unroll
            for (int i = 0; i < MT; i++) {
                int mb = wm + i * 16;
                af[i][0] = fu(as[(mb + g) * 20 + kb + t]);
                af[i][1] = fu(as[(mb + 8 + g) * 20 + kb + t]);
                af[i][2] = fu(as[(mb + g) * 20 + kb + t + 4]);
                af[i][3] = fu(as[(mb + 8 + g) * 20 + kb + t + 4]);
            }
#pragma unroll
            for (int j = 0; j < NT; j++) {
                int nb = wn + j * 8 + g;
                if (TB) {
                    bf[j][0] = fu(bs[nb * 20 + kb + t]);
                    bf[j][1] = fu(bs[nb * 20 + kb + t + 4]);
                } else {
                    bf[j][0] = fu(bs[(kb + t) * (BN + 8) + nb]);
                    bf[j][1] = fu(bs[(kb + t + 4) * (BN + 8) + nb]);
                }
            }
#pragma unroll
            for (int i = 0; i < MT; i++)
#pragma unroll
                for (int j = 0; j < NT; j++)
                    mma_tf32(acc[i][j], af[i], bf[j]);
        }
    }

    // epilogue
#pragma unroll
    for (int i = 0; i < MT; i++) {
        int gm = m0 + wm + i * 16 + g;
#pragma unroll
        for (int j = 0; j < NT; j++) {
            int gn = n0 + wn + j * 8 + 2 * t;
            float v00 = alpha * acc[i][j][0];
            float v01 = alpha * acc[i][j][1];
            float v10 = alpha * acc[i][j][2];
            float v11 = alpha * acc[i][j][3];
            if (MODE == 1) {
                int which = gn >> 9;
                int h = (gn >> 6) & 7;
                int c = gn & 63;
                float sc = (which == 0) ? 0.125f : 1.f;
                float* tgt = (which == 0) ? Qp : ((which == 1) ? Kp : Vp);
                int b0i = gm >> 13, i0i = gm & (SEQ - 1);
                int b1i = (gm + 8) >> 13, i1i = (gm + 8) & (SEQ - 1);
                long long d0 = (((long long)(b0i * HEADS + h)) * SEQ + i0i) * DH + c;
                long long d1 = (((long long)(b1i * HEADS + h)) * SEQ + i1i) * DH + c;
                *(float2*)(tgt + d0) = make_float2(v00 * sc, v01 * sc);
                *(float2*)(tgt + d1) = make_float2(v10 * sc, v11 * sc);
            } else if (MODE == 3) {
                int which = gn >> 9;           // 0 = QL, 1 = KL
                int h = (gn >> 6) & 7;
                int c = gn & 63;
                float sc = (which == 0) ? 0.125f : 1.f;
                float* tgt = (which == 0) ? Qp : Kp;
                int b0i = gm >> 8, m0i = gm & 255;
                int b1i = (gm + 8) >> 8, m1i = (gm + 8) & 255;
                long long d0 = (((long long)(b0i * HEADS + h)) * LM + m0i) * DH + c;
                long long d1 = (((long long)(b1i * HEADS + h)) * LM + m1i) * DH + c;
                *(float2*)(tgt + d0) = make_float2(v00 * sc, v01 * sc);
                *(float2*)(tgt + d1) = make_float2(v10 * sc, v11 * sc);
            } else {
                if (bias) {
                    v00 += bias[gn]; v01 += bias[gn + 1];
                    v10 += bias[gn]; v11 += bias[gn + 1];
                }
                if (resid) {
                    v00 += resid[(long long)gm * N + gn];
                    v01 += resid[(long long)gm * N + gn + 1];
                    v10 += resid[(long long)(gm + 8) * N + gn];
                    v11 += resid[(long long)(gm + 8) * N + gn + 1];
                }
                if (betaI != 0.f) {
                    if (gm == gn)         v00 += betaI;
                    if (gm == gn + 1)     v01 += betaI;
                    if (gm + 8 == gn)     v10 += betaI;
                    if (gm + 8 == gn + 1) v11 += betaI;
                }
                *(float2*)(C + (long long)gm * N + gn)       = make_float2(v00, v01);
                *(float2*)(C + (long long)(gm + 8) * N + gn) = make_float2(v10, v11);
                if (MODE == 2) {
                    float w00 = ((gm == gn)         ? beta2 : 0.f) - v00;
                    float w01 = ((gm == gn + 1)     ? beta2 : 0.f) - v01;
                    float w10 = ((gm + 8 == gn)     ? beta2 : 0.f) - v10;
                    float w11 = ((gm + 8 == gn + 1) ? beta2 : 0.f) - v11;
                    *(float2*)(C2 + (long long)gm * N + gn)       = make_float2(w00, w01);
                    *(float2*)(C2 + (long long)(gm + 8) * N + gn) = make_float2(w10, w11);
                }
            }
        }
    }
}

// ---------------- fused softmax(A@B^T)@C, cp.async double-buffered ----------
#define SAV_SMEM_FLOATS (64*68 + 2*64*68 + 2*64*72)
template<bool FINAL>
__global__ void __launch_bounds__(256) fused_sav(
    const float* __restrict__ A, const float* __restrict__ B, const float* __restrict__ C,
    float* __restrict__ OUT, float* __restrict__ PMAX, float* __restrict__ PSUM,
    int M_total, int N_total, int chunk_len)
{
    extern __shared__ float fs[];
    float* Qs = fs;
    float* Ks = fs + 64*68;
    float* Vs = Ks + 2*64*68;
    float* macc = Qs;
    float* wmax = Qs + 64*64;
    float* wsum = Qs + 64*64 + 128;

    const int bh = blockIdx.z, mt = blockIdx.x, ck = blockIdx.y;
    const int m0 = mt * 64;
    const int tid = threadIdx.x;
    const int w = tid >> 5, lane = tid & 31;
    const int g = lane >> 2, t = lane & 3;
    const int wm = (w >> 1) * 16;
    const int wni = w & 1;
    const int wn = wni * 32;

    const float* Ap = A + ((long long)bh * M_total + m0) * DH;
    const float* Bb = B + (long long)bh * N_total * DH;
    const float* Cb = C + (long long)bh * N_total * DH;

#pragma unroll
    for (int it = 0; it < 4; ++it) {
        int idx = it * 256 + tid;
        int r = idx >> 4, c = (idx & 15) << 2;
        *(float4*)(Qs + r * 68 + c) = *(const float4*)(Ap + r * DH + c);
    }

    const int n_start = ck * chunk_len;

    auto load_kv = [&](int st, int nb) {
        const float* Kp = Bb + (long long)(n_start + nb) * DH;
        const float* Vp = Cb + (long long)(n_start + nb) * DH;
        float* ks = Ks + st * 64 * 68;
        float* vs = Vs + st * 64 * 72;
#pragma unroll
        for (int it = 0; it < 4; ++it) {
            int idx = it * 256 + tid;
            int r = idx >> 4, c = (idx & 15) << 2;
            cpa16(ks + r * 68 + c, Kp + r * DH + c);
        }
#pragma unroll
        for (int it = 0; it < 4; ++it) {
            int idx = it * 256 + tid;
            int r = idx >> 4, c = (idx & 15) << 2;
            cpa16(vs + r * 72 + c, Vp + r * DH + c);
        }
    };

    float acc2[8][4];
#pragma unroll
    for (int nt = 0; nt < 8; ++nt)
#pragma unroll
        for (int r = 0; r < 4; ++r) acc2[nt][r] = 0.f;
    float rmax0 = -1e30f, rmax1 = -1e30f, rsum0 = 0.f, rsum1 = 0.f;

    const int srcA = (lane & ~3) | (t >> 1);
    const int srcB = srcA + 2;
    const bool hi = t & 1;

    load_kv(0, 0);
    CP_COMMIT();

    const int nt_iters = chunk_len / 64;
    for (int itn = 0; itn < nt_iters; ++itn) {
        if (itn + 1 < nt_iters) {
            load_kv((itn + 1) & 1, (itn + 1) * 64);
            CP_COMMIT();
            CP_WAIT1();
        } else {
            CP_WAIT0();
        }
        __syncthreads();
        const float* ks = Ks + (itn & 1) * 64 * 68;
        const float* vs = Vs + (itn & 1) * 64 * 72;

        float sacc[4][4];
#pragma unroll
        for (int j = 0; j < 4; ++j)
#pragma unroll
            for (int r = 0; r < 4; ++r) sacc[j][r] = 0.f;
#pragma unroll
        for (int kk0 = 0; kk0 < 8; ++kk0) {
            int kb = kk0 * 8;
            unsigned af[4];
            af[0] = fu(Qs[(wm + g) * 68 + kb + t]);
            af[1] = fu(Qs[(wm + 8 + g) * 68 + kb + t]);
            af[2] = fu(Qs[(wm + g) * 68 + kb + t + 4]);
            af[3] = fu(Qs[(wm + 8 + g) * 68 + kb + t + 4]);
#pragma unroll
            for (int j = 0; j < 4; ++j) {
                int nbq = wn + j * 8 + g;
                unsigned bf[2];
                bf[0] = fu(ks[nbq * 68 + kb + t]);
                bf[1] = fu(ks[nbq * 68 + kb + t + 4]);
                mma_tf32(sacc[j], af, bf);
            }
        }
        float tm0 = -1e30f, tm1 = -1e30f;
#pragma unroll
        for (int j = 0; j < 4; ++j) {
            tm0 = fmaxf(tm0, fmaxf(sacc[j][0], sacc[j][1]));
            tm1 = fmaxf(tm1, fmaxf(sacc[j][2], sacc[j][3]));
        }
        tm0 = fmaxf(tm0, __shfl_xor_sync(0xffffffffu, tm0, 1));
        tm0 = fmaxf(tm0, __shfl_xor_sync(0xffffffffu, tm0, 2));
        tm1 = fmaxf(tm1, __shfl_xor_sync(0xffffffffu, tm1, 1));
        tm1 = fmaxf(tm1, __shfl_xor_sync(0xffffffffu, tm1, 2));
        float nm0 = fmaxf(rmax0, tm0), nm1 = fmaxf(rmax1, tm1);
        float sc0 = __expf(rmax0 - nm0), sc1 = __expf(rmax1 - nm1);
        float ts0 = 0.f, ts1 = 0.f;
#pragma unroll
        for (int j = 0; j < 4; ++j) {
            sacc[j][0] = __expf(sacc[j][0] - nm0);
            sacc[j][1] = __expf(sacc[j][1] - nm0);
            sacc[j][2] = __expf(sacc[j][2] - nm1);
            sacc[j][3] = __expf(sacc[j][3] - nm1);
            ts0 += sacc[j][0] + sacc[j][1];
            ts1 += sacc[j][2] + sacc[j][3];
        }
        ts0 += __shfl_xor_sync(0xffffffffu, ts0, 1);
        ts0 += __shfl_xor_sync(0xffffffffu, ts0, 2);
        ts1 += __shfl_xor_sync(0xffffffffu, ts1, 1);
        ts1 += __shfl_xor_sync(0xffffffffu, ts1, 2);
        rsum0 = rsum0 * sc0 + ts0;
        rsum1 = rsum1 * sc1 + ts1;
        rmax0 = nm0; rmax1 = nm1;
#pragma unroll
        for (int nt = 0; nt < 8; ++nt) {
            acc2[nt][0] *= sc0; acc2[nt][1] *= sc0;
            acc2[nt][2] *= sc1; acc2[nt][3] *= sc1;
        }
#pragma unroll
        for (int j2 = 0; j2 < 4; ++j2) {
            unsigned p0 = fu(sacc[j2][0]), p1 = fu(sacc[j2][1]);
            unsigned p2 = fu(sacc[j2][2]), p3 = fu(sacc[j2][3]);
            unsigned a0a = __shfl_sync(0xffffffffu, p0, srcA);
            unsigned a0b = __shfl_sync(0xffffffffu, p1, srcA);
            unsigned a1a = __shfl_sync(0xffffffffu, p2, srcA);
            unsigned a1b = __shfl_sync(0xffffffffu, p3, srcA);
            unsigned a2a = __shfl_sync(0xffffffffu, p0, srcB);
            unsigned a2b = __shfl_sync(0xffffffffu, p1, srcB);
            unsigned a3a = __shfl_sync(0xffffffffu, p2, srcB);
            unsigned a3b = __shfl_sync(0xffffffffu, p3, srcB);
            unsigned af2[4];
            af2[0] = hi ? a0b : a0a;
            af2[1] = hi ? a1b : a1a;
            af2[2] = hi ? a2b : a2a;
            af2[3] = hi ? a3b : a3a;
            int kb = wn + j2 * 8;
#pragma unroll
            for (int nt = 0; nt < 8; ++nt) {
                unsigned bf[2];
                bf[0] = fu(vs[(kb + t) * 72 + nt * 8 + g]);
                bf[1] = fu(vs[(kb + t + 4) * 72 + nt * 8 + g]);
                mma_tf32(acc2[nt], af2, bf);
            }
        }
        __syncthreads();
    }

    if (t == 0) {
        wmax[wni*64 + wm + g]     = rmax0;
        wmax[wni*64 + wm + 8 + g] = rmax1;
        wsum[wni*64 + wm + g]     = rsum0;
        wsum[wni*64 + wm + 8 + g] = rsum1;
    }
    __syncthreads();
    int other = wni ^ 1;
    float om0 = wmax[other*64 + wm + g],     os0 = wsum[other*64 + wm + g];
    float om1 = wmax[other*64 + wm + 8 + g], os1 = wsum[other*64 + wm + 8 + g];
    float gm0 = fmaxf(rmax0, om0), gm1 = fmaxf(rmax1, om1);
    float f0 = __expf(rmax0 - gm0), f1 = __expf(rmax1 - gm1);
    float gs0 = rsum0 * f0 + os0 * __expf(om0 - gm0);
    float gs1 = rsum1 * f1 + os1 * __expf(om1 - gm1);
#pragma unroll
    for (int nt = 0; nt < 8; ++nt) {
        acc2[nt][0] *= f0; acc2[nt][1] *= f0;
        acc2[nt][2] *= f1; acc2[nt][3] *= f1;
    }
    __syncthreads();
    if (wni == 1) {
#pragma unroll
        for (int nt = 0; nt < 8; ++nt) {
            *(float2*)&macc[(wm + g)*64 + nt*8 + 2*t]     = make_float2(acc2[nt][0], acc2[nt][1]);
            *(float2*)&macc[(wm + 8 + g)*64 + nt*8 + 2*t] = make_float2(acc2[nt][2], acc2[nt][3]);
        }
    }
    __syncthreads();
    if (wni == 0) {
        int row0 = m0 + wm + g, row1 = row0 + 8;
        if (FINAL) {
            float inv0 = 1.f / gs0, inv1 = 1.f / gs1;
            float* O = OUT + (long long)bh * M_total * DH;
#pragma unroll
            for (int nt = 0; nt < 8; ++nt) {
                int cc = nt*8 + 2*t;
                float2 m0v = *(float2*)&macc[(wm + g)*64 + cc];
                float2 m1v = *(float2*)&macc[(wm + 8 + g)*64 + cc];
                *(float2*)(O + (long long)row0 * DH + cc) =
                    make_float2((acc2[nt][0] + m0v.x) * inv0, (acc2[nt][1] + m0v.y) * inv0);
                *(float2*)(O + (long long)row1 * DH + cc) =
                    make_float2((acc2[nt][2] + m1v.x) * inv1, (acc2[nt][3] + m1v.y) * inv1);
            }
        } else {
            long long pb = ((long long)bh * NCHUNK + ck) * M_total;
            float* O = OUT + pb * DH;
#pragma unroll
            for (int nt = 0; nt < 8; ++nt) {
                int cc = nt*8 + 2*t;
                float2 m0v = *(float2*)&macc[(wm + g)*64 + cc];
                float2 m1v = *(float2*)&macc[(wm + 8 + g)*64 + cc];
                *(float2*)(O + (long long)row0 * DH + cc) =
                    make_float2(acc2[nt][0] + m0v.x, acc2[nt][1] + m0v.y);
                *(float2*)(O + (long long)row1 * DH + cc) =
                    make_float2(acc2[nt][2] + m1v.x, acc2[nt][3] + m1v.y);
            }
            if (t == 0) {
                PMAX[pb + row0] = gm0; PMAX[pb + row1] = gm1;
                PSUM[pb + row0] = gs0; PSUM[pb + row1] = gs1;
            }
        }
    }
}

// ---------------- combine chunk partials -> a3v ----------------
__global__ void sav_combine(const float* __restrict__ pacc, const float* __restrict__ pmax,
                            const float* __restrict__ psum, float* __restrict__ out)
{
    int idx = blockIdx.x * 256 + threadIdx.x;
    int d = idx & 63;
    int m = (idx >> 6) & (LM - 1);
    int bh = idx >> 14;
    float gmax = -1e30f;
#pragma unroll
    for (int ck = 0; ck < NCHUNK; ++ck)
        gmax = fmaxf(gmax, pmax[((long long)bh * NCHUNK + ck) * LM + m]);
    float gsum = 0.f, val = 0.f;
#pragma unroll
    for (int ck = 0; ck < NCHUNK; ++ck) {
        long long pb = ((long long)bh * NCHUNK + ck) * LM + m;
        float f = __expf(pmax[pb] - gmax);
        gsum += psum[pb] * f;
        val  += pacc[pb * DH + d] * f;
    }
    out[idx] = val / gsum;
}

// ---------------- row softmax (256-wide rows) ----------------
__global__ void softmax_rows(float* __restrict__ S)
{
    float* row = S + (long long)blockIdx.x * 256;
    int tid = threadIdx.x;
    float v = row[tid];
    __shared__ float red[256];
    red[tid] = v; __syncthreads();
    for (int t = 128; t > 0; t >>= 1) {
        if (tid < t) red[tid] = fmaxf(red[tid], red[tid + t]);
        __syncthreads();
    }
    float mx = red[0]; __syncthreads();
    v = __expf(v - mx);
    red[tid] = v; __syncthreads();
    for (int t = 128; t > 0; t >>= 1) {
        if (tid < t) red[tid] += red[tid + t];
        __syncthreads();
    }
    row[tid] = v / red[0];
}

// ---------------- pinv scale: per-bh col/row abs-sum maxima ----------------
__global__ void colrow_max(const float* __restrict__ A2, float* __restrict__ s)
{
    int bh = blockIdx.x, j = threadIdx.x;
    const float* X = A2 + (long long)bh * LM * LM;
    float cs = 0.f, rs = 0.f;
    for (int i = 0; i < LM; ++i) {
        cs += fabsf(X[i * LM + j]);
        rs += fabsf(X[j * LM + i]);
    }
    __shared__ float r1[256], r2[256];
    r1[j] = cs; r2[j] = rs; __syncthreads();
    for (int t = 128; t > 0; t >>= 1) {
        if (j < t) { r1[j] = fmaxf(r1[j], r1[j+t]); r2[j] = fmaxf(r2[j], r2[j+t]); }
        __syncthreads();
    }
    if (j == 0) { s[bh] = r1[0]; s[32 + bh] = r2[0]; }
}

__global__ void make_z0(const float* __restrict__ A2, const float* __restrict__ s,
                        float* __restrict__ Z)
{
    __shared__ float red[64];
    int tid = threadIdx.x;
    if (tid < 64) red[tid] = s[tid];
    __syncthreads();
    float cm = red[0], rm = red[32];
#pragma unroll
    for (int i = 1; i < 32; ++i) { cm = fmaxf(cm, red[i]); rm = fmaxf(rm, red[32 + i]); }
    float inv = 1.f / (cm * rm);
    long long idx = (long long)blockIdx.x * 256 + tid;
    int c  = idx & 255;
    int r  = (int)((idx >> 8) & 255);
    int bh = (int)(idx >> 16);
    Z[idx] = A2[(long long)bh * LM * LM + (long long)c * LM + r] * inv;
}

// ---------------- conv + combine ----------------
__global__ void __launch_bounds__(256) conv_combine(
    const float* __restrict__ V, const float* __restrict__ O,
    const float* __restrict__ cw, float* __restrict__ TOK)
{
    int bh = blockIdx.y;
    int h = bh & 7, b = bh >> 3;
    int i0 = blockIdx.x * 64;
    __shared__ float sv[96][64];
    __shared__ float w[KSZ];
    int tid = threadIdx.x;
    if (tid < KSZ) w[tid] = cw[h * KSZ + tid];
    const float* Vb = V + (long long)bh * SEQ * DH;
    for (int e = tid; e < 96 * 64; e += 256) {
        int rr = e >> 6, c = e & 63;
        int gi = i0 - 16 + rr;
        sv[rr][c] = (gi >= 0 && gi < SEQ) ? Vb[(long long)gi * DH + c] : 0.f;
    }
    __syncthreads();
    int c  = tid & 63;
    int ib = tid >> 6;
#pragma unroll 4
    for (int j = 0; j < 16; ++j) {
        int il = ib * 16 + j;
        float acc = O[((long long)bh * SEQ + i0 + il) * DH + c];
#pragma unroll
        for (int t = 0; t < KSZ; ++t) acc += w[t] * sv[il + t][c];
        long long tok = (long long)b * SEQ + i0 + il;
        TOK[tok * DMODEL + h * DH + c] = acc;
    }
}

// ---------------- host driver ----------------
extern "C" void kernel_launch(void* const* d_in, const int* in_sizes, int n_in,
                              void* d_out, int out_size)
{
    const float* x      = (const float*)d_in[0];
    const float* ln_w   = (const float*)d_in[1];
    const float* ln_b   = (const float*)d_in[2];
    const float* w_qkv  = (const float*)d_in[3];
    const float* w_out  = (const float*)d_in[4];
    const float* b_out  = (const float*)d_in[5];
    const float* conv_w = (const float*)d_in[6];
    float* out = (float*)d_out;

    static cudaStream_t s1 = nullptr;
    static cudaEvent_t evFork = nullptr, evJoin = nullptr;
    if (s1 == nullptr) {
        cudaStreamCreateWithFlags(&s1, cudaStreamNonBlocking);
        cudaEventCreateWithFlags(&evFork, cudaEventDisableTiming);
        cudaEventCreateWithFlags(&evJoin, cudaEventDisableTiming);
    }

    void *p;
    cudaGetSymbolAddress(&p, g_xn);    float* xn  = (float*)p;
    cudaGetSymbolAddress(&p, g_xnl);   float* XNL = (float*)p;
    cudaGetSymbolAddress(&p, g_q);     float* Q   = (float*)p;
    cudaGetSymbolAddress(&p, g_k);     float* K   = (float*)p;
    cudaGetSymbolAddress(&p, g_v);     float* V   = (float*)p;
    cudaGetSymbolAddress(&p, g_ql);    float* QL  = (float*)p;
    cudaGetSymbolAddress(&p, g_kl);    float* KL  = (float*)p;
    cudaGetSymbolAddress(&p, g_attn2); float* A2  = (float*)p;
    cudaGetSymbolAddress(&p, g_za);    float* ZA  = (float*)p;
    cudaGetSymbolAddress(&p, g_zb);    float* ZB  = (float*)p;
    cudaGetSymbolAddress(&p, g_xz);    float* XZ  = (float*)p;
    cudaGetSymbolAddress(&p, g_t1);    float* T1  = (float*)p;
    cudaGetSymbolAddress(&p, g_t2);    float* T2  = (float*)p;
    cudaGetSymbolAddress(&p, g_a3v);   float* A3V = (float*)p;
    cudaGetSymbolAddress(&p, g_zav);   float* ZAV = (float*)p;
    cudaGetSymbolAddress(&p, g_outh);  float* OH  = (float*)p;
    cudaGetSymbolAddress(&p, g_tok);   float* TOK = (float*)p;
    cudaGetSymbolAddress(&p, g_pacc);  float* PAC = (float*)p;
    cudaGetSymbolAddress(&p, g_pmax);  float* PMX = (float*)p;
    cudaGetSymbolAddress(&p, g_psum);  float* PSM = (float*)p;
    cudaGetSymbolAddress(&p, g_scale); float* S   = (float*)p;

    const long long sL  = (long long)LM * DH;
    const long long sA2 = (long long)LM * LM;

    const int sav_smem = SAV_SMEM_FLOATS * 4;
    cudaFuncSetAttribute(fused_sav<true>,  cudaFuncAttributeMaxDynamicSharedMemorySize, sav_smem);
    cudaFuncSetAttribute(fused_sav<false>, cudaFuncAttributeMaxDynamicSharedMemorySize, sav_smem);

    // ---- prefix (stream 0): LN, group means, QL/KL projection ----
    ln_kernel<<<NTOK, 128>>>(x, ln_w, ln_b, xn);
    group_mean<<<NGRP, 128>>>(xn, XNL);
    gemm_tc<64,64,2,2,true,3><<<dim3(16, 16, 1), 128>>>(XNL, w_qkv, nullptr,
        NGRP, 2*DMODEL, DMODEL, 0, 0, 0, 1.f, 0.f, nullptr, nullptr, nullptr, 0.f, QL, KL, nullptr);

    // ---- fork: branch A (serial pinv chain) on s1 ----
    cudaEventRecord(evFork, 0);
    cudaStreamWaitEvent(s1, evFork, 0);
    gemm_tc<64,64,2,2,true,0><<<dim3(4, 4, BH), 128, 0, s1>>>(QL, KL, A2,
        LM, LM, DH, sL, sL, sA2, 1.f, 0.f, nullptr, nullptr, nullptr, 0.f, nullptr, nullptr, nullptr);
    softmax_rows<<<BH*LM, 256, 0, s1>>>(A2);
    colrow_max<<<BH, 256, 0, s1>>>(A2, S);
    make_z0<<<(BH*LM*LM)/256, 256, 0, s1>>>(A2, S, ZA);
    float* Zin = ZA; float* Zout = ZB;
    for (int it = 0; it < 6; ++it) {
        gemm_tc<64,64,2,2,false,2><<<dim3(4,4,BH), 128, 0, s1>>>(A2, Zin, XZ,
            LM, LM, LM, sA2, sA2, sA2, 1.f, 0.f, nullptr, nullptr, T1, 7.f, nullptr, nullptr, nullptr);
        gemm_tc<64,64,2,2,false,0><<<dim3(4,4,BH), 128, 0, s1>>>(XZ, T1, T2,
            LM, LM, LM, sA2, sA2, sA2, -1.f, 15.f, nullptr, nullptr, nullptr, 0.f, nullptr, nullptr, nullptr);
        gemm_tc<64,64,2,2,false,0><<<dim3(4,4,BH), 128, 0, s1>>>(XZ, T2, T1,
            LM, LM, LM, sA2, sA2, sA2, -1.f, 13.f, nullptr, nullptr, nullptr, 0.f, nullptr, nullptr, nullptr);
        gemm_tc<64,64,2,2,false,0><<<dim3(4,4,BH), 128, 0, s1>>>(Zin, T1, Zout,
            LM, LM, LM, sA2, sA2, sA2, 0.25f, 0.f, nullptr, nullptr, nullptr, 0.f, nullptr, nullptr, nullptr);
        float* tmp = Zin; Zin = Zout; Zout = tmp;
    }
    cudaEventRecord(evJoin, s1);

    // ---- branch B (throughput-bound) on stream 0 ----
    gemm_tc<128,128,2,4,true,1><<<dim3(12, 256, 1), 256>>>(xn, w_qkv, nullptr,
        NTOK, 3*DMODEL, DMODEL, 0, 0, 0, 1.f, 0.f, nullptr, nullptr, nullptr, 0.f, Q, K, V);
    fused_sav<false><<<dim3(LM/64, NCHUNK, BH), 256, sav_smem>>>(QL, K, V,
        PAC, PMX, PSM, LM, SEQ, SEQ/NCHUNK);
    sav_combine<<<(BH*LM*DH)/256, 256>>>(PAC, PMX, PSM, A3V);

    // ---- join ----
    cudaStreamWaitEvent(0, evJoin, 0);
    gemm_tc<64,64,2,2,false,0><<<dim3(1, 4, BH), 128>>>(Zin, A3V, ZAV,
        LM, DH, LM, sA2, sL, sL, 1.f, 0.f, nullptr, nullptr, nullptr, 0.f, nullptr, nullptr, nullptr);
    fused_sav<true><<<dim3(SEQ/64, 1, BH), 256, sav_smem>>>(Q, KL, ZAV,
        OH, nullptr, nullptr, SEQ, LM, LM);
    conv_combine<<<dim3(SEQ/64, BH), 256>>>(V, OH, conv_w, TOK);
    gemm_tc<128,128,2,4,true,0><<<dim3(4, 256, 1), 256>>>(TOK, w_out, out,
        NTOK, DMODEL, DMODEL, 0, 0, 0, 1.f, 0.f, b_out, x, nullptr, 0.f, nullptr, nullptr, nullptr);
}

// round 7
// speedup vs baseline: 1.0892x; 1.0350x over previous
#include <cuda_runtime.h>
#include <cstdint>

// ---------------- problem constants ----------------
#define BATCH 4
#define SEQ   8192
#define DMODEL 512
#define HEADS 8
#define DH    64
#define LM    256
#define LGRP  32
#define NTOK  (BATCH*SEQ)
#define BH    (BATCH*HEADS)
#define KSZ   33
#define NCHUNK 8
#define NGRP  (NTOK/LGRP)

// ---------------- scratch ----------------
__device__ float g_xn   [(size_t)NTOK*DMODEL];
__device__ float g_xnl  [(size_t)NGRP*DMODEL];
__device__ float g_q    [(size_t)BH*SEQ*DH];
__device__ float g_k    [(size_t)BH*SEQ*DH];
__device__ float g_v    [(size_t)BH*SEQ*DH];
__device__ float g_ql   [(size_t)BH*LM*DH];
__device__ float g_kl   [(size_t)BH*LM*DH];
__device__ float g_attn2[(size_t)BH*LM*LM];
__device__ float g_za   [(size_t)BH*LM*LM];
__device__ float g_zb   [(size_t)BH*LM*LM];
__device__ float g_xz   [(size_t)BH*LM*LM];
__device__ float g_t1   [(size_t)BH*LM*LM];
__device__ float g_t2   [(size_t)BH*LM*LM];
__device__ float g_a3v  [(size_t)BH*LM*DH];
__device__ float g_zav  [(size_t)BH*LM*DH];
__device__ float g_tok  [(size_t)NTOK*DMODEL];
__device__ float g_pacc [(size_t)BH*NCHUNK*LM*DH];
__device__ float g_pmax [(size_t)BH*NCHUNK*LM];
__device__ float g_psum [(size_t)BH*NCHUNK*LM];
__device__ float g_scale[64];

// ---------------- helpers ----------------
__device__ __forceinline__ void mma_tf32(float* c, const unsigned* a, const unsigned* b) {
    asm volatile(
        "mma.sync.aligned.m16n8k8.row.col.f32.tf32.tf32.f32 "
        "{%0,%1,%2,%3},{%4,%5,%6,%7},{%8,%9},{%0,%1,%2,%3};"
        : "+f"(c[0]), "+f"(c[1]), "+f"(c[2]), "+f"(c[3])
        : "r"(a[0]), "r"(a[1]), "r"(a[2]), "r"(a[3]), "r"(b[0]), "r"(b[1]));
}

__device__ __forceinline__ void cpa16(float* s, const float* g) {
    unsigned sa = (unsigned)__cvta_generic_to_shared(s);
    asm volatile("cp.async.cg.shared.global [%0], [%1], 16;" :: "r"(sa), "l"(g));
}
#define CP_COMMIT() asm volatile("cp.async.commit_group;")
#define CP_WAIT1()  asm volatile("cp.async.wait_group 1;")
#define CP_WAIT0()  asm volatile("cp.async.wait_group 0;")

__device__ __forceinline__ unsigned fu(float f) { return __float_as_uint(f); }

// ---------------- LayerNorm ----------------
__global__ void ln_kernel(const float* __restrict__ x, const float* __restrict__ w,
                          const float* __restrict__ b, float* __restrict__ y)
{
    int row = blockIdx.x;
    int tid = threadIdx.x;
    const float* xr = x + (long long)row * DMODEL;
    float4 v = *(const float4*)(xr + tid * 4);
    float s  = v.x + v.y + v.z + v.w;
    float s2 = v.x*v.x + v.y*v.y + v.z*v.z + v.w*v.w;
    __shared__ float r1[128], r2[128];
    r1[tid] = s; r2[tid] = s2; __syncthreads();
    for (int t = 64; t > 0; t >>= 1) {
        if (tid < t) { r1[tid] += r1[tid+t]; r2[tid] += r2[tid+t]; }
        __syncthreads();
    }
    float mean = r1[0] * (1.0f / DMODEL);
    float var  = r2[0] * (1.0f / DMODEL) - mean * mean;
    float inv  = rsqrtf(var + 1e-5f);
    float4 w4 = *(const float4*)(w + tid * 4);
    float4 b4 = *(const float4*)(b + tid * 4);
    float4 o;
    o.x = (v.x - mean) * inv * w4.x + b4.x;
    o.y = (v.y - mean) * inv * w4.y + b4.y;
    o.z = (v.z - mean) * inv * w4.z + b4.z;
    o.w = (v.w - mean) * inv * w4.w + b4.w;
    *(float4*)(y + (long long)row * DMODEL + tid * 4) = o;
}

// ---------------- group mean over 32 consecutive tokens ----------------
__global__ void group_mean(const float* __restrict__ xn, float* __restrict__ xnl)
{
    int g = blockIdx.x;
    int tid = threadIdx.x;
    const float* p = xn + (long long)g * LGRP * DMODEL + tid * 4;
    float4 s = make_float4(0.f, 0.f, 0.f, 0.f);
#pragma unroll
    for (int i = 0; i < LGRP; ++i) {
        float4 v = *(const float4*)(p + (long long)i * DMODEL);
        s.x += v.x; s.y += v.y; s.z += v.z; s.w += v.w;
    }
    const float inv = 1.f / LGRP;
    s.x *= inv; s.y *= inv; s.z *= inv; s.w *= inv;
    *(float4*)(xnl + (long long)g * DMODEL + tid * 4) = s;
}

// ---------------- tensor-core GEMM, cp.async 3-stage pipeline ----------------
// MODE 0: C = alpha*A@op(B) + betaI*I (+bias) (+resid)
// MODE 1: qkv split epilogue -> Qp,Kp,Vp head-major (Q scaled by 0.125)
// MODE 2: C = alpha*A@op(B); C2 = beta2*I - C
// MODE 3: ql/kl split epilogue (N=1024): cols 0-511 -> Qp (x0.125), 512-1023 -> Kp
template<int BM, int BN, int WARPS_M, int WARPS_N, bool TB, int MODE>
__global__ void __launch_bounds__(32*WARPS_M*WARPS_N) gemm_tc(
    const float* __restrict__ A, const float* __restrict__ B, float* __restrict__ C,
    int M, int N, int K, long long sA, long long sB, long long sC,
    float alpha, float betaI, const float* __restrict__ bias, const float* __restrict__ resid,
    float* __restrict__ C2, float beta2,
    float* __restrict__ Qp, float* __restrict__ Kp, float* __restrict__ Vp)
{
    constexpr int BK  = 16;
    constexpr int NTH = 32 * WARPS_M * WARPS_N;
    constexpr int WM  = BM / WARPS_M;
    constexpr int WN  = BN / WARPS_N;
    constexpr int MT  = WM / 16;
    constexpr int NT  = WN / 8;
    constexpr int SA  = BM * 20;
    constexpr int SB  = TB ? BN * 20 : BK * (BN + 8);
    constexpr int AC  = BM * 4 / NTH;
    constexpr int BC  = TB ? BN * 4 / NTH : (BK * BN / 4) / NTH;

    const int z = blockIdx.z;
    A += z * sA; B += z * sB;
    if (C)  C  += z * sC;
    if (C2) C2 += z * sC;
    if (resid) resid += z * sC;

    __shared__ float smem[3 * (SA + SB)];

    const int tid  = threadIdx.x;
    const int w    = tid >> 5, lane = tid & 31;
    const int g    = lane >> 2, t = lane & 3;
    const int wm   = (w / WARPS_N) * WM;
    const int wn   = (w % WARPS_N) * WN;
    const int m0   = blockIdx.y * BM;
    const int n0   = blockIdx.x * BN;

    float acc[MT][NT][4];
#pragma unroll
    for (int i = 0; i < MT; i++)
#pragma unroll
        for (int j = 0; j < NT; j++)
#pragma unroll
            for (int r = 0; r < 4; r++) acc[i][j][r] = 0.f;

    auto load_stage = [&](int st, int k0) {
        float* as = smem + st * (SA + SB);
        float* bs = as + SA;
#pragma unroll
        for (int it = 0; it < AC; ++it) {
            int idx = it * NTH + tid;
            int r = idx >> 2, ch = (idx & 3) << 2;
            cpa16(as + r * 20 + ch, A + (long long)(m0 + r) * K + k0 + ch);
        }
        if (TB) {
#pragma unroll
            for (int it = 0; it < BC; ++it) {
                int idx = it * NTH + tid;
                int r = idx >> 2, ch = (idx & 3) << 2;
                cpa16(bs + r * 20 + ch, B + (long long)(n0 + r) * K + k0 + ch);
            }
        } else {
#pragma unroll
            for (int it = 0; it < BC; ++it) {
                int idx = it * NTH + tid;
                int kr = idx / (BN / 4), c = (idx % (BN / 4)) << 2;
                cpa16(bs + kr * (BN + 8) + c, B + (long long)(k0 + kr) * N + n0 + c);
            }
        }
    };

    const int nk = K / BK;
    load_stage(0, 0);
    CP_COMMIT();
    if (nk > 1) { load_stage(1, BK); CP_COMMIT(); }

    for (int kt = 0; kt < nk; ++kt) {
        if (kt + 2 < nk) {
            CP_WAIT1();
            __syncthreads();
            load_stage((kt + 2) % 3, (kt + 2) * BK);
            CP_COMMIT();
        } else if (kt + 1 < nk) {
            CP_WAIT1();
            __syncthreads();
        } else {
            CP_WAIT0();
            __syncthreads();
        }
        const float* as = smem + (kt % 3) * (SA + SB);
        const float* bs = as + SA;
#pragma unroll
        for (int ks = 0; ks < 2; ++ks) {
            const int kb = ks * 8;
            unsigned af[MT][4], bf[NT][2];
#pragma unroll
            for (int i = 0; i < MT; i++) {
                int mb = wm + i * 16;
                af[i][0] = fu(as[(mb + g) * 20 + kb + t]);
                af[i][1] = fu(as[(mb + 8 + g) * 20 + kb + t]);
                af[i][2] = fu(as[(mb + g) * 20 + kb + t + 4]);
                af[i][3] = fu(as[(mb + 8 + g) * 20 + kb + t + 4]);
            }
#pragma unroll
            for (int j = 0; j < NT; j++) {
                int nb = wn + j * 8 + g;
                if (TB) {
                    bf[j][0] = fu(bs[nb * 20 + kb + t]);
                    bf[j][1] = fu(bs[nb * 20 + kb + t + 4]);
                } else {
                    bf[j][0] = fu(bs[(kb + t) * (BN + 8) + nb]);
                    bf[j][1] = fu(bs[(kb + t + 4) * (BN + 8) + nb]);
                }
            }
#pragma unroll
            for (int i = 0; i < MT; i++)
#pragma unroll
                for (int j = 0; j < NT; j++)
                    mma_tf32(acc[i][j], af[i], bf[j]);
        }
    }

    // epilogue
#pragma unroll
    for (int i = 0; i < MT; i++) {
        int gm = m0 + wm + i * 16 + g;
#pragma unroll
        for (int j = 0; j < NT; j++) {
            int gn = n0 + wn + j * 8 + 2 * t;
            float v00 = alpha * acc[i][j][0];
            float v01 = alpha * acc[i][j][1];
            float v10 = alpha * acc[i][j][2];
            float v11 = alpha * acc[i][j][3];
            if (MODE == 1) {
                int which = gn >> 9;
                int h = (gn >> 6) & 7;
                int c = gn & 63;
                float sc = (which == 0) ? 0.125f : 1.f;
                float* tgt = (which == 0) ? Qp : ((which == 1) ? Kp : Vp);
                int b0i = gm >> 13, i0i = gm & (SEQ - 1);
                int b1i = (gm + 8) >> 13, i1i = (gm + 8) & (SEQ - 1);
                long long d0 = (((long long)(b0i * HEADS + h)) * SEQ + i0i) * DH + c;
                long long d1 = (((long long)(b1i * HEADS + h)) * SEQ + i1i) * DH + c;
                *(float2*)(tgt + d0) = make_float2(v00 * sc, v01 * sc);
                *(float2*)(tgt + d1) = make_float2(v10 * sc, v11 * sc);
            } else if (MODE == 3) {
                int which = gn >> 9;
                int h = (gn >> 6) & 7;
                int c = gn & 63;
                float sc = (which == 0) ? 0.125f : 1.f;
                float* tgt = (which == 0) ? Qp : Kp;
                int b0i = gm >> 8, m0i = gm & 255;
                int b1i = (gm + 8) >> 8, m1i = (gm + 8) & 255;
                long long d0 = (((long long)(b0i * HEADS + h)) * LM + m0i) * DH + c;
                long long d1 = (((long long)(b1i * HEADS + h)) * LM + m1i) * DH + c;
                *(float2*)(tgt + d0) = make_float2(v00 * sc, v01 * sc);
                *(float2*)(tgt + d1) = make_float2(v10 * sc, v11 * sc);
            } else {
                if (bias) {
                    v00 += bias[gn]; v01 += bias[gn + 1];
                    v10 += bias[gn]; v11 += bias[gn + 1];
                }
                if (resid) {
                    v00 += resid[(long long)gm * N + gn];
                    v01 += resid[(long long)gm * N + gn + 1];
                    v10 += resid[(long long)(gm + 8) * N + gn];
                    v11 += resid[(long long)(gm + 8) * N + gn + 1];
                }
                if (betaI != 0.f) {
                    if (gm == gn)         v00 += betaI;
                    if (gm == gn + 1)     v01 += betaI;
                    if (gm + 8 == gn)     v10 += betaI;
                    if (gm + 8 == gn + 1) v11 += betaI;
                }
                *(float2*)(C + (long long)gm * N + gn)       = make_float2(v00, v01);
                *(float2*)(C + (long long)(gm + 8) * N + gn) = make_float2(v10, v11);
                if (MODE == 2) {
                    float w00 = ((gm == gn)         ? beta2 : 0.f) - v00;
                    float w01 = ((gm == gn + 1)     ? beta2 : 0.f) - v01;
                    float w10 = ((gm + 8 == gn)     ? beta2 : 0.f) - v10;
                    float w11 = ((gm + 8 == gn + 1) ? beta2 : 0.f) - v11;
                    *(float2*)(C2 + (long long)gm * N + gn)       = make_float2(w00, w01);
                    *(float2*)(C2 + (long long)(gm + 8) * N + gn) = make_float2(w10, w11);
                }
            }
        }
    }
}

// ---------------- fused softmax(A@B^T)@C, cp.async double-buffered ----------
// FINAL variant also applies the depthwise residual conv over V and writes
// token-major TOK directly.
#define SAV_SMEM_FLOATS (64*68 + 2*64*68 + 2*64*72)
template<bool FINAL>
__global__ void __launch_bounds__(256) fused_sav(
    const float* __restrict__ A, const float* __restrict__ B, const float* __restrict__ C,
    float* __restrict__ OUT, float* __restrict__ PMAX, float* __restrict__ PSUM,
    int M_total, int N_total, int chunk_len,
    const float* __restrict__ Vg, const float* __restrict__ cw, float* __restrict__ TOK)
{
    extern __shared__ float fs[];
    float* Qs = fs;
    float* Ks = fs + 64*68;
    float* Vs = Ks + 2*64*68;
    float* macc = Qs;
    float* wmax = Qs + 64*64;
    float* wsum = Qs + 64*64 + 128;
    float* VW   = Ks;            // conv V window (96 x 64) reuses K buffers
    float* wsm  = Vs;            // conv weights (33)

    const int bh = blockIdx.z, mt = blockIdx.x, ck = blockIdx.y;
    const int m0 = mt * 64;
    const int tid = threadIdx.x;
    const int w = tid >> 5, lane = tid & 31;
    const int g = lane >> 2, t = lane & 3;
    const int wm = (w >> 1) * 16;
    const int wni = w & 1;
    const int wn = wni * 32;

    const float* Ap = A + ((long long)bh * M_total + m0) * DH;
    const float* Bb = B + (long long)bh * N_total * DH;
    const float* Cb = C + (long long)bh * N_total * DH;

#pragma unroll
    for (int it = 0; it < 4; ++it) {
        int idx = it * 256 + tid;
        int r = idx >> 4, c = (idx & 15) << 2;
        *(float4*)(Qs + r * 68 + c) = *(const float4*)(Ap + r * DH + c);
    }

    const int n_start = ck * chunk_len;

    auto load_kv = [&](int st, int nb) {
        const float* Kp = Bb + (long long)(n_start + nb) * DH;
        const float* Vp = Cb + (long long)(n_start + nb) * DH;
        float* ks = Ks + st * 64 * 68;
        float* vs = Vs + st * 64 * 72;
#pragma unroll
        for (int it = 0; it < 4; ++it) {
            int idx = it * 256 + tid;
            int r = idx >> 4, c = (idx & 15) << 2;
            cpa16(ks + r * 68 + c, Kp + r * DH + c);
        }
#pragma unroll
        for (int it = 0; it < 4; ++it) {
            int idx = it * 256 + tid;
            int r = idx >> 4, c = (idx & 15) << 2;
            cpa16(vs + r * 72 + c, Vp + r * DH + c);
        }
    };

    float acc2[8][4];
#pragma unroll
    for (int nt = 0; nt < 8; ++nt)
#pragma unroll
        for (int r = 0; r < 4; ++r) acc2[nt][r] = 0.f;
    float rmax0 = -1e30f, rmax1 = -1e30f, rsum0 = 0.f, rsum1 = 0.f;

    const int srcA = (lane & ~3) | (t >> 1);
    const int srcB = srcA + 2;
    const bool hi = t & 1;

    load_kv(0, 0);
    CP_COMMIT();

    const int nt_iters = chunk_len / 64;
    for (int itn = 0; itn < nt_iters; ++itn) {
        if (itn + 1 < nt_iters) {
            load_kv((itn + 1) & 1, (itn + 1) * 64);
            CP_COMMIT();
            CP_WAIT1();
        } else {
            CP_WAIT0();
        }
        __syncthreads();
        const float* ks = Ks + (itn & 1) * 64 * 68;
        const float* vs = Vs + (itn & 1) * 64 * 72;

        float sacc[4][4];
#pragma unroll
        for (int j = 0; j < 4; ++j)
#pragma unroll
            for (int r = 0; r < 4; ++r) sacc[j][r] = 0.f;
#pragma unroll
        for (int kk0 = 0; kk0 < 8; ++kk0) {
            int kb = kk0 * 8;
            unsigned af[4];
            af[0] = fu(Qs[(wm + g) * 68 + kb + t]);
            af[1] = fu(Qs[(wm + 8 + g) * 68 + kb + t]);
            af[2] = fu(Qs[(wm + g) * 68 + kb + t + 4]);
            af[3] = fu(Qs[(wm + 8 + g) * 68 + kb + t + 4]);
#pragma unroll
            for (int j = 0; j < 4; ++j) {
                int nbq = wn + j * 8 + g;
                unsigned bf[2];
                bf[0] = fu(ks[nbq * 68 + kb + t]);
                bf[1] = fu(ks[nbq * 68 + kb + t + 4]);
                mma_tf32(sacc[j], af, bf);
            }
        }
        float tm0 = -1e30f, tm1 = -1e30f;
#pragma unroll
        for (int j = 0; j < 4; ++j) {
            tm0 = fmaxf(tm0, fmaxf(sacc[j][0], sacc[j][1]));
            tm1 = fmaxf(tm1, fmaxf(sacc[j][2], sacc[j][3]));
        }
        tm0 = fmaxf(tm0, __shfl_xor_sync(0xffffffffu, tm0, 1));
        tm0 = fmaxf(tm0, __shfl_xor_sync(0xffffffffu, tm0, 2));
        tm1 = fmaxf(tm1, __shfl_xor_sync(0xffffffffu, tm1, 1));
        tm1 = fmaxf(tm1, __shfl_xor_sync(0xffffffffu, tm1, 2));
        float nm0 = fmaxf(rmax0, tm0), nm1 = fmaxf(rmax1, tm1);
        float sc0 = __expf(rmax0 - nm0), sc1 = __expf(rmax1 - nm1);
        float ts0 = 0.f, ts1 = 0.f;
#pragma unroll
        for (int j = 0; j < 4; ++j) {
            sacc[j][0] = __expf(sacc[j][0] - nm0);
            sacc[j][1] = __expf(sacc[j][1] - nm0);
            sacc[j][2] = __expf(sacc[j][2] - nm1);
            sacc[j][3] = __expf(sacc[j][3] - nm1);
            ts0 += sacc[j][0] + sacc[j][1];
            ts1 += sacc[j][2] + sacc[j][3];
        }
        ts0 += __shfl_xor_sync(0xffffffffu, ts0, 1);
        ts0 += __shfl_xor_sync(0xffffffffu, ts0, 2);
        ts1 += __shfl_xor_sync(0xffffffffu, ts1, 1);
        ts1 += __shfl_xor_sync(0xffffffffu, ts1, 2);
        rsum0 = rsum0 * sc0 + ts0;
        rsum1 = rsum1 * sc1 + ts1;
        rmax0 = nm0; rmax1 = nm1;
#pragma unroll
        for (int nt = 0; nt < 8; ++nt) {
            acc2[nt][0] *= sc0; acc2[nt][1] *= sc0;
            acc2[nt][2] *= sc1; acc2[nt][3] *= sc1;
        }
#pragma unroll
        for (int j2 = 0; j2 < 4; ++j2) {
            unsigned p0 = fu(sacc[j2][0]), p1 = fu(sacc[j2][1]);
            unsigned p2 = fu(sacc[j2][2]), p3 = fu(sacc[j2][3]);
            unsigned a0a = __shfl_sync(0xffffffffu, p0, srcA);
            unsigned a0b = __shfl_sync(0xffffffffu, p1, srcA);
            unsigned a1a = __shfl_sync(0xffffffffu, p2, srcA);
            unsigned a1b = __shfl_sync(0xffffffffu, p3, srcA);
            unsigned a2a = __shfl_sync(0xffffffffu, p0, srcB);
            unsigned a2b = __shfl_sync(0xffffffffu, p1, srcB);
            unsigned a3a = __shfl_sync(0xffffffffu, p2, srcB);
            unsigned a3b = __shfl_sync(0xffffffffu, p3, srcB);
            unsigned af2[4];
            af2[0] = hi ? a0b : a0a;
            af2[1] = hi ? a1b : a1a;
            af2[2] = hi ? a2b : a2a;
            af2[3] = hi ? a3b : a3a;
            int kb = wn + j2 * 8;
#pragma unroll
            for (int nt = 0; nt < 8; ++nt) {
                unsigned bf[2];
                bf[0] = fu(vs[(kb + t) * 72 + nt * 8 + g]);
                bf[1] = fu(vs[(kb + t + 4) * 72 + nt * 8 + g]);
                mma_tf32(acc2[nt], af2, bf);
            }
        }
        __syncthreads();
    }

    if (t == 0) {
        wmax[wni*64 + wm + g]     = rmax0;
        wmax[wni*64 + wm + 8 + g] = rmax1;
        wsum[wni*64 + wm + g]     = rsum0;
        wsum[wni*64 + wm + 8 + g] = rsum1;
    }
    __syncthreads();
    int other = wni ^ 1;
    float om0 = wmax[other*64 + wm + g],     os0 = wsum[other*64 + wm + g];
    float om1 = wmax[other*64 + wm + 8 + g], os1 = wsum[other*64 + wm + 8 + g];
    float gm0 = fmaxf(rmax0, om0), gm1 = fmaxf(rmax1, om1);
    float f0 = __expf(rmax0 - gm0), f1 = __expf(rmax1 - gm1);
    float gs0 = rsum0 * f0 + os0 * __expf(om0 - gm0);
    float gs1 = rsum1 * f1 + os1 * __expf(om1 - gm1);
#pragma unroll
    for (int nt = 0; nt < 8; ++nt) {
        acc2[nt][0] *= f0; acc2[nt][1] *= f0;
        acc2[nt][2] *= f1; acc2[nt][3] *= f1;
    }
    __syncthreads();
    if (wni == 1) {
#pragma unroll
        for (int nt = 0; nt < 8; ++nt) {
            *(float2*)&macc[(wm + g)*64 + nt*8 + 2*t]     = make_float2(acc2[nt][0], acc2[nt][1]);
            *(float2*)&macc[(wm + 8 + g)*64 + nt*8 + 2*t] = make_float2(acc2[nt][2], acc2[nt][3]);
        }
    }
    __syncthreads();
    if (FINAL) {
        // merge into macc (normalized rows), then conv + token-major write
        if (wni == 0) {
            float inv0 = 1.f / gs0, inv1 = 1.f / gs1;
#pragma unroll
            for (int nt = 0; nt < 8; ++nt) {
                int cc = nt*8 + 2*t;
                float2 m0v = *(float2*)&macc[(wm + g)*64 + cc];
                float2 m1v = *(float2*)&macc[(wm + 8 + g)*64 + cc];
                *(float2*)&macc[(wm + g)*64 + cc] =
                    make_float2((acc2[nt][0] + m0v.x) * inv0, (acc2[nt][1] + m0v.y) * inv0);
                *(float2*)&macc[(wm + 8 + g)*64 + cc] =
                    make_float2((acc2[nt][2] + m1v.x) * inv1, (acc2[nt][3] + m1v.y) * inv1);
            }
        }
        __syncthreads();
        const int h = bh & 7, b = bh >> 3;
        if (tid < KSZ) wsm[tid] = cw[h * KSZ + tid];
        const float* Vb = Vg + (long long)bh * SEQ * DH;
#pragma unroll
        for (int it = 0; it < 24; ++it) {
            int e = it * 256 + tid;
            int rr = e >> 6, c = e & 63;
            int gi = m0 - 16 + rr;
            VW[rr * 64 + c] = (gi >= 0 && gi < SEQ) ? Vb[(long long)gi * DH + c] : 0.f;
        }
        __syncthreads();
        int c = tid & 63, ib = tid >> 6;
#pragma unroll 4
        for (int j = 0; j < 16; ++j) {
            int il = ib * 16 + j;
            float accv = macc[il * 64 + c];
#pragma unroll
            for (int tt = 0; tt < KSZ; ++tt) accv += wsm[tt] * VW[(il + tt) * 64 + c];
            long long tok = (long long)b * SEQ + m0 + il;
            TOK[tok * DMODEL + h * DH + c] = accv;
        }
    } else {
        if (wni == 0) {
            int row0 = m0 + wm + g, row1 = row0 + 8;
            long long pb = ((long long)bh * NCHUNK + ck) * M_total;
            float* O = OUT + pb * DH;
#pragma unroll
            for (int nt = 0; nt < 8; ++nt) {
                int cc = nt*8 + 2*t;
                float2 m0v = *(float2*)&macc[(wm + g)*64 + cc];
                float2 m1v = *(float2*)&macc[(wm + 8 + g)*64 + cc];
                *(float2*)(O + (long long)row0 * DH + cc) =
                    make_float2(acc2[nt][0] + m0v.x, acc2[nt][1] + m0v.y);
                *(float2*)(O + (long long)row1 * DH + cc) =
                    make_float2(acc2[nt][2] + m1v.x, acc2[nt][3] + m1v.y);
            }
            if (t == 0) {
                PMAX[pb + row0] = gm0; PMAX[pb + row1] = gm1;
                PSUM[pb + row0] = gs0; PSUM[pb + row1] = gs1;
            }
        }
    }
}

// ---------------- combine chunk partials -> a3v ----------------
__global__ void sav_combine(const float* __restrict__ pacc, const float* __restrict__ pmax,
                            const float* __restrict__ psum, float* __restrict__ out)
{
    int idx = blockIdx.x * 256 + threadIdx.x;
    int d = idx & 63;
    int m = (idx >> 6) & (LM - 1);
    int bh = idx >> 14;
    float gmax = -1e30f;
#pragma unroll
    for (int ck = 0; ck < NCHUNK; ++ck)
        gmax = fmaxf(gmax, pmax[((long long)bh * NCHUNK + ck) * LM + m]);
    float gsum = 0.f, val = 0.f;
#pragma unroll
    for (int ck = 0; ck < NCHUNK; ++ck) {
        long long pb = ((long long)bh * NCHUNK + ck) * LM + m;
        float f = __expf(pmax[pb] - gmax);
        gsum += psum[pb] * f;
        val  += pacc[pb * DH + d] * f;
    }
    out[idx] = val / gsum;
}

// ---------------- row softmax (256-wide rows) ----------------
__global__ void softmax_rows(float* __restrict__ S)
{
    float* row = S + (long long)blockIdx.x * 256;
    int tid = threadIdx.x;
    float v = row[tid];
    __shared__ float red[256];
    red[tid] = v; __syncthreads();
    for (int t = 128; t > 0; t >>= 1) {
        if (tid < t) red[tid] = fmaxf(red[tid], red[tid + t]);
        __syncthreads();
    }
    float mx = red[0]; __syncthreads();
    v = __expf(v - mx);
    red[tid] = v; __syncthreads();
    for (int t = 128; t > 0; t >>= 1) {
        if (tid < t) red[tid] += red[tid + t];
        __syncthreads();
    }
    row[tid] = v / red[0];
}

// ---------------- pinv scale: per-bh col/row abs-sum maxima ----------------
__global__ void colrow_max(const float* __restrict__ A2, float* __restrict__ s)
{
    int bh = blockIdx.x, j = threadIdx.x;
    const float* X = A2 + (long long)bh * LM * LM;
    float cs = 0.f, rs = 0.f;
    for (int i = 0; i < LM; ++i) {
        cs += fabsf(X[i * LM + j]);
        rs += fabsf(X[j * LM + i]);
    }
    __shared__ float r1[256], r2[256];
    r1[j] = cs; r2[j] = rs; __syncthreads();
    for (int t = 128; t > 0; t >>= 1) {
        if (j < t) { r1[j] = fmaxf(r1[j], r1[j+t]); r2[j] = fmaxf(r2[j], r2[j+t]); }
        __syncthreads();
    }
    if (j == 0) { s[bh] = r1[0]; s[32 + bh] = r2[0]; }
}

__global__ void make_z0(const float* __restrict__ A2, const float* __restrict__ s,
                        float* __restrict__ Z)
{
    __shared__ float red[64];
    int tid = threadIdx.x;
    if (tid < 64) red[tid] = s[tid];
    __syncthreads();
    float cm = red[0], rm = red[32];
#pragma unroll
    for (int i = 1; i < 32; ++i) { cm = fmaxf(cm, red[i]); rm = fmaxf(rm, red[32 + i]); }
    float inv = 1.f / (cm * rm);
    long long idx = (long long)blockIdx.x * 256 + tid;
    int c  = idx & 255;
    int r  = (int)((idx >> 8) & 255);
    int bh = (int)(idx >> 16);
    Z[idx] = A2[(long long)bh * LM * LM + (long long)c * LM + r] * inv;
}

// ---------------- host driver ----------------
extern "C" void kernel_launch(void* const* d_in, const int* in_sizes, int n_in,
                              void* d_out, int out_size)
{
    const float* x      = (const float*)d_in[0];
    const float* ln_w   = (const float*)d_in[1];
    const float* ln_b   = (const float*)d_in[2];
    const float* w_qkv  = (const float*)d_in[3];
    const float* w_out  = (const float*)d_in[4];
    const float* b_out  = (const float*)d_in[5];
    const float* conv_w = (const float*)d_in[6];
    float* out = (float*)d_out;

    static cudaStream_t s1 = nullptr;
    static cudaEvent_t evFork = nullptr, evJoin = nullptr;
    if (s1 == nullptr) {
        cudaStreamCreateWithFlags(&s1, cudaStreamNonBlocking);
        cudaEventCreateWithFlags(&evFork, cudaEventDisableTiming);
        cudaEventCreateWithFlags(&evJoin, cudaEventDisableTiming);
    }

    void *p;
    cudaGetSymbolAddress(&p, g_xn);    float* xn  = (float*)p;
    cudaGetSymbolAddress(&p, g_xnl);   float* XNL = (float*)p;
    cudaGetSymbolAddress(&p, g_q);     float* Q   = (float*)p;
    cudaGetSymbolAddress(&p, g_k);     float* K   = (float*)p;
    cudaGetSymbolAddress(&p, g_v);     float* V   = (float*)p;
    cudaGetSymbolAddress(&p, g_ql);    float* QL  = (float*)p;
    cudaGetSymbolAddress(&p, g_kl);    float* KL  = (float*)p;
    cudaGetSymbolAddress(&p, g_attn2); float* A2  = (float*)p;
    cudaGetSymbolAddress(&p, g_za);    float* ZA  = (float*)p;
    cudaGetSymbolAddress(&p, g_zb);    float* ZB  = (float*)p;
    cudaGetSymbolAddress(&p, g_xz);    float* XZ  = (float*)p;
    cudaGetSymbolAddress(&p, g_t1);    float* T1  = (float*)p;
    cudaGetSymbolAddress(&p, g_t2);    float* T2  = (float*)p;
    cudaGetSymbolAddress(&p, g_a3v);   float* A3V = (float*)p;
    cudaGetSymbolAddress(&p, g_zav);   float* ZAV = (float*)p;
    cudaGetSymbolAddress(&p, g_tok);   float* TOK = (float*)p;
    cudaGetSymbolAddress(&p, g_pacc);  float* PAC = (float*)p;
    cudaGetSymbolAddress(&p, g_pmax);  float* PMX = (float*)p;
    cudaGetSymbolAddress(&p, g_psum);  float* PSM = (float*)p;
    cudaGetSymbolAddress(&p, g_scale); float* S   = (float*)p;

    const long long sL  = (long long)LM * DH;
    const long long sA2 = (long long)LM * LM;

    const int sav_smem = SAV_SMEM_FLOATS * 4;
    cudaFuncSetAttribute(fused_sav<true>,  cudaFuncAttributeMaxDynamicSharedMemorySize, sav_smem);
    cudaFuncSetAttribute(fused_sav<false>, cudaFuncAttributeMaxDynamicSharedMemorySize, sav_smem);

    // ---- prefix (stream 0): LN, group means, QL/KL projection ----
    ln_kernel<<<NTOK, 128>>>(x, ln_w, ln_b, xn);
    group_mean<<<NGRP, 128>>>(xn, XNL);
    gemm_tc<64,64,2,2,true,3><<<dim3(16, 16, 1), 128>>>(XNL, w_qkv, nullptr,
        NGRP, 2*DMODEL, DMODEL, 0, 0, 0, 1.f, 0.f, nullptr, nullptr, nullptr, 0.f, QL, KL, nullptr);

    // ---- fork: branch A (serial pinv chain) on s1 ----
    cudaEventRecord(evFork, 0);
    cudaStreamWaitEvent(s1, evFork, 0);
    gemm_tc<64,64,2,2,true,0><<<dim3(4, 4, BH), 128, 0, s1>>>(QL, KL, A2,
        LM, LM, DH, sL, sL, sA2, 1.f, 0.f, nullptr, nullptr, nullptr, 0.f, nullptr, nullptr, nullptr);
    softmax_rows<<<BH*LM, 256, 0, s1>>>(A2);
    colrow_max<<<BH, 256, 0, s1>>>(A2, S);
    make_z0<<<(BH*LM*LM)/256, 256, 0, s1>>>(A2, S, ZA);
    float* Zin = ZA; float* Zout = ZB;
    for (int it = 0; it < 6; ++it) {
        gemm_tc<64,64,2,2,false,2><<<dim3(4,4,BH), 128, 0, s1>>>(A2, Zin, XZ,
            LM, LM, LM, sA2, sA2, sA2, 1.f, 0.f, nullptr, nullptr, T1, 7.f, nullptr, nullptr, nullptr);
        gemm_tc<64,64,2,2,false,0><<<dim3(4,4,BH), 128, 0, s1>>>(XZ, T1, T2,
            LM, LM, LM, sA2, sA2, sA2, -1.f, 15.f, nullptr, nullptr, nullptr, 0.f, nullptr, nullptr, nullptr);
        gemm_tc<64,64,2,2,false,0><<<dim3(4,4,BH), 128, 0, s1>>>(XZ, T2, T1,
            LM, LM, LM, sA2, sA2, sA2, -1.f, 13.f, nullptr, nullptr, nullptr, 0.f, nullptr, nullptr, nullptr);
        gemm_tc<64,64,2,2,false,0><<<dim3(4,4,BH), 128, 0, s1>>>(Zin, T1, Zout,
            LM, LM, LM, sA2, sA2, sA2, 0.25f, 0.f, nullptr, nullptr, nullptr, 0.f, nullptr, nullptr, nullptr);
        float* tmp = Zin; Zin = Zout; Zout = tmp;
    }
    cudaEventRecord(evJoin, s1);

    // ---- branch B (throughput-bound) on stream 0 ----
    gemm_tc<128,128,2,2,true,1><<<dim3(12, 256, 1), 128>>>(xn, w_qkv, nullptr,
        NTOK, 3*DMODEL, DMODEL, 0, 0, 0, 1.f, 0.f, nullptr, nullptr, nullptr, 0.f, Q, K, V);
    fused_sav<false><<<dim3(LM/64, NCHUNK, BH), 256, sav_smem>>>(QL, K, V,
        PAC, PMX, PSM, LM, SEQ, SEQ/NCHUNK, nullptr, nullptr, nullptr);
    sav_combine<<<(BH*LM*DH)/256, 256>>>(PAC, PMX, PSM, A3V);

    // ---- join ----
    cudaStreamWaitEvent(0, evJoin, 0);
    gemm_tc<64,64,2,2,false,0><<<dim3(1, 4, BH), 128>>>(Zin, A3V, ZAV,
        LM, DH, LM, sA2, sL, sL, 1.f, 0.f, nullptr, nullptr, nullptr, 0.f, nullptr, nullptr, nullptr);
    // outh + conv fused, writes TOK token-major directly
    fused_sav<true><<<dim3(SEQ/64, 1, BH), 256, sav_smem>>>(Q, KL, ZAV,
        nullptr, nullptr, nullptr, SEQ, LM, LM, V, conv_w, TOK);
    // final: out = x + TOK @ w_out^T + b_out
    gemm_tc<128,128,2,2,true,0><<<dim3(4, 256, 1), 128>>>(TOK, w_out, out,
        NTOK, DMODEL, DMODEL, 0, 0, 0, 1.f, 0.f, b_out, x, nullptr, 0.f, nullptr, nullptr, nullptr);
}

// round 8
// speedup vs baseline: 1.3762x; 1.2635x over previous
#include <cuda_runtime.h>
#include <cuda_bf16.h>
#include <cstdint>

// ---------------- problem constants ----------------
#define BATCH 4
#define SEQ   8192
#define DMODEL 512
#define HEADS 8
#define DH    64
#define LM    256
#define LGRP  32
#define NTOK  (BATCH*SEQ)
#define BH    (BATCH*HEADS)
#define KSZ   33
#define NCHUNK 8
#define NGRP  (NTOK/LGRP)

typedef __nv_bfloat16 bf16;
typedef __nv_bfloat162 bf162;

// ---------------- scratch ----------------
__device__ bf16  g_xnb  [(size_t)NTOK*DMODEL];
__device__ bf16  g_xnlb [(size_t)NGRP*DMODEL];
__device__ bf16  g_wqkvb[(size_t)3*DMODEL*DMODEL];
__device__ bf16  g_woutb[(size_t)DMODEL*DMODEL];
__device__ bf16  g_qb   [(size_t)BH*SEQ*DH];
__device__ bf16  g_kb   [(size_t)BH*SEQ*DH];
__device__ bf16  g_vb   [(size_t)BH*SEQ*DH];
__device__ float g_ql   [(size_t)BH*LM*DH];
__device__ float g_kl   [(size_t)BH*LM*DH];
__device__ bf16  g_qlb  [(size_t)BH*LM*DH];
__device__ bf16  g_klb  [(size_t)BH*LM*DH];
__device__ float g_attn2[(size_t)BH*LM*LM];
__device__ float g_za   [(size_t)BH*LM*LM];
__device__ float g_zb   [(size_t)BH*LM*LM];
__device__ float g_xz   [(size_t)BH*LM*LM];
__device__ float g_t1   [(size_t)BH*LM*LM];
__device__ float g_t2   [(size_t)BH*LM*LM];
__device__ float g_a3v  [(size_t)BH*LM*DH];
__device__ bf16  g_zavb [(size_t)BH*LM*DH];
__device__ bf16  g_tokb [(size_t)NTOK*DMODEL];
__device__ float g_pacc [(size_t)BH*NCHUNK*LM*DH];
__device__ float g_pmax [(size_t)BH*NCHUNK*LM];
__device__ float g_psum [(size_t)BH*NCHUNK*LM];
__device__ float g_scale[64];

// ---------------- helpers ----------------
__device__ __forceinline__ void mma_tf32(float* c, const unsigned* a, const unsigned* b) {
    asm volatile(
        "mma.sync.aligned.m16n8k8.row.col.f32.tf32.tf32.f32 "
        "{%0,%1,%2,%3},{%4,%5,%6,%7},{%8,%9},{%0,%1,%2,%3};"
        : "+f"(c[0]), "+f"(c[1]), "+f"(c[2]), "+f"(c[3])
        : "r"(a[0]), "r"(a[1]), "r"(a[2]), "r"(a[3]), "r"(b[0]), "r"(b[1]));
}
__device__ __forceinline__ void mma_bf(float* c, const unsigned* a, const unsigned* b) {
    asm volatile(
        "mma.sync.aligned.m16n8k16.row.col.f32.bf16.bf16.f32 "
        "{%0,%1,%2,%3},{%4,%5,%6,%7},{%8,%9},{%0,%1,%2,%3};"
        : "+f"(c[0]), "+f"(c[1]), "+f"(c[2]), "+f"(c[3])
        : "r"(a[0]), "r"(a[1]), "r"(a[2]), "r"(a[3]), "r"(b[0]), "r"(b[1]));
}
__device__ __forceinline__ void cpa16(void* s, const void* g) {
    unsigned sa = (unsigned)__cvta_generic_to_shared(s);
    asm volatile("cp.async.cg.shared.global [%0], [%1], 16;" :: "r"(sa), "l"(g));
}
#define CP_COMMIT() asm volatile("cp.async.commit_group;")
#define CP_WAIT1()  asm volatile("cp.async.wait_group 1;")
#define CP_WAIT0()  asm volatile("cp.async.wait_group 0;")

__device__ __forceinline__ unsigned fu(float f) { return __float_as_uint(f); }
// pack two floats -> bf16x2 (lo = first)
__device__ __forceinline__ unsigned pk(float lo, float hi) {
    unsigned r;
    asm("cvt.rn.bf16x2.f32 %0, %1, %2;" : "=r"(r) : "f"(hi), "f"(lo));
    return r;
}
__device__ __forceinline__ unsigned ldu(const bf16* p) { return *(const unsigned*)p; }
__device__ __forceinline__ unsigned lds2(const bf16* p, int i0, int i1) {
    unsigned lo = *(const unsigned short*)(p + i0);
    unsigned hi = *(const unsigned short*)(p + i1);
    return lo | (hi << 16);
}

// ---------------- fp32 -> bf16 convert ----------------
__global__ void cvt_bf(const float* __restrict__ src, bf16* __restrict__ dst, int n2)
{
    int i = blockIdx.x * 256 + threadIdx.x;
    if (i < n2) {
        float2 v = *(const float2*)(src + 2 * i);
        *(unsigned*)(dst + 2 * i) = pk(v.x, v.y);
    }
}

// ---------------- LayerNorm -> bf16 ----------------
__global__ void ln_kernel(const float* __restrict__ x, const float* __restrict__ w,
                          const float* __restrict__ b, bf16* __restrict__ y)
{
    int row = blockIdx.x;
    int tid = threadIdx.x;
    const float* xr = x + (long long)row * DMODEL;
    float4 v = *(const float4*)(xr + tid * 4);
    float s  = v.x + v.y + v.z + v.w;
    float s2 = v.x*v.x + v.y*v.y + v.z*v.z + v.w*v.w;
    __shared__ float r1[128], r2[128];
    r1[tid] = s; r2[tid] = s2; __syncthreads();
    for (int t = 64; t > 0; t >>= 1) {
        if (tid < t) { r1[tid] += r1[tid+t]; r2[tid] += r2[tid+t]; }
        __syncthreads();
    }
    float mean = r1[0] * (1.0f / DMODEL);
    float var  = r2[0] * (1.0f / DMODEL) - mean * mean;
    float inv  = rsqrtf(var + 1e-5f);
    float4 w4 = *(const float4*)(w + tid * 4);
    float4 b4 = *(const float4*)(b + tid * 4);
    float o0 = (v.x - mean) * inv * w4.x + b4.x;
    float o1 = (v.y - mean) * inv * w4.y + b4.y;
    float o2 = (v.z - mean) * inv * w4.z + b4.z;
    float o3 = (v.w - mean) * inv * w4.w + b4.w;
    uint2 u; u.x = pk(o0, o1); u.y = pk(o2, o3);
    *(uint2*)(y + (long long)row * DMODEL + tid * 4) = u;
}

// ---------------- group mean over 32 consecutive tokens (bf16 in/out) -------
__global__ void group_mean(const bf16* __restrict__ xn, bf16* __restrict__ xnl)
{
    int g = blockIdx.x;
    int tid = threadIdx.x;
    const bf162* p = (const bf162*)(xn + (long long)g * LGRP * DMODEL) + tid * 2;
    float2 s0 = make_float2(0.f, 0.f), s1 = make_float2(0.f, 0.f);
#pragma unroll
    for (int i = 0; i < LGRP; ++i) {
        float2 a = __bfloat1622float2(p[(long long)i * (DMODEL/2)]);
        float2 b = __bfloat1622float2(p[(long long)i * (DMODEL/2) + 1]);
        s0.x += a.x; s0.y += a.y; s1.x += b.x; s1.y += b.y;
    }
    const float inv = 1.f / LGRP;
    uint2 u; u.x = pk(s0.x * inv, s0.y * inv); u.y = pk(s1.x * inv, s1.y * inv);
    *(uint2*)(xnl + (long long)g * DMODEL + tid * 4) = u;
}

// ---------------- bf16 tensor-core GEMM (m16n8k16), TB layout, 3-stage -------
// MODE 0: C = acc + bias + resid (fp32 out)
// MODE 1: qkv split -> Qb,Kb,Vb bf16 head-major (Q x0.125)
// MODE 3: ql/kl split (N=1024) -> Qf,Kf fp32 AND Qb,Kb bf16 head-major (Q x0.125)
template<int BM, int BN, int WARPS_M, int WARPS_N, int MODE>
__global__ void __launch_bounds__(32*WARPS_M*WARPS_N) gemm_bf(
    const bf16* __restrict__ A, const bf16* __restrict__ B, float* __restrict__ C,
    int M, int N, int K,
    const float* __restrict__ bias, const float* __restrict__ resid,
    float* __restrict__ Qf, float* __restrict__ Kf,
    bf16* __restrict__ Qb, bf16* __restrict__ Kb, bf16* __restrict__ Vb)
{
    constexpr int BK  = 32;
    constexpr int NTH = 32 * WARPS_M * WARPS_N;
    constexpr int WM  = BM / WARPS_M;
    constexpr int WN  = BN / WARPS_N;
    constexpr int MT  = WM / 16;
    constexpr int NT  = WN / 8;
    constexpr int RS  = BK + 8;           // 40 bf16 row stride
    constexpr int SA  = BM * RS;
    constexpr int SB  = BN * RS;
    constexpr int AC  = BM * 4 / NTH;     // 16B chunks per thread
    constexpr int BC  = BN * 4 / NTH;

    extern __shared__ __align__(16) bf16 sm[];

    const int tid  = threadIdx.x;
    const int w    = tid >> 5, lane = tid & 31;
    const int g    = lane >> 2, t = lane & 3;
    const int wm   = (w / WARPS_N) * WM;
    const int wn   = (w % WARPS_N) * WN;
    const int m0   = blockIdx.y * BM;
    const int n0   = blockIdx.x * BN;

    float acc[MT][NT][4];
#pragma unroll
    for (int i = 0; i < MT; i++)
#pragma unroll
        for (int j = 0; j < NT; j++)
#pragma unroll
            for (int r = 0; r < 4; r++) acc[i][j][r] = 0.f;

    auto load_stage = [&](int st, int k0) {
        bf16* as = sm + st * (SA + SB);
        bf16* bs = as + SA;
#pragma unroll
        for (int it = 0; it < AC; ++it) {
            int idx = it * NTH + tid;
            int r = idx >> 2, ch = (idx & 3) << 3;
            cpa16(as + r * RS + ch, A + (long long)(m0 + r) * K + k0 + ch);
        }
#pragma unroll
        for (int it = 0; it < BC; ++it) {
            int idx = it * NTH + tid;
            int r = idx >> 2, ch = (idx & 3) << 3;
            cpa16(bs + r * RS + ch, B + (long long)(n0 + r) * K + k0 + ch);
        }
    };

    const int nk = K / BK;
    load_stage(0, 0);
    CP_COMMIT();
    if (nk > 1) { load_stage(1, BK); CP_COMMIT(); }

    for (int kt = 0; kt < nk; ++kt) {
        if (kt + 2 < nk) {
            CP_WAIT1();
            __syncthreads();
            load_stage((kt + 2) % 3, (kt + 2) * BK);
            CP_COMMIT();
        } else if (kt + 1 < nk) {
            CP_WAIT1();
            __syncthreads();
        } else {
            CP_WAIT0();
            __syncthreads();
        }
        const bf16* as = sm + (kt % 3) * (SA + SB);
        const bf16* bs = as + SA;
#pragma unroll
        for (int ks = 0; ks < 2; ++ks) {
            const int kb = ks * 16;
            unsigned af[MT][4], bf[NT][2];
#pragma unroll
            for (int i = 0; i < MT; i++) {
                int mb = wm + i * 16;
                af[i][0] = ldu(as + (mb + g) * RS + kb + 2*t);
                af[i][1] = ldu(as + (mb + 8 + g) * RS + kb + 2*t);
                af[i][2] = ldu(as + (mb + g) * RS + kb + 8 + 2*t);
                af[i][3] = ldu(as + (mb + 8 + g) * RS + kb + 8 + 2*t);
            }
#pragma unroll
            for (int j = 0; j < NT; j++) {
                int nb = wn + j * 8 + g;
                bf[j][0] = ldu(bs + nb * RS + kb + 2*t);
                bf[j][1] = ldu(bs + nb * RS + kb + 8 + 2*t);
            }
#pragma unroll
            for (int i = 0; i < MT; i++)
#pragma unroll
                for (int j = 0; j < NT; j++)
                    mma_bf(acc[i][j], af[i], bf[j]);
        }
    }

    // epilogue
#pragma unroll
    for (int i = 0; i < MT; i++) {
        int gm = m0 + wm + i * 16 + g;
#pragma unroll
        for (int j = 0; j < NT; j++) {
            int gn = n0 + wn + j * 8 + 2 * t;
            float v00 = acc[i][j][0], v01 = acc[i][j][1];
            float v10 = acc[i][j][2], v11 = acc[i][j][3];
            if (MODE == 1) {
                int which = gn >> 9;
                int h = (gn >> 6) & 7;
                int c = gn & 63;
                float sc = (which == 0) ? 0.125f : 1.f;
                bf16* tgt = (which == 0) ? Qb : ((which == 1) ? Kb : Vb);
                int b0i = gm >> 13, i0i = gm & (SEQ - 1);
                int b1i = (gm + 8) >> 13, i1i = (gm + 8) & (SEQ - 1);
                long long d0 = (((long long)(b0i * HEADS + h)) * SEQ + i0i) * DH + c;
                long long d1 = (((long long)(b1i * HEADS + h)) * SEQ + i1i) * DH + c;
                *(unsigned*)(tgt + d0) = pk(v00 * sc, v01 * sc);
                *(unsigned*)(tgt + d1) = pk(v10 * sc, v11 * sc);
            } else if (MODE == 3) {
                int which = gn >> 9;
                int h = (gn >> 6) & 7;
                int c = gn & 63;
                float sc = (which == 0) ? 0.125f : 1.f;
                float* tf = (which == 0) ? Qf : Kf;
                bf16*  tb = (which == 0) ? Qb : Kb;
                int b0i = gm >> 8, m0i = gm & 255;
                int b1i = (gm + 8) >> 8, m1i = (gm + 8) & 255;
                long long d0 = (((long long)(b0i * HEADS + h)) * LM + m0i) * DH + c;
                long long d1 = (((long long)(b1i * HEADS + h)) * LM + m1i) * DH + c;
                *(float2*)(tf + d0) = make_float2(v00 * sc, v01 * sc);
                *(float2*)(tf + d1) = make_float2(v10 * sc, v11 * sc);
                *(unsigned*)(tb + d0) = pk(v00 * sc, v01 * sc);
                *(unsigned*)(tb + d1) = pk(v10 * sc, v11 * sc);
            } else {
                if (bias) {
                    v00 += bias[gn]; v01 += bias[gn + 1];
                    v10 += bias[gn]; v11 += bias[gn + 1];
                }
                if (resid) {
                    v00 += resid[(long long)gm * N + gn];
                    v01 += resid[(long long)gm * N + gn + 1];
                    v10 += resid[(long long)(gm + 8) * N + gn];
                    v11 += resid[(long long)(gm + 8) * N + gn + 1];
                }
                *(float2*)(C + (long long)gm * N + gn)       = make_float2(v00, v01);
                *(float2*)(C + (long long)(gm + 8) * N + gn) = make_float2(v10, v11);
            }
        }
    }
}

// ---------------- tf32 tensor-core GEMM (pinv chain + attn2 + ZAV) ----------
// MODE 0: C = alpha*A@op(B) + betaI*I
// MODE 2: C = alpha*A@op(B); C2 = beta2*I - C
// MODE 4: bf16 out via Qp pointer (no C)
template<int BM, int BN, int WARPS_M, int WARPS_N, bool TB, int MODE>
__global__ void __launch_bounds__(32*WARPS_M*WARPS_N) gemm_tc(
    const float* __restrict__ A, const float* __restrict__ B, float* __restrict__ C,
    int M, int N, int K, long long sA, long long sB, long long sC,
    float alpha, float betaI, float* __restrict__ C2, float beta2,
    float* __restrict__ Qp)
{
    constexpr int BK  = 16;
    constexpr int NTH = 32 * WARPS_M * WARPS_N;
    constexpr int WM  = BM / WARPS_M;
    constexpr int WN  = BN / WARPS_N;
    constexpr int MT  = WM / 16;
    constexpr int NT  = WN / 8;
    constexpr int SA  = BM * 20;
    constexpr int SB  = TB ? BN * 20 : BK * (BN + 8);
    constexpr int AC  = BM * 4 / NTH;
    constexpr int BC  = TB ? BN * 4 / NTH : (BK * BN / 4) / NTH;

    const int z = blockIdx.z;
    A += z * sA; B += z * sB;
    if (C)  C  += z * sC;
    if (C2) C2 += z * sC;

    __shared__ float smem[3 * (SA + SB)];

    const int tid  = threadIdx.x;
    const int w    = tid >> 5, lane = tid & 31;
    const int g    = lane >> 2, t = lane & 3;
    const int wm   = (w / WARPS_N) * WM;
    const int wn   = (w % WARPS_N) * WN;
    const int m0   = blockIdx.y * BM;
    const int n0   = blockIdx.x * BN;

    float acc[MT][NT][4];
#pragma unroll
    for (int i = 0; i < MT; i++)
#pragma unroll
        for (int j = 0; j < NT; j++)
#pragma unroll
            for (int r = 0; r < 4; r++) acc[i][j][r] = 0.f;

    auto load_stage = [&](int st, int k0) {
        float* as = smem + st * (SA + SB);
        float* bs = as + SA;
#pragma unroll
        for (int it = 0; it < AC; ++it) {
            int idx = it * NTH + tid;
            int r = idx >> 2, ch = (idx & 3) << 2;
            cpa16(as + r * 20 + ch, A + (long long)(m0 + r) * K + k0 + ch);
        }
        if (TB) {
#pragma unroll
            for (int it = 0; it < BC; ++it) {
                int idx = it * NTH + tid;
                int r = idx >> 2, ch = (idx & 3) << 2;
                cpa16(bs + r * 20 + ch, B + (long long)(n0 + r) * K + k0 + ch);
            }
        } else {
#pragma unroll
            for (int it = 0; it < BC; ++it) {
                int idx = it * NTH + tid;
                int kr = idx / (BN / 4), c = (idx % (BN / 4)) << 2;
                cpa16(bs + kr * (BN + 8) + c, B + (long long)(k0 + kr) * N + n0 + c);
            }
        }
    };

    const int nk = K / BK;
    load_stage(0, 0);
    CP_COMMIT();
    if (nk > 1) { load_stage(1, BK); CP_COMMIT(); }

    for (int kt = 0; kt < nk; ++kt) {
        if (kt + 2 < nk) {
            CP_WAIT1();
            __syncthreads();
            load_stage((kt + 2) % 3, (kt + 2) * BK);
            CP_COMMIT();
        } else if (kt + 1 < nk) {
            CP_WAIT1();
            __syncthreads();
        } else {
            CP_WAIT0();
            __syncthreads();
        }
        const float* as = smem + (kt % 3) * (SA + SB);
        const float* bs = as + SA;
#pragma unroll
        for (int ks = 0; ks < 2; ++ks) {
            const int kb = ks * 8;
            unsigned af[MT][4], bf[NT][2];
#pragma unroll
            for (int i = 0; i < MT; i++) {
                int mb = wm + i * 16;
                af[i][0] = fu(as[(mb + g) * 20 + kb + t]);
                af[i][1] = fu(as[(mb + 8 + g) * 20 + kb + t]);
                af[i][2] = fu(as[(mb + g) * 20 + kb + t + 4]);
                af[i][3] = fu(as[(mb + 8 + g) * 20 + kb + t + 4]);
            }
#pragma unroll
            for (int j = 0; j < NT; j++) {
                int nb = wn + j * 8 + g;
                if (TB) {
                    bf[j][0] = fu(bs[nb * 20 + kb + t]);
                    bf[j][1] = fu(bs[nb * 20 + kb + t + 4]);
                } else {
                    bf[j][0] = fu(bs[(kb + t) * (BN + 8) + nb]);
                    bf[j][1] = fu(bs[(kb + t + 4) * (BN + 8) + nb]);
                }
            }
#pragma unroll
            for (int i = 0; i < MT; i++)
#pragma unroll
                for (int j = 0; j < NT; j++)
                    mma_tf32(acc[i][j], af[i], bf[j]);
        }
    }

#pragma unroll
    for (int i = 0; i < MT; i++) {
        int gm = m0 + wm + i * 16 + g;
#pragma unroll
        for (int j = 0; j < NT; j++) {
            int gn = n0 + wn + j * 8 + 2 * t;
            float v00 = alpha * acc[i][j][0];
            float v01 = alpha * acc[i][j][1];
            float v10 = alpha * acc[i][j][2];
            float v11 = alpha * acc[i][j][3];
            if (MODE == 4) {
                bf16* Cb = (bf16*)Qp + (long long)z * sC;
                *(unsigned*)(Cb + (long long)gm * N + gn)       = pk(v00, v01);
                *(unsigned*)(Cb + (long long)(gm + 8) * N + gn) = pk(v10, v11);
            } else {
                if (betaI != 0.f) {
                    if (gm == gn)         v00 += betaI;
                    if (gm == gn + 1)     v01 += betaI;
                    if (gm + 8 == gn)     v10 += betaI;
                    if (gm + 8 == gn + 1) v11 += betaI;
                }
                *(float2*)(C + (long long)gm * N + gn)       = make_float2(v00, v01);
                *(float2*)(C + (long long)(gm + 8) * N + gn) = make_float2(v10, v11);
                if (MODE == 2) {
                    float w00 = ((gm == gn)         ? beta2 : 0.f) - v00;
                    float w01 = ((gm == gn + 1)     ? beta2 : 0.f) - v01;
                    float w10 = ((gm + 8 == gn)     ? beta2 : 0.f) - v10;
                    float w11 = ((gm + 8 == gn + 1) ? beta2 : 0.f) - v11;
                    *(float2*)(C2 + (long long)gm * N + gn)       = make_float2(w00, w01);
                    *(float2*)(C2 + (long long)(gm + 8) * N + gn) = make_float2(w10, w11);
                }
            }
        }
    }
}

// ---------------- fused softmax(A@B^T)@C in bf16 ----------------------------
// FINAL: + depthwise conv residual over Vg, writes TOK (bf16) token-major.
#define SAV_SMEM_BYTES (5*64*72*2)    // Qs + 2*Ks + 2*Vs, all [64][72] bf16
template<bool FINAL>
__global__ void __launch_bounds__(256) fused_sav(
    const bf16* __restrict__ A, const bf16* __restrict__ B, const bf16* __restrict__ C,
    float* __restrict__ OUT, float* __restrict__ PMAX, float* __restrict__ PSUM,
    int M_total, int N_total, int chunk_len,
    const bf16* __restrict__ Vg, const float* __restrict__ cw, bf16* __restrict__ TOK)
{
    extern __shared__ __align__(16) char sb[];
    bf16* Qs = (bf16*)sb;                          // [64][72]
    bf16* Ks = Qs + 64*72;                         // 2 stages
    bf16* Vs = Ks + 2*64*72;                       // 2 stages
    float* macc = (float*)sb;                      // [64][64] fp32 (epilogue)
    float* wmax = (float*)(sb + 16384);
    float* wsum = (float*)(sb + 16896);
    bf16*  VW   = (bf16*)(sb + 17408);             // [96][64] bf16 (conv window)
    float* wsm  = (float*)(sb + 17408 + 12288);    // [33]

    const int bh = blockIdx.z, mt = blockIdx.x, ck = blockIdx.y;
    const int m0 = mt * 64;
    const int tid = threadIdx.x;
    const int w = tid >> 5, lane = tid & 31;
    const int g = lane >> 2, t = lane & 3;
    const int wm = (w >> 1) * 16;
    const int wni = w & 1;
    const int wn = wni * 32;

    const bf16* Ap = A + ((long long)bh * M_total + m0) * DH;
    const bf16* Bb = B + (long long)bh * N_total * DH;
    const bf16* Cb = C + (long long)bh * N_total * DH;

    // Q tile 64x64 bf16
#pragma unroll
    for (int it = 0; it < 2; ++it) {
        int idx = it * 256 + tid;
        int r = idx >> 3, c = (idx & 7) << 3;
        *(uint4*)(Qs + r * 72 + c) = *(const uint4*)(Ap + r * DH + c);
    }

    const int n_start = ck * chunk_len;

    auto load_kv = [&](int st, int nb) {
        const bf16* Kp = Bb + (long long)(n_start + nb) * DH;
        const bf16* Vp = Cb + (long long)(n_start + nb) * DH;
        bf16* ks = Ks + st * 64 * 72;
        bf16* vs = Vs + st * 64 * 72;
#pragma unroll
        for (int it = 0; it < 2; ++it) {
            int idx = it * 256 + tid;
            int r = idx >> 3, c = (idx & 7) << 3;
            cpa16(ks + r * 72 + c, Kp + r * DH + c);
            cpa16(vs + r * 72 + c, Vp + r * DH + c);
        }
    };

    float acc2[8][4];
#pragma unroll
    for (int nt = 0; nt < 8; ++nt)
#pragma unroll
        for (int r = 0; r < 4; ++r) acc2[nt][r] = 0.f;
    float rmax0 = -1e30f, rmax1 = -1e30f, rsum0 = 0.f, rsum1 = 0.f;

    load_kv(0, 0);
    CP_COMMIT();

    const int nt_iters = chunk_len / 64;
    for (int itn = 0; itn < nt_iters; ++itn) {
        if (itn + 1 < nt_iters) {
            load_kv((itn + 1) & 1, (itn + 1) * 64);
            CP_COMMIT();
            CP_WAIT1();
        } else {
            CP_WAIT0();
        }
        __syncthreads();
        const bf16* ks = Ks + (itn & 1) * 64 * 72;
        const bf16* vs = Vs + (itn & 1) * 64 * 72;

        // S = Q @ K^T  (warp tile 16x32)
        float sacc[4][4];
#pragma unroll
        for (int j = 0; j < 4; ++j)
#pragma unroll
            for (int r = 0; r < 4; ++r) sacc[j][r] = 0.f;
#pragma unroll
        for (int kk0 = 0; kk0 < 4; ++kk0) {
            int kb = kk0 * 16;
            unsigned af[4];
            af[0] = ldu(Qs + (wm + g) * 72 + kb + 2*t);
            af[1] = ldu(Qs + (wm + 8 + g) * 72 + kb + 2*t);
            af[2] = ldu(Qs + (wm + g) * 72 + kb + 8 + 2*t);
            af[3] = ldu(Qs + (wm + 8 + g) * 72 + kb + 8 + 2*t);
#pragma unroll
            for (int j = 0; j < 4; ++j) {
                int nb = wn + j * 8 + g;
                unsigned bfr[2];
                bfr[0] = ldu(ks + nb * 72 + kb + 2*t);
                bfr[1] = ldu(ks + nb * 72 + kb + 8 + 2*t);
                mma_bf(sacc[j], af, bfr);
            }
        }
        // online softmax
        float tm0 = -1e30f, tm1 = -1e30f;
#pragma unroll
        for (int j = 0; j < 4; ++j) {
            tm0 = fmaxf(tm0, fmaxf(sacc[j][0], sacc[j][1]));
            tm1 = fmaxf(tm1, fmaxf(sacc[j][2], sacc[j][3]));
        }
        tm0 = fmaxf(tm0, __shfl_xor_sync(0xffffffffu, tm0, 1));
        tm0 = fmaxf(tm0, __shfl_xor_sync(0xffffffffu, tm0, 2));
        tm1 = fmaxf(tm1, __shfl_xor_sync(0xffffffffu, tm1, 1));
        tm1 = fmaxf(tm1, __shfl_xor_sync(0xffffffffu, tm1, 2));
        float nm0 = fmaxf(rmax0, tm0), nm1 = fmaxf(rmax1, tm1);
        float sc0 = __expf(rmax0 - nm0), sc1 = __expf(rmax1 - nm1);
        float ts0 = 0.f, ts1 = 0.f;
#pragma unroll
        for (int j = 0; j < 4; ++j) {
            sacc[j][0] = __expf(sacc[j][0] - nm0);
            sacc[j][1] = __expf(sacc[j][1] - nm0);
            sacc[j][2] = __expf(sacc[j][2] - nm1);
            sacc[j][3] = __expf(sacc[j][3] - nm1);
            ts0 += sacc[j][0] + sacc[j][1];
            ts1 += sacc[j][2] + sacc[j][3];
        }
        ts0 += __shfl_xor_sync(0xffffffffu, ts0, 1);
        ts0 += __shfl_xor_sync(0xffffffffu, ts0, 2);
        ts1 += __shfl_xor_sync(0xffffffffu, ts1, 1);
        ts1 += __shfl_xor_sync(0xffffffffu, ts1, 2);
        rsum0 = rsum0 * sc0 + ts0;
        rsum1 = rsum1 * sc1 + ts1;
        rmax0 = nm0; rmax1 = nm1;
#pragma unroll
        for (int nt = 0; nt < 8; ++nt) {
            acc2[nt][0] *= sc0; acc2[nt][1] *= sc0;
            acc2[nt][2] *= sc1; acc2[nt][3] *= sc1;
        }
        // acc2 += P @ V : A-frag is packed accumulators (no shuffles)
#pragma unroll
        for (int kc = 0; kc < 2; ++kc) {
            int kb2 = wn + kc * 16;
            unsigned af2[4];
            af2[0] = pk(sacc[kc*2][0], sacc[kc*2][1]);
            af2[1] = pk(sacc[kc*2][2], sacc[kc*2][3]);
            af2[2] = pk(sacc[kc*2+1][0], sacc[kc*2+1][1]);
            af2[3] = pk(sacc[kc*2+1][2], sacc[kc*2+1][3]);
#pragma unroll
            for (int nt = 0; nt < 8; ++nt) {
                int n = nt * 8 + g;
                unsigned bfv[2];
                bfv[0] = lds2(vs, (kb2 + 2*t) * 72 + n,     (kb2 + 2*t + 1) * 72 + n);
                bfv[1] = lds2(vs, (kb2 + 8 + 2*t) * 72 + n, (kb2 + 9 + 2*t) * 72 + n);
                mma_bf(acc2[nt], af2, bfv);
            }
        }
        __syncthreads();
    }

    // merge the two n-warps
    if (t == 0) {
        wmax[wni*64 + wm + g]     = rmax0;
        wmax[wni*64 + wm + 8 + g] = rmax1;
        wsum[wni*64 + wm + g]     = rsum0;
        wsum[wni*64 + wm + 8 + g] = rsum1;
    }
    __syncthreads();
    int other = wni ^ 1;
    float om0 = wmax[other*64 + wm + g],     os0 = wsum[other*64 + wm + g];
    float om1 = wmax[other*64 + wm + 8 + g], os1 = wsum[other*64 + wm + 8 + g];
    float gm0 = fmaxf(rmax0, om0), gm1 = fmaxf(rmax1, om1);
    float f0 = __expf(rmax0 - gm0), f1 = __expf(rmax1 - gm1);
    float gs0 = rsum0 * f0 + os0 * __expf(om0 - gm0);
    float gs1 = rsum1 * f1 + os1 * __expf(om1 - gm1);
#pragma unroll
    for (int nt = 0; nt < 8; ++nt) {
        acc2[nt][0] *= f0; acc2[nt][1] *= f0;
        acc2[nt][2] *= f1; acc2[nt][3] *= f1;
    }
    __syncthreads();
    if (wni == 1) {
#pragma unroll
        for (int nt = 0; nt < 8; ++nt) {
            *(float2*)&macc[(wm + g)*64 + nt*8 + 2*t]     = make_float2(acc2[nt][0], acc2[nt][1]);
            *(float2*)&macc[(wm + 8 + g)*64 + nt*8 + 2*t] = make_float2(acc2[nt][2], acc2[nt][3]);
        }
    }
    __syncthreads();
    if (FINAL) {
        if (wni == 0) {
            float inv0 = 1.f / gs0, inv1 = 1.f / gs1;
#pragma unroll
            for (int nt = 0; nt < 8; ++nt) {
                int cc = nt*8 + 2*t;
                float2 m0v = *(float2*)&macc[(wm + g)*64 + cc];
                float2 m1v = *(float2*)&macc[(wm + 8 + g)*64 + cc];
                *(float2*)&macc[(wm + g)*64 + cc] =
                    make_float2((acc2[nt][0] + m0v.x) * inv0, (acc2[nt][1] + m0v.y) * inv0);
                *(float2*)&macc[(wm + 8 + g)*64 + cc] =
                    make_float2((acc2[nt][2] + m1v.x) * inv1, (acc2[nt][3] + m1v.y) * inv1);
            }
        }
        __syncthreads();
        const int h = bh & 7, b = bh >> 3;
        if (tid < KSZ) wsm[tid] = cw[h * KSZ + tid];
        const bf16* Vb2 = Vg + (long long)bh * SEQ * DH;
#pragma unroll
        for (int it = 0; it < 12; ++it) {
            int pp = it * 256 + tid;
            int rr = pp >> 5, c2 = (pp & 31) << 1;
            int gi = m0 - 16 + rr;
            unsigned val = 0;
            if (gi >= 0 && gi < SEQ) val = *(const unsigned*)(Vb2 + (long long)gi * DH + c2);
            *(unsigned*)(VW + rr * 64 + c2) = val;
        }
        __syncthreads();
        int c = tid & 63, ib = tid >> 6;
#pragma unroll 4
        for (int j = 0; j < 16; ++j) {
            int il = ib * 16 + j;
            float accv = macc[il * 64 + c];
#pragma unroll
            for (int tt = 0; tt < KSZ; ++tt)
                accv += wsm[tt] * __bfloat162float(VW[(il + tt) * 64 + c]);
            long long tok = (long long)b * SEQ + m0 + il;
            TOK[tok * DMODEL + h * DH + c] = __float2bfloat16(accv);
        }
    } else {
        if (wni == 0) {
            int row0 = m0 + wm + g, row1 = row0 + 8;
            long long pb = ((long long)bh * NCHUNK + ck) * M_total;
            float* O = OUT + pb * DH;
#pragma unroll
            for (int nt = 0; nt < 8; ++nt) {
                int cc = nt*8 + 2*t;
                float2 m0v = *(float2*)&macc[(wm + g)*64 + cc];
                float2 m1v = *(float2*)&macc[(wm + 8 + g)*64 + cc];
                *(float2*)(O + (long long)row0 * DH + cc) =
                    make_float2(acc2[nt][0] + m0v.x, acc2[nt][1] + m0v.y);
                *(float2*)(O + (long long)row1 * DH + cc) =
                    make_float2(acc2[nt][2] + m1v.x, acc2[nt][3] + m1v.y);
            }
            if (t == 0) {
                PMAX[pb + row0] = gm0; PMAX[pb + row1] = gm1;
                PSUM[pb + row0] = gs0; PSUM[pb + row1] = gs1;
            }
        }
    }
}

// ---------------- combine chunk partials -> a3v (fp32) ----------------------
__global__ void sav_combine(const float* __restrict__ pacc, const float* __restrict__ pmax,
                            const float* __restrict__ psum, float* __restrict__ out)
{
    int idx = blockIdx.x * 256 + threadIdx.x;
    int d = idx & 63;
    int m = (idx >> 6) & (LM - 1);
    int bh = idx >> 14;
    float gmax = -1e30f;
#pragma unroll
    for (int ck = 0; ck < NCHUNK; ++ck)
        gmax = fmaxf(gmax, pmax[((long long)bh * NCHUNK + ck) * LM + m]);
    float gsum = 0.f, val = 0.f;
#pragma unroll
    for (int ck = 0; ck < NCHUNK; ++ck) {
        long long pb = ((long long)bh * NCHUNK + ck) * LM + m;
        float f = __expf(pmax[pb] - gmax);
        gsum += psum[pb] * f;
        val  += pacc[pb * DH + d] * f;
    }
    out[idx] = val / gsum;
}

// ---------------- row softmax (256-wide rows) ----------------
__global__ void softmax_rows(float* __restrict__ S)
{
    float* row = S + (long long)blockIdx.x * 256;
    int tid = threadIdx.x;
    float v = row[tid];
    __shared__ float red[256];
    red[tid] = v; __syncthreads();
    for (int t = 128; t > 0; t >>= 1) {
        if (tid < t) red[tid] = fmaxf(red[tid], red[tid + t]);
        __syncthreads();
    }
    float mx = red[0]; __syncthreads();
    v = __expf(v - mx);
    red[tid] = v; __syncthreads();
    for (int t = 128; t > 0; t >>= 1) {
        if (tid < t) red[tid] += red[tid + t];
        __syncthreads();
    }
    row[tid] = v / red[0];
}

// ---------------- pinv scale ----------------
__global__ void colrow_max(const float* __restrict__ A2, float* __restrict__ s)
{
    int bh = blockIdx.x, j = threadIdx.x;
    const float* X = A2 + (long long)bh * LM * LM;
    float cs = 0.f, rs = 0.f;
    for (int i = 0; i < LM; ++i) {
        cs += fabsf(X[i * LM + j]);
        rs += fabsf(X[j * LM + i]);
    }
    __shared__ float r1[256], r2[256];
    r1[j] = cs; r2[j] = rs; __syncthreads();
    for (int t = 128; t > 0; t >>= 1) {
        if (j < t) { r1[j] = fmaxf(r1[j], r1[j+t]); r2[j] = fmaxf(r2[j], r2[j+t]); }
        __syncthreads();
    }
    if (j == 0) { s[bh] = r1[0]; s[32 + bh] = r2[0]; }
}

__global__ void make_z0(const float* __restrict__ A2, const float* __restrict__ s,
                        float* __restrict__ Z)
{
    __shared__ float red[64];
    int tid = threadIdx.x;
    if (tid < 64) red[tid] = s[tid];
    __syncthreads();
    float cm = red[0], rm = red[32];
#pragma unroll
    for (int i = 1; i < 32; ++i) { cm = fmaxf(cm, red[i]); rm = fmaxf(rm, red[32 + i]); }
    float inv = 1.f / (cm * rm);
    long long idx = (long long)blockIdx.x * 256 + tid;
    int c  = idx & 255;
    int r  = (int)((idx >> 8) & 255);
    int bh = (int)(idx >> 16);
    Z[idx] = A2[(long long)bh * LM * LM + (long long)c * LM + r] * inv;
}

// ---------------- host driver ----------------
extern "C" void kernel_launch(void* const* d_in, const int* in_sizes, int n_in,
                              void* d_out, int out_size)
{
    const float* x      = (const float*)d_in[0];
    const float* ln_w   = (const float*)d_in[1];
    const float* ln_b   = (const float*)d_in[2];
    const float* w_qkv  = (const float*)d_in[3];
    const float* w_out  = (const float*)d_in[4];
    const float* b_out  = (const float*)d_in[5];
    const float* conv_w = (const float*)d_in[6];
    float* out = (float*)d_out;

    static cudaStream_t s1 = nullptr;
    static cudaEvent_t evFork = nullptr, evJoin = nullptr;
    if (s1 == nullptr) {
        cudaStreamCreateWithFlags(&s1, cudaStreamNonBlocking);
        cudaEventCreateWithFlags(&evFork, cudaEventDisableTiming);
        cudaEventCreateWithFlags(&evJoin, cudaEventDisableTiming);
    }

    void *p;
    cudaGetSymbolAddress(&p, g_xnb);   bf16* XNB = (bf16*)p;
    cudaGetSymbolAddress(&p, g_xnlb);  bf16* XNLB= (bf16*)p;
    cudaGetSymbolAddress(&p, g_wqkvb); bf16* WQB = (bf16*)p;
    cudaGetSymbolAddress(&p, g_woutb); bf16* WOB = (bf16*)p;
    cudaGetSymbolAddress(&p, g_qb);    bf16* Qb  = (bf16*)p;
    cudaGetSymbolAddress(&p, g_kb);    bf16* Kb  = (bf16*)p;
    cudaGetSymbolAddress(&p, g_vb);    bf16* Vb  = (bf16*)p;
    cudaGetSymbolAddress(&p, g_ql);    float* QL = (float*)p;
    cudaGetSymbolAddress(&p, g_kl);    float* KL = (float*)p;
    cudaGetSymbolAddress(&p, g_qlb);   bf16* QLb = (bf16*)p;
    cudaGetSymbolAddress(&p, g_klb);   bf16* KLb = (bf16*)p;
    cudaGetSymbolAddress(&p, g_attn2); float* A2 = (float*)p;
    cudaGetSymbolAddress(&p, g_za);    float* ZA = (float*)p;
    cudaGetSymbolAddress(&p, g_zb);    float* ZB = (float*)p;
    cudaGetSymbolAddress(&p, g_xz);    float* XZ = (float*)p;
    cudaGetSymbolAddress(&p, g_t1);    float* T1 = (float*)p;
    cudaGetSymbolAddress(&p, g_t2);    float* T2 = (float*)p;
    cudaGetSymbolAddress(&p, g_a3v);   float* A3V= (float*)p;
    cudaGetSymbolAddress(&p, g_zavb);  bf16* ZAVb= (bf16*)p;
    cudaGetSymbolAddress(&p, g_tokb);  bf16* TOKb= (bf16*)p;
    cudaGetSymbolAddress(&p, g_pacc);  float* PAC= (float*)p;
    cudaGetSymbolAddress(&p, g_pmax);  float* PMX= (float*)p;
    cudaGetSymbolAddress(&p, g_psum);  float* PSM= (float*)p;
    cudaGetSymbolAddress(&p, g_scale); float* S  = (float*)p;

    const long long sL  = (long long)LM * DH;
    const long long sA2 = (long long)LM * LM;

    const int bf_smem = 3 * (128*40 + 128*40) * 2;   // 61440
    cudaFuncSetAttribute(gemm_bf<128,128,2,2,0>, cudaFuncAttributeMaxDynamicSharedMemorySize, bf_smem);
    cudaFuncSetAttribute(gemm_bf<128,128,2,2,1>, cudaFuncAttributeMaxDynamicSharedMemorySize, bf_smem);
    cudaFuncSetAttribute(gemm_bf<128,128,2,2,3>, cudaFuncAttributeMaxDynamicSharedMemorySize, bf_smem);
    cudaFuncSetAttribute(fused_sav<true>,  cudaFuncAttributeMaxDynamicSharedMemorySize, SAV_SMEM_BYTES);
    cudaFuncSetAttribute(fused_sav<false>, cudaFuncAttributeMaxDynamicSharedMemorySize, SAV_SMEM_BYTES);

    // ---- prefix (stream 0) ----
    cvt_bf<<<(3*DMODEL*DMODEL/2 + 255)/256, 256>>>(w_qkv, WQB, 3*DMODEL*DMODEL/2);
    cvt_bf<<<(DMODEL*DMODEL/2 + 255)/256, 256>>>(w_out, WOB, DMODEL*DMODEL/2);
    ln_kernel<<<NTOK, 128>>>(x, ln_w, ln_b, XNB);
    group_mean<<<NGRP, 128>>>(XNB, XNLB);
    gemm_bf<128,128,2,2,3><<<dim3(8, 8, 1), 128, bf_smem>>>(XNLB, WQB, nullptr,
        NGRP, 2*DMODEL, DMODEL, nullptr, nullptr, QL, KL, QLb, KLb, nullptr);

    // ---- fork: branch A (serial pinv chain, tf32) on s1 ----
    cudaEventRecord(evFork, 0);
    cudaStreamWaitEvent(s1, evFork, 0);
    gemm_tc<64,64,2,2,true,0><<<dim3(4, 4, BH), 128, 0, s1>>>(QL, KL, A2,
        LM, LM, DH, sL, sL, sA2, 1.f, 0.f, nullptr, 0.f, nullptr);
    softmax_rows<<<BH*LM, 256, 0, s1>>>(A2);
    colrow_max<<<BH, 256, 0, s1>>>(A2, S);
    make_z0<<<(BH*LM*LM)/256, 256, 0, s1>>>(A2, S, ZA);
    float* Zin = ZA; float* Zout = ZB;
    for (int it = 0; it < 6; ++it) {
        gemm_tc<64,64,2,2,false,2><<<dim3(4,4,BH), 128, 0, s1>>>(A2, Zin, XZ,
            LM, LM, LM, sA2, sA2, sA2, 1.f, 0.f, T1, 7.f, nullptr);
        gemm_tc<64,64,2,2,false,0><<<dim3(4,4,BH), 128, 0, s1>>>(XZ, T1, T2,
            LM, LM, LM, sA2, sA2, sA2, -1.f, 15.f, nullptr, 0.f, nullptr);
        gemm_tc<64,64,2,2,false,0><<<dim3(4,4,BH), 128, 0, s1>>>(XZ, T2, T1,
            LM, LM, LM, sA2, sA2, sA2, -1.f, 13.f, nullptr, 0.f, nullptr);
        gemm_tc<64,64,2,2,false,0><<<dim3(4,4,BH), 128, 0, s1>>>(Zin, T1, Zout,
            LM, LM, LM, sA2, sA2, sA2, 0.25f, 0.f, nullptr, 0.f, nullptr);
        float* tmp = Zin; Zin = Zout; Zout = tmp;
    }
    cudaEventRecord(evJoin, s1);

    // ---- branch B (bf16, throughput-bound) on stream 0 ----
    gemm_bf<128,128,2,2,1><<<dim3(12, 256, 1), 128, bf_smem>>>(XNB, WQB, nullptr,
        NTOK, 3*DMODEL, DMODEL, nullptr, nullptr, nullptr, nullptr, Qb, Kb, Vb);
    fused_sav<false><<<dim3(LM/64, NCHUNK, BH), 256, SAV_SMEM_BYTES>>>(QLb, Kb, Vb,
        PAC, PMX, PSM, LM, SEQ, SEQ/NCHUNK, nullptr, nullptr, nullptr);
    sav_combine<<<(BH*LM*DH)/256, 256>>>(PAC, PMX, PSM, A3V);

    // ---- join ----
    cudaStreamWaitEvent(0, evJoin, 0);
    gemm_tc<64,64,2,2,false,4><<<dim3(1, 4, BH), 128>>>(Zin, A3V, nullptr,
        LM, DH, LM, sA2, sL, sL, 1.f, 0.f, nullptr, 0.f, (float*)ZAVb);
    fused_sav<true><<<dim3(SEQ/64, 1, BH), 256, SAV_SMEM_BYTES>>>(Qb, KLb, ZAVb,
        nullptr, nullptr, nullptr, SEQ, LM, LM, Vb, conv_w, TOKb);
    gemm_bf<128,128,2,2,0><<<dim3(4, 256, 1), 128, bf_smem>>>(TOKb, WOB, out,
        NTOK, DMODEL, DMODEL, b_out, x, nullptr, nullptr, nullptr, nullptr, nullptr);
}

// round 10
// speedup vs baseline: 1.4260x; 1.0362x over previous
#include <cuda_runtime.h>
#include <cuda_bf16.h>
#include <cstdint>

// ---------------- problem constants ----------------
#define BATCH 4
#define SEQ   8192
#define DMODEL 512
#define HEADS 8
#define DH    64
#define LM    256
#define LGRP  32
#define NTOK  (BATCH*SEQ)
#define BH    (BATCH*HEADS)
#define KSZ   33
#define NCHUNK 8
#define NGRP  (NTOK/LGRP)

typedef __nv_bfloat16 bf16;
typedef __nv_bfloat162 bf162;

// ---------------- scratch ----------------
__device__ bf16  g_xnb  [(size_t)NTOK*DMODEL];
__device__ bf16  g_xnlb [(size_t)NGRP*DMODEL];
__device__ bf16  g_wqkvb[(size_t)3*DMODEL*DMODEL];
__device__ bf16  g_woutb[(size_t)DMODEL*DMODEL];
__device__ bf16  g_qb   [(size_t)BH*SEQ*DH];
__device__ bf16  g_kb   [(size_t)BH*SEQ*DH];
__device__ bf16  g_vb   [(size_t)BH*SEQ*DH];
__device__ float g_ql   [(size_t)BH*LM*DH];
__device__ float g_kl   [(size_t)BH*LM*DH];
__device__ bf16  g_qlb  [(size_t)BH*LM*DH];
__device__ bf16  g_klb  [(size_t)BH*LM*DH];
__device__ float g_attn2[(size_t)BH*LM*LM];
__device__ float g_za   [(size_t)BH*LM*LM];
__device__ float g_zb   [(size_t)BH*LM*LM];
__device__ float g_xz   [(size_t)BH*LM*LM];
__device__ float g_t1   [(size_t)BH*LM*LM];
__device__ float g_t2   [(size_t)BH*LM*LM];
__device__ float g_a3v  [(size_t)BH*LM*DH];
__device__ bf16  g_zavb [(size_t)BH*LM*DH];
__device__ bf16  g_tokb [(size_t)NTOK*DMODEL];
__device__ float g_pacc [(size_t)BH*NCHUNK*LM*DH];
__device__ float g_pmax [(size_t)BH*NCHUNK*LM];
__device__ float g_psum [(size_t)BH*NCHUNK*LM];
__device__ float g_scale[64];

// ---------------- helpers ----------------
__device__ __forceinline__ void mma_tf32(float* c, const unsigned* a, const unsigned* b) {
    asm volatile(
        "mma.sync.aligned.m16n8k8.row.col.f32.tf32.tf32.f32 "
        "{%0,%1,%2,%3},{%4,%5,%6,%7},{%8,%9},{%0,%1,%2,%3};"
        : "+f"(c[0]), "+f"(c[1]), "+f"(c[2]), "+f"(c[3])
        : "r"(a[0]), "r"(a[1]), "r"(a[2]), "r"(a[3]), "r"(b[0]), "r"(b[1]));
}
__device__ __forceinline__ void mma_bf(float* c, const unsigned* a, const unsigned* b) {
    asm volatile(
        "mma.sync.aligned.m16n8k16.row.col.f32.bf16.bf16.f32 "
        "{%0,%1,%2,%3},{%4,%5,%6,%7},{%8,%9},{%0,%1,%2,%3};"
        : "+f"(c[0]), "+f"(c[1]), "+f"(c[2]), "+f"(c[3])
        : "r"(a[0]), "r"(a[1]), "r"(a[2]), "r"(a[3]), "r"(b[0]), "r"(b[1]));
}
__device__ __forceinline__ void cpa16(void* s, const void* g) {
    unsigned sa = (unsigned)__cvta_generic_to_shared(s);
    asm volatile("cp.async.cg.shared.global [%0], [%1], 16;" :: "r"(sa), "l"(g));
}
#define CP_COMMIT() asm volatile("cp.async.commit_group;")
#define CP_WAIT1()  asm volatile("cp.async.wait_group 1;")
#define CP_WAIT0()  asm volatile("cp.async.wait_group 0;")

__device__ __forceinline__ unsigned fu(float f) { return __float_as_uint(f); }
__device__ __forceinline__ unsigned pk(float lo, float hi) {
    unsigned r;
    asm("cvt.rn.bf16x2.f32 %0, %1, %2;" : "=r"(r) : "f"(hi), "f"(lo));
    return r;
}
__device__ __forceinline__ unsigned ldu(const bf16* p) { return *(const unsigned*)p; }
__device__ __forceinline__ unsigned lds2(const bf16* p, int i0, int i1) {
    unsigned lo = *(const unsigned short*)(p + i0);
    unsigned hi = *(const unsigned short*)(p + i1);
    return lo | (hi << 16);
}

// ---------------- fp32 -> bf16 convert ----------------
__global__ void cvt_bf(const float* __restrict__ src, bf16* __restrict__ dst, int n2)
{
    int i = blockIdx.x * 256 + threadIdx.x;
    if (i < n2) {
        float2 v = *(const float2*)(src + 2 * i);
        *(unsigned*)(dst + 2 * i) = pk(v.x, v.y);
    }
}

// ---------------- LayerNorm -> bf16 ----------------
__global__ void ln_kernel(const float* __restrict__ x, const float* __restrict__ w,
                          const float* __restrict__ b, bf16* __restrict__ y)
{
    int row = blockIdx.x;
    int tid = threadIdx.x;
    const float* xr = x + (long long)row * DMODEL;
    float4 v = *(const float4*)(xr + tid * 4);
    float s  = v.x + v.y + v.z + v.w;
    float s2 = v.x*v.x + v.y*v.y + v.z*v.z + v.w*v.w;
    __shared__ float r1[128], r2[128];
    r1[tid] = s; r2[tid] = s2; __syncthreads();
    for (int t = 64; t > 0; t >>= 1) {
        if (tid < t) { r1[tid] += r1[tid+t]; r2[tid] += r2[tid+t]; }
        __syncthreads();
    }
    float mean = r1[0] * (1.0f / DMODEL);
    float var  = r2[0] * (1.0f / DMODEL) - mean * mean;
    float inv  = rsqrtf(var + 1e-5f);
    float4 w4 = *(const float4*)(w + tid * 4);
    float4 b4 = *(const float4*)(b + tid * 4);
    float o0 = (v.x - mean) * inv * w4.x + b4.x;
    float o1 = (v.y - mean) * inv * w4.y + b4.y;
    float o2 = (v.z - mean) * inv * w4.z + b4.z;
    float o3 = (v.w - mean) * inv * w4.w + b4.w;
    uint2 u; u.x = pk(o0, o1); u.y = pk(o2, o3);
    *(uint2*)(y + (long long)row * DMODEL + tid * 4) = u;
}

// ---------------- group mean over 32 consecutive tokens ----------------
__global__ void group_mean(const bf16* __restrict__ xn, bf16* __restrict__ xnl)
{
    int g = blockIdx.x;
    int tid = threadIdx.x;
    const bf162* p = (const bf162*)(xn + (long long)g * LGRP * DMODEL) + tid * 2;
    float2 s0 = make_float2(0.f, 0.f), s1 = make_float2(0.f, 0.f);
#pragma unroll
    for (int i = 0; i < LGRP; ++i) {
        float2 a = __bfloat1622float2(p[(long long)i * (DMODEL/2)]);
        float2 b = __bfloat1622float2(p[(long long)i * (DMODEL/2) + 1]);
        s0.x += a.x; s0.y += a.y; s1.x += b.x; s1.y += b.y;
    }
    const float inv = 1.f / LGRP;
    uint2 u; u.x = pk(s0.x * inv, s0.y * inv); u.y = pk(s1.x * inv, s1.y * inv);
    *(uint2*)(xnl + (long long)g * DMODEL + tid * 4) = u;
}

// ---------------- bf16 tensor-core GEMM (m16n8k16), TB layout, 3-stage, BK=64 ----
// MODE 0: C = acc + bias + resid (fp32 out)
// MODE 1: qkv split -> Qb,Kb,Vb bf16 head-major (Q x0.125)
// MODE 3: ql/kl split (N=1024) -> Qf,Kf fp32 AND Qb,Kb bf16 head-major (Q x0.125)
template<int BM, int BN, int WARPS_M, int WARPS_N, int MODE>
__global__ void __launch_bounds__(32*WARPS_M*WARPS_N) gemm_bf(
    const bf16* __restrict__ A, const bf16* __restrict__ B, float* __restrict__ C,
    int M, int N, int K,
    const float* __restrict__ bias, const float* __restrict__ resid,
    float* __restrict__ Qf, float* __restrict__ Kf,
    bf16* __restrict__ Qb, bf16* __restrict__ Kb, bf16* __restrict__ Vb)
{
    constexpr int BK  = 64;
    constexpr int NTH = 32 * WARPS_M * WARPS_N;
    constexpr int WM  = BM / WARPS_M;
    constexpr int WN  = BN / WARPS_N;
    constexpr int MT  = WM / 16;
    constexpr int NT  = WN / 8;
    constexpr int RS  = BK + 8;           // 72 bf16 row stride
    constexpr int SA  = BM * RS;
    constexpr int SB  = BN * RS;
    constexpr int CPR = BK / 8;           // 16B chunks per row (8)
    constexpr int AC  = BM * CPR / NTH;
    constexpr int BC  = BN * CPR / NTH;

    extern __shared__ __align__(16) bf16 sm[];

    const int tid  = threadIdx.x;
    const int w    = tid >> 5, lane = tid & 31;
    const int g    = lane >> 2, t = lane & 3;
    const int wm   = (w / WARPS_N) * WM;
    const int wn   = (w % WARPS_N) * WN;
    const int m0   = blockIdx.y * BM;
    const int n0   = blockIdx.x * BN;

    float acc[MT][NT][4];
#pragma unroll
    for (int i = 0; i < MT; i++)
#pragma unroll
        for (int j = 0; j < NT; j++)
#pragma unroll
            for (int r = 0; r < 4; r++) acc[i][j][r] = 0.f;

    auto load_stage = [&](int st, int k0) {
        bf16* as = sm + st * (SA + SB);
        bf16* bs = as + SA;
#pragma unroll
        for (int it = 0; it < AC; ++it) {
            int idx = it * NTH + tid;
            int r = idx / CPR, ch = (idx % CPR) << 3;
            cpa16(as + r * RS + ch, A + (long long)(m0 + r) * K + k0 + ch);
        }
#pragma unroll
        for (int it = 0; it < BC; ++it) {
            int idx = it * NTH + tid;
            int r = idx / CPR, ch = (idx % CPR) << 3;
            cpa16(bs + r * RS + ch, B + (long long)(n0 + r) * K + k0 + ch);
        }
    };

    const int nk = K / BK;
    load_stage(0, 0);
    CP_COMMIT();
    if (nk > 1) { load_stage(1, BK); CP_COMMIT(); }

    for (int kt = 0; kt < nk; ++kt) {
        if (kt + 2 < nk) {
            CP_WAIT1();
            __syncthreads();
            load_stage((kt + 2) % 3, (kt + 2) * BK);
            CP_COMMIT();
        } else if (kt + 1 < nk) {
            CP_WAIT1();
            __syncthreads();
        } else {
            CP_WAIT0();
            __syncthreads();
        }
        const bf16* as = sm + (kt % 3) * (SA + SB);
        const bf16* bs = as + SA;
#pragma unroll
        for (int ks = 0; ks < 4; ++ks) {
            const int kb = ks * 16;
            unsigned af[MT][4], bfr[NT][2];
#pragma unroll
            for (int i = 0; i < MT; i++) {
                int mb = wm + i * 16;
                af[i][0] = ldu(as + (mb + g) * RS + kb + 2*t);
                af[i][1] = ldu(as + (mb + 8 + g) * RS + kb + 2*t);
                af[i][2] = ldu(as + (mb + g) * RS + kb + 8 + 2*t);
                af[i][3] = ldu(as + (mb + 8 + g) * RS + kb + 8 + 2*t);
            }
#pragma unroll
            for (int j = 0; j < NT; j++) {
                int nb = wn + j * 8 + g;
                bfr[j][0] = ldu(bs + nb * RS + kb + 2*t);
                bfr[j][1] = ldu(bs + nb * RS + kb + 8 + 2*t);
            }
#pragma unroll
            for (int i = 0; i < MT; i++)
#pragma unroll
                for (int j = 0; j < NT; j++)
                    mma_bf(acc[i][j], af[i], bfr[j]);
        }
    }

    // epilogue
#pragma unroll
    for (int i = 0; i < MT; i++) {
        int gm = m0 + wm + i * 16 + g;
#pragma unroll
        for (int j = 0; j < NT; j++) {
            int gn = n0 + wn + j * 8 + 2 * t;
            float v00 = acc[i][j][0], v01 = acc[i][j][1];
            float v10 = acc[i][j][2], v11 = acc[i][j][3];
            if (MODE == 1) {
                int which = gn >> 9;
                int h = (gn >> 6) & 7;
                int c = gn & 63;
                float sc = (which == 0) ? 0.125f : 1.f;
                bf16* tgt = (which == 0) ? Qb : ((which == 1) ? Kb : Vb);
                int b0i = gm >> 13, i0i = gm & (SEQ - 1);
                int b1i = (gm + 8) >> 13, i1i = (gm + 8) & (SEQ - 1);
                long long d0 = (((long long)(b0i * HEADS + h)) * SEQ + i0i) * DH + c;
                long long d1 = (((long long)(b1i * HEADS + h)) * SEQ + i1i) * DH + c;
                *(unsigned*)(tgt + d0) = pk(v00 * sc, v01 * sc);
                *(unsigned*)(tgt + d1) = pk(v10 * sc, v11 * sc);
            } else if (MODE == 3) {
                int which = gn >> 9;
                int h = (gn >> 6) & 7;
                int c = gn & 63;
                float sc = (which == 0) ? 0.125f : 1.f;
                float* tf = (which == 0) ? Qf : Kf;
                bf16*  tb = (which == 0) ? Qb : Kb;
                int b0i = gm >> 8, m0i = gm & 255;
                int b1i = (gm + 8) >> 8, m1i = (gm + 8) & 255;
                long long d0 = (((long long)(b0i * HEADS + h)) * LM + m0i) * DH + c;
                long long d1 = (((long long)(b1i * HEADS + h)) * LM + m1i) * DH + c;
                *(float2*)(tf + d0) = make_float2(v00 * sc, v01 * sc);
                *(float2*)(tf + d1) = make_float2(v10 * sc, v11 * sc);
                *(unsigned*)(tb + d0) = pk(v00 * sc, v01 * sc);
                *(unsigned*)(tb + d1) = pk(v10 * sc, v11 * sc);
            } else {
                if (bias) {
                    v00 += bias[gn]; v01 += bias[gn + 1];
                    v10 += bias[gn]; v11 += bias[gn + 1];
                }
                if (resid) {
                    v00 += resid[(long long)gm * N + gn];
                    v01 += resid[(long long)gm * N + gn + 1];
                    v10 += resid[(long long)(gm + 8) * N + gn];
                    v11 += resid[(long long)(gm + 8) * N + gn + 1];
                }
                *(float2*)(C + (long long)gm * N + gn)       = make_float2(v00, v01);
                *(float2*)(C + (long long)(gm + 8) * N + gn) = make_float2(v10, v11);
            }
        }
    }
}

// ---------------- tf32 tensor-core GEMM (pinv chain + attn2 + ZAV) ----------
// MODE 0: C = alpha*A@op(B) + betaI*I
// MODE 2: C = alpha*A@op(B); C2 = beta2*I - C
// MODE 4: bf16 out via Qp pointer (no C)
template<int BM, int BN, int WARPS_M, int WARPS_N, bool TB, int MODE>
__global__ void __launch_bounds__(32*WARPS_M*WARPS_N) gemm_tc(
    const float* __restrict__ A, const float* __restrict__ B, float* __restrict__ C,
    int M, int N, int K, long long sA, long long sB, long long sC,
    float alpha, float betaI, float* __restrict__ C2, float beta2,
    float* __restrict__ Qp)
{
    constexpr int BK  = 16;
    constexpr int NTH = 32 * WARPS_M * WARPS_N;
    constexpr int WM  = BM / WARPS_M;
    constexpr int WN  = BN / WARPS_N;
    constexpr int MT  = WM / 16;
    constexpr int NT  = WN / 8;
    constexpr int SA  = BM * 20;
    constexpr int SB  = TB ? BN * 20 : BK * (BN + 8);
    constexpr int AC  = BM * 4 / NTH;
    constexpr int BC  = TB ? BN * 4 / NTH : (BK * BN / 4) / NTH;

    const int z = blockIdx.z;
    A += z * sA; B += z * sB;
    if (C)  C  += z * sC;
    if (C2) C2 += z * sC;

    __shared__ float smem[3 * (SA + SB)];

    const int tid  = threadIdx.x;
    const int w    = tid >> 5, lane = tid & 31;
    const int g    = lane >> 2, t = lane & 3;
    const int wm   = (w / WARPS_N) * WM;
    const int wn   = (w % WARPS_N) * WN;
    const int m0   = blockIdx.y * BM;
    const int n0   = blockIdx.x * BN;

    float acc[MT][NT][4];
#pragma unroll
    for (int i = 0; i < MT; i++)
#pragma unroll
        for (int j = 0; j < NT; j++)
#pragma unroll
            for (int r = 0; r < 4; r++) acc[i][j][r] = 0.f;

    auto load_stage = [&](int st, int k0) {
        float* as = smem + st * (SA + SB);
        float* bs = as + SA;
#pragma unroll
        for (int it = 0; it < AC; ++it) {
            int idx = it * NTH + tid;
            int r = idx >> 2, ch = (idx & 3) << 2;
            cpa16(as + r * 20 + ch, A + (long long)(m0 + r) * K + k0 + ch);
        }
        if (TB) {
#pragma unroll
            for (int it = 0; it < BC; ++it) {
                int idx = it * NTH + tid;
                int r = idx >> 2, ch = (idx & 3) << 2;
                cpa16(bs + r * 20 + ch, B + (long long)(n0 + r) * K + k0 + ch);
            }
        } else {
#pragma unroll
            for (int it = 0; it < BC; ++it) {
                int idx = it * NTH + tid;
                int kr = idx / (BN / 4), c = (idx % (BN / 4)) << 2;
                cpa16(bs + kr * (BN + 8) + c, B + (long long)(k0 + kr) * N + n0 + c);
            }
        }
    };

    const int nk = K / BK;
    load_stage(0, 0);
    CP_COMMIT();
    if (nk > 1) { load_stage(1, BK); CP_COMMIT(); }

    for (int kt = 0; kt < nk; ++kt) {
        if (kt + 2 < nk) {
            CP_WAIT1();
            __syncthreads();
            load_stage((kt + 2) % 3, (kt + 2) * BK);
            CP_COMMIT();
        } else if (kt + 1 < nk) {
            CP_WAIT1();
            __syncthreads();
        } else {
            CP_WAIT0();
            __syncthreads();
        }
        const float* as = smem + (kt % 3) * (SA + SB);
        const float* bs = as + SA;
#pragma unroll
        for (int ks = 0; ks < 2; ++ks) {
            const int kb = ks * 8;
            unsigned af[MT][4], bfr[NT][2];
#pragma unroll
            for (int i = 0; i < MT; i++) {
                int mb = wm + i * 16;
                af[i][0] = fu(as[(mb + g) * 20 + kb + t]);
                af[i][1] = fu(as[(mb + 8 + g) * 20 + kb + t]);
                af[i][2] = fu(as[(mb + g) * 20 + kb + t + 4]);
                af[i][3] = fu(as[(mb + 8 + g) * 20 + kb + t + 4]);
            }
#pragma unroll
            for (int j = 0; j < NT; j++) {
                int nb = wn + j * 8 + g;
                if (TB) {
                    bfr[j][0] = fu(bs[nb * 20 + kb + t]);
                    bfr[j][1] = fu(bs[nb * 20 + kb + t + 4]);
                } else {
                    bfr[j][0] = fu(bs[(kb + t) * (BN + 8) + nb]);
                    bfr[j][1] = fu(bs[(kb + t + 4) * (BN + 8) + nb]);
                }
            }
#pragma unroll
            for (int i = 0; i < MT; i++)
#pragma unroll
                for (int j = 0; j < NT; j++)
                    mma_tf32(acc[i][j], af[i], bfr[j]);
        }
    }

#pragma unroll
    for (int i = 0; i < MT; i++) {
        int gm = m0 + wm + i * 16 + g;
#pragma unroll
        for (int j = 0; j < NT; j++) {
            int gn = n0 + wn + j * 8 + 2 * t;
            float v00 = alpha * acc[i][j][0];
            float v01 = alpha * acc[i][j][1];
            float v10 = alpha * acc[i][j][2];
            float v11 = alpha * acc[i][j][3];
            if (MODE == 4) {
                bf16* Cb = (bf16*)Qp + (long long)z * sC;
                *(unsigned*)(Cb + (long long)gm * N + gn)       = pk(v00, v01);
                *(unsigned*)(Cb + (long long)(gm + 8) * N + gn) = pk(v10, v11);
            } else {
                if (betaI != 0.f) {
                    if (gm == gn)         v00 += betaI;
                    if (gm == gn + 1)     v01 += betaI;
                    if (gm + 8 == gn)     v10 += betaI;
                    if (gm + 8 == gn + 1) v11 += betaI;
                }
                *(float2*)(C + (long long)gm * N + gn)       = make_float2(v00, v01);
                *(float2*)(C + (long long)(gm + 8) * N + gn) = make_float2(v10, v11);
                if (MODE == 2) {
                    float w00 = ((gm == gn)         ? beta2 : 0.f) - v00;
                    float w01 = ((gm == gn + 1)     ? beta2 : 0.f) - v01;
                    float w10 = ((gm + 8 == gn)     ? beta2 : 0.f) - v10;
                    float w11 = ((gm + 8 == gn + 1) ? beta2 : 0.f) - v11;
                    *(float2*)(C2 + (long long)gm * N + gn)       = make_float2(w00, w01);
                    *(float2*)(C2 + (long long)(gm + 8) * N + gn) = make_float2(w10, w11);
                }
            }
        }
    }
}

// ---------------- fused softmax(A@B^T)@C in bf16 ----------------------------
// FINAL: + depthwise conv residual over Vg, writes TOK (bf16) token-major.
#define SAV_SMEM_BYTES (5*64*72*2)
template<bool FINAL>
__global__ void __launch_bounds__(256) fused_sav(
    const bf16* __restrict__ A, const bf16* __restrict__ B, const bf16* __restrict__ C,
    float* __restrict__ OUT, float* __restrict__ PMAX, float* __restrict__ PSUM,
    int M_total, int N_total, int chunk_len,
    const bf16* __restrict__ Vg, const float* __restrict__ cw, bf16* __restrict__ TOK)
{
    extern __shared__ __align__(16) char sb[];
    bf16* Qs = (bf16*)sb;
    bf16* Ks = Qs + 64*72;
    bf16* Vs = Ks + 2*64*72;
    float* macc = (float*)sb;
    float* wmax = (float*)(sb + 16384);
    float* wsum = (float*)(sb + 16896);
    bf16*  VW   = (bf16*)(sb + 17408);
    float* wsm  = (float*)(sb + 17408 + 12288);

    const int bh = blockIdx.z, mt = blockIdx.x, ck = blockIdx.y;
    const int m0 = mt * 64;
    const int tid = threadIdx.x;
    const int w = tid >> 5, lane = tid & 31;
    const int g = lane >> 2, t = lane & 3;
    const int wm = (w >> 1) * 16;
    const int wni = w & 1;
    const int wn = wni * 32;

    const bf16* Ap = A + ((long long)bh * M_total + m0) * DH;
    const bf16* Bb = B + (long long)bh * N_total * DH;
    const bf16* Cb = C + (long long)bh * N_total * DH;

#pragma unroll
    for (int it = 0; it < 2; ++it) {
        int idx = it * 256 + tid;
        int r = idx >> 3, c = (idx & 7) << 3;
        *(uint4*)(Qs + r * 72 + c) = *(const uint4*)(Ap + r * DH + c);
    }

    const int n_start = ck * chunk_len;

    auto load_kv = [&](int st, int nb) {
        const bf16* Kp = Bb + (long long)(n_start + nb) * DH;
        const bf16* Vp = Cb + (long long)(n_start + nb) * DH;
        bf16* ks = Ks + st * 64 * 72;
        bf16* vs = Vs + st * 64 * 72;
#pragma unroll
        for (int it = 0; it < 2; ++it) {
            int idx = it * 256 + tid;
            int r = idx >> 3, c = (idx & 7) << 3;
            cpa16(ks + r * 72 + c, Kp + r * DH + c);
            cpa16(vs + r * 72 + c, Vp + r * DH + c);
        }
    };

    float acc2[8][4];
#pragma unroll
    for (int nt = 0; nt < 8; ++nt)
#pragma unroll
        for (int r = 0; r < 4; ++r) acc2[nt][r] = 0.f;
    float rmax0 = -1e30f, rmax1 = -1e30f, rsum0 = 0.f, rsum1 = 0.f;

    load_kv(0, 0);
    CP_COMMIT();

    const int nt_iters = chunk_len / 64;
    for (int itn = 0; itn < nt_iters; ++itn) {
        if (itn + 1 < nt_iters) {
            load_kv((itn + 1) & 1, (itn + 1) * 64);
            CP_COMMIT();
            CP_WAIT1();
        } else {
            CP_WAIT0();
        }
        __syncthreads();
        const bf16* ks = Ks + (itn & 1) * 64 * 72;
        const bf16* vs = Vs + (itn & 1) * 64 * 72;

        float sacc[4][4];
#pragma unroll
        for (int j = 0; j < 4; ++j)
#pragma unroll
            for (int r = 0; r < 4; ++r) sacc[j][r] = 0.f;
#pragma unroll
        for (int kk0 = 0; kk0 < 4; ++kk0) {
            int kb = kk0 * 16;
            unsigned af[4];
            af[0] = ldu(Qs + (wm + g) * 72 + kb + 2*t);
            af[1] = ldu(Qs + (wm + 8 + g) * 72 + kb + 2*t);
            af[2] = ldu(Qs + (wm + g) * 72 + kb + 8 + 2*t);
            af[3] = ldu(Qs + (wm + 8 + g) * 72 + kb + 8 + 2*t);
#pragma unroll
            for (int j = 0; j < 4; ++j) {
                int nb = wn + j * 8 + g;
                unsigned bfr[2];
                bfr[0] = ldu(ks + nb * 72 + kb + 2*t);
                bfr[1] = ldu(ks + nb * 72 + kb + 8 + 2*t);
                mma_bf(sacc[j], af, bfr);
            }
        }
        float tm0 = -1e30f, tm1 = -1e30f;
#pragma unroll
        for (int j = 0; j < 4; ++j) {
            tm0 = fmaxf(tm0, fmaxf(sacc[j][0], sacc[j][1]));
            tm1 = fmaxf(tm1, fmaxf(sacc[j][2], sacc[j][3]));
        }
        tm0 = fmaxf(tm0, __shfl_xor_sync(0xffffffffu, tm0, 1));
        tm0 = fmaxf(tm0, __shfl_xor_sync(0xffffffffu, tm0, 2));
        tm1 = fmaxf(tm1, __shfl_xor_sync(0xffffffffu, tm1, 1));
        tm1 = fmaxf(tm1, __shfl_xor_sync(0xffffffffu, tm1, 2));
        float nm0 = fmaxf(rmax0, tm0), nm1 = fmaxf(rmax1, tm1);
        float sc0 = __expf(rmax0 - nm0), sc1 = __expf(rmax1 - nm1);
        float ts0 = 0.f, ts1 = 0.f;
#pragma unroll
        for (int j = 0; j < 4; ++j) {
            sacc[j][0] = __expf(sacc[j][0] - nm0);
            sacc[j][1] = __expf(sacc[j][1] - nm0);
            sacc[j][2] = __expf(sacc[j][2] - nm1);
            sacc[j][3] = __expf(sacc[j][3] - nm1);
            ts0 += sacc[j][0] + sacc[j][1];
            ts1 += sacc[j][2] + sacc[j][3];
        }
        ts0 += __shfl_xor_sync(0xffffffffu, ts0, 1);
        ts0 += __shfl_xor_sync(0xffffffffu, ts0, 2);
        ts1 += __shfl_xor_sync(0xffffffffu, ts1, 1);
        ts1 += __shfl_xor_sync(0xffffffffu, ts1, 2);
        rsum0 = rsum0 * sc0 + ts0;
        rsum1 = rsum1 * sc1 + ts1;
        rmax0 = nm0; rmax1 = nm1;
#pragma unroll
        for (int nt = 0; nt < 8; ++nt) {
            acc2[nt][0] *= sc0; acc2[nt][1] *= sc0;
            acc2[nt][2] *= sc1; acc2[nt][3] *= sc1;
        }
#pragma unroll
        for (int kc = 0; kc < 2; ++kc) {
            int kb2 = wn + kc * 16;
            unsigned af2[4];
            af2[0] = pk(sacc[kc*2][0], sacc[kc*2][1]);
            af2[1] = pk(sacc[kc*2][2], sacc[kc*2][3]);
            af2[2] = pk(sacc[kc*2+1][0], sacc[kc*2+1][1]);
            af2[3] = pk(sacc[kc*2+1][2], sacc[kc*2+1][3]);
#pragma unroll
            for (int nt = 0; nt < 8; ++nt) {
                int n = nt * 8 + g;
                unsigned bfv[2];
                bfv[0] = lds2(vs, (kb2 + 2*t) * 72 + n,     (kb2 + 2*t + 1) * 72 + n);
                bfv[1] = lds2(vs, (kb2 + 8 + 2*t) * 72 + n, (kb2 + 9 + 2*t) * 72 + n);
                mma_bf(acc2[nt], af2, bfv);
            }
        }
        __syncthreads();
    }

    if (t == 0) {
        wmax[wni*64 + wm + g]     = rmax0;
        wmax[wni*64 + wm + 8 + g] = rmax1;
        wsum[wni*64 + wm + g]     = rsum0;
        wsum[wni*64 + wm + 8 + g] = rsum1;
    }
    __syncthreads();
    int other = wni ^ 1;
    float om0 = wmax[other*64 + wm + g],     os0 = wsum[other*64 + wm + g];
    float om1 = wmax[other*64 + wm + 8 + g], os1 = wsum[other*64 + wm + 8 + g];
    float gm0 = fmaxf(rmax0, om0), gm1 = fmaxf(rmax1, om1);
    float f0 = __expf(rmax0 - gm0), f1 = __expf(rmax1 - gm1);
    float gs0 = rsum0 * f0 + os0 * __expf(om0 - gm0);
    float gs1 = rsum1 * f1 + os1 * __expf(om1 - gm1);
#pragma unroll
    for (int nt = 0; nt < 8; ++nt) {
        acc2[nt][0] *= f0; acc2[nt][1] *= f0;
        acc2[nt][2] *= f1; acc2[nt][3] *= f1;
    }
    __syncthreads();
    if (wni == 1) {
#pragma unroll
        for (int nt = 0; nt < 8; ++nt) {
            *(float2*)&macc[(wm + g)*64 + nt*8 + 2*t]     = make_float2(acc2[nt][0], acc2[nt][1]);
            *(float2*)&macc[(wm + 8 + g)*64 + nt*8 + 2*t] = make_float2(acc2[nt][2], acc2[nt][3]);
        }
    }
    __syncthreads();
    if (FINAL) {
        if (wni == 0) {
            float inv0 = 1.f / gs0, inv1 = 1.f / gs1;
#pragma unroll
            for (int nt = 0; nt < 8; ++nt) {
                int cc = nt*8 + 2*t;
                float2 m0v = *(float2*)&macc[(wm + g)*64 + cc];
                float2 m1v = *(float2*)&macc[(wm + 8 + g)*64 + cc];
                *(float2*)&macc[(wm + g)*64 + cc] =
                    make_float2((acc2[nt][0] + m0v.x) * inv0, (acc2[nt][1] + m0v.y) * inv0);
                *(float2*)&macc[(wm + 8 + g)*64 + cc] =
                    make_float2((acc2[nt][2] + m1v.x) * inv1, (acc2[nt][3] + m1v.y) * inv1);
            }
        }
        __syncthreads();
        const int h = bh & 7, b = bh >> 3;
        if (tid < KSZ) wsm[tid] = cw[h * KSZ + tid];
        const bf16* Vb2 = Vg + (long long)bh * SEQ * DH;
#pragma unroll
        for (int it = 0; it < 12; ++it) {
            int pp = it * 256 + tid;
            int rr = pp >> 5, c2 = (pp & 31) << 1;
            int gi = m0 - 16 + rr;
            unsigned val = 0;
            if (gi >= 0 && gi < SEQ) val = *(const unsigned*)(Vb2 + (long long)gi * DH + c2);
            *(unsigned*)(VW + rr * 64 + c2) = val;
        }
        __syncthreads();
        int c = tid & 63, ib = tid >> 6;
#pragma unroll 4
        for (int j = 0; j < 16; ++j) {
            int il = ib * 16 + j;
            float accv = macc[il * 64 + c];
#pragma unroll
            for (int tt = 0; tt < KSZ; ++tt)
                accv += wsm[tt] * __bfloat162float(VW[(il + tt) * 64 + c]);
            long long tok = (long long)b * SEQ + m0 + il;
            TOK[tok * DMODEL + h * DH + c] = __float2bfloat16(accv);
        }
    } else {
        if (wni == 0) {
            int row0 = m0 + wm + g, row1 = row0 + 8;
            long long pb = ((long long)bh * NCHUNK + ck) * M_total;
            float* O = OUT + pb * DH;
#pragma unroll
            for (int nt = 0; nt < 8; ++nt) {
                int cc = nt*8 + 2*t;
                float2 m0v = *(float2*)&macc[(wm + g)*64 + cc];
                float2 m1v = *(float2*)&macc[(wm + 8 + g)*64 + cc];
                *(float2*)(O + (long long)row0 * DH + cc) =
                    make_float2(acc2[nt][0] + m0v.x, acc2[nt][1] + m0v.y);
                *(float2*)(O + (long long)row1 * DH + cc) =
                    make_float2(acc2[nt][2] + m1v.x, acc2[nt][3] + m1v.y);
            }
            if (t == 0) {
                PMAX[pb + row0] = gm0; PMAX[pb + row1] = gm1;
                PSUM[pb + row0] = gs0; PSUM[pb + row1] = gs1;
            }
        }
    }
}

// ---------------- combine chunk partials -> a3v ----------------
__global__ void sav_combine(const float* __restrict__ pacc, const float* __restrict__ pmax,
                            const float* __restrict__ psum, float* __restrict__ out)
{
    int idx = blockIdx.x * 256 + threadIdx.x;
    int d = idx & 63;
    int m = (idx >> 6) & (LM - 1);
    int bh = idx >> 14;
    float gmax = -1e30f;
#pragma unroll
    for (int ck = 0; ck < NCHUNK; ++ck)
        gmax = fmaxf(gmax, pmax[((long long)bh * NCHUNK + ck) * LM + m]);
    float gsum = 0.f, val = 0.f;
#pragma unroll
    for (int ck = 0; ck < NCHUNK; ++ck) {
        long long pb = ((long long)bh * NCHUNK + ck) * LM + m;
        float f = __expf(pmax[pb] - gmax);
        gsum += psum[pb] * f;
        val  += pacc[pb * DH + d] * f;
    }
    out[idx] = val / gsum;
}

// ---------------- row softmax ----------------
__global__ void softmax_rows(float* __restrict__ S)
{
    float* row = S + (long long)blockIdx.x * 256;
    int tid = threadIdx.x;
    float v = row[tid];
    __shared__ float red[256];
    red[tid] = v; __syncthreads();
    for (int t = 128; t > 0; t >>= 1) {
        if (tid < t) red[tid] = fmaxf(red[tid], red[tid + t]);
        __syncthreads();
    }
    float mx = red[0]; __syncthreads();
    v = __expf(v - mx);
    red[tid] = v; __syncthreads();
    for (int t = 128; t > 0; t >>= 1) {
        if (tid < t) red[tid] += red[tid + t];
        __syncthreads();
    }
    row[tid] = v / red[0];
}

// ---------------- pinv scale ----------------
__global__ void colrow_max(const float* __restrict__ A2, float* __restrict__ s)
{
    int bh = blockIdx.x, j = threadIdx.x;
    const float* X = A2 + (long long)bh * LM * LM;
    float cs = 0.f, rs = 0.f;
    for (int i = 0; i < LM; ++i) {
        cs += fabsf(X[i * LM + j]);
        rs += fabsf(X[j * LM + i]);
    }
    __shared__ float r1[256], r2[256];
    r1[j] = cs; r2[j] = rs; __syncthreads();
    for (int t = 128; t > 0; t >>= 1) {
        if (j < t) { r1[j] = fmaxf(r1[j], r1[j+t]); r2[j] = fmaxf(r2[j], r2[j+t]); }
        __syncthreads();
    }
    if (j == 0) { s[bh] = r1[0]; s[32 + bh] = r2[0]; }
}

__global__ void make_z0(const float* __restrict__ A2, const float* __restrict__ s,
                        float* __restrict__ Z)
{
    __shared__ float red[64];
    int tid = threadIdx.x;
    if (tid < 64) red[tid] = s[tid];
    __syncthreads();
    float cm = red[0], rm = red[32];
#pragma unroll
    for (int i = 1; i < 32; ++i) { cm = fmaxf(cm, red[i]); rm = fmaxf(rm, red[32 + i]); }
    float inv = 1.f / (cm * rm);
    long long idx = (long long)blockIdx.x * 256 + tid;
    int c  = idx & 255;
    int r  = (int)((idx >> 8) & 255);
    int bh = (int)(idx >> 16);
    Z[idx] = A2[(long long)bh * LM * LM + (long long)c * LM + r] * inv;
}

// ---------------- host driver ----------------
extern "C" void kernel_launch(void* const* d_in, const int* in_sizes, int n_in,
                              void* d_out, int out_size)
{
    const float* x      = (const float*)d_in[0];
    const float* ln_w   = (const float*)d_in[1];
    const float* ln_b   = (const float*)d_in[2];
    const float* w_qkv  = (const float*)d_in[3];
    const float* w_out  = (const float*)d_in[4];
    const float* b_out  = (const float*)d_in[5];
    const float* conv_w = (const float*)d_in[6];
    float* out = (float*)d_out;

    static cudaStream_t s1 = nullptr;
    static cudaEvent_t evFork = nullptr, evJoin = nullptr;
    if (s1 == nullptr) {
        cudaStreamCreateWithFlags(&s1, cudaStreamNonBlocking);
        cudaEventCreateWithFlags(&evFork, cudaEventDisableTiming);
        cudaEventCreateWithFlags(&evJoin, cudaEventDisableTiming);
    }

    void *p;
    cudaGetSymbolAddress(&p, g_xnb);   bf16* XNB = (bf16*)p;
    cudaGetSymbolAddress(&p, g_xnlb);  bf16* XNLB= (bf16*)p;
    cudaGetSymbolAddress(&p, g_wqkvb); bf16* WQB = (bf16*)p;
    cudaGetSymbolAddress(&p, g_woutb); bf16* WOB = (bf16*)p;
    cudaGetSymbolAddress(&p, g_qb);    bf16* Qb  = (bf16*)p;
    cudaGetSymbolAddress(&p, g_kb);    bf16* Kb  = (bf16*)p;
    cudaGetSymbolAddress(&p, g_vb);    bf16* Vb  = (bf16*)p;
    cudaGetSymbolAddress(&p, g_ql);    float* QL = (float*)p;
    cudaGetSymbolAddress(&p, g_kl);    float* KL = (float*)p;
    cudaGetSymbolAddress(&p, g_qlb);   bf16* QLb = (bf16*)p;
    cudaGetSymbolAddress(&p, g_klb);   bf16* KLb = (bf16*)p;
    cudaGetSymbolAddress(&p, g_attn2); float* A2 = (float*)p;
    cudaGetSymbolAddress(&p, g_za);    float* ZA = (float*)p;
    cudaGetSymbolAddress(&p, g_zb);    float* ZB = (float*)p;
    cudaGetSymbolAddress(&p, g_xz);    float* XZ = (float*)p;
    cudaGetSymbolAddress(&p, g_t1);    float* T1 = (float*)p;
    cudaGetSymbolAddress(&p, g_t2);    float* T2 = (float*)p;
    cudaGetSymbolAddress(&p, g_a3v);   float* A3V= (float*)p;
    cudaGetSymbolAddress(&p, g_zavb);  bf16* ZAVb= (bf16*)p;
    cudaGetSymbolAddress(&p, g_tokb);  bf16* TOKb= (bf16*)p;
    cudaGetSymbolAddress(&p, g_pacc);  float* PAC= (float*)p;
    cudaGetSymbolAddress(&p, g_pmax);  float* PMX= (float*)p;
    cudaGetSymbolAddress(&p, g_psum);  float* PSM= (float*)p;
    cudaGetSymbolAddress(&p, g_scale); float* S  = (float*)p;

    const long long sL  = (long long)LM * DH;
    const long long sA2 = (long long)LM * LM;

    const int bf_smem = 3 * (128*72 + 128*72) * 2;   // 110592
    cudaFuncSetAttribute(gemm_bf<128,128,2,2,0>, cudaFuncAttributeMaxDynamicSharedMemorySize, bf_smem);
    cudaFuncSetAttribute(gemm_bf<128,128,2,2,1>, cudaFuncAttributeMaxDynamicSharedMemorySize, bf_smem);
    cudaFuncSetAttribute(gemm_bf<128,128,2,2,3>, cudaFuncAttributeMaxDynamicSharedMemorySize, bf_smem);
    cudaFuncSetAttribute(fused_sav<true>,  cudaFuncAttributeMaxDynamicSharedMemorySize, SAV_SMEM_BYTES);
    cudaFuncSetAttribute(fused_sav<false>, cudaFuncAttributeMaxDynamicSharedMemorySize, SAV_SMEM_BYTES);

    // ---- prefix (stream 0) ----
    cvt_bf<<<(3*DMODEL*DMODEL/2 + 255)/256, 256>>>(w_qkv, WQB, 3*DMODEL*DMODEL/2);
    cvt_bf<<<(DMODEL*DMODEL/2 + 255)/256, 256>>>(w_out, WOB, DMODEL*DMODEL/2);
    ln_kernel<<<NTOK, 128>>>(x, ln_w, ln_b, XNB);
    group_mean<<<NGRP, 128>>>(XNB, XNLB);
    gemm_bf<128,128,2,2,3><<<dim3(8, 8, 1), 128, bf_smem>>>(XNLB, WQB, nullptr,
        NGRP, 2*DMODEL, DMODEL, nullptr, nullptr, QL, KL, QLb, KLb, nullptr);

    // ---- fork: branch A (serial pinv chain, tf32) on s1 ----
    cudaEventRecord(evFork, 0);
    cudaStreamWaitEvent(s1, evFork, 0);
    gemm_tc<64,64,2,2,true,0><<<dim3(4, 4, BH), 128, 0, s1>>>(QL, KL, A2,
        LM, LM, DH, sL, sL, sA2, 1.f, 0.f, nullptr, 0.f, nullptr);
    softmax_rows<<<BH*LM, 256, 0, s1>>>(A2);
    colrow_max<<<BH, 256, 0, s1>>>(A2, S);
    make_z0<<<(BH*LM*LM)/256, 256, 0, s1>>>(A2, S, ZA);
    float* Zin = ZA; float* Zout = ZB;
    for (int it = 0; it < 6; ++it) {
        gemm_tc<64,64,2,2,false,2><<<dim3(4,4,BH), 128, 0, s1>>>(A2, Zin, XZ,
            LM, LM, LM, sA2, sA2, sA2, 1.f, 0.f, T1, 7.f, nullptr);
        gemm_tc<64,64,2,2,false,0><<<dim3(4,4,BH), 128, 0, s1>>>(XZ, T1, T2,
            LM, LM, LM, sA2, sA2, sA2, -1.f, 15.f, nullptr, 0.f, nullptr);
        gemm_tc<64,64,2,2,false,0><<<dim3(4,4,BH), 128, 0, s1>>>(XZ, T2, T1,
            LM, LM, LM, sA2, sA2, sA2, -1.f, 13.f, nullptr, 0.f, nullptr);
        gemm_tc<64,64,2,2,false,0><<<dim3(4,4,BH), 128, 0, s1>>>(Zin, T1, Zout,
            LM, LM, LM, sA2, sA2, sA2, 0.25f, 0.f, nullptr, 0.f, nullptr);
        float* tmp = Zin; Zin = Zout; Zout = tmp;
    }
    cudaEventRecord(evJoin, s1);

    // ---- branch B (bf16, throughput-bound) on stream 0 ----
    gemm_bf<128,128,2,2,1><<<dim3(12, 256, 1), 128, bf_smem>>>(XNB, WQB, nullptr,
        NTOK, 3*DMODEL, DMODEL, nullptr, nullptr, nullptr, nullptr, Qb, Kb, Vb);
    fused_sav<false><<<dim3(LM/64, NCHUNK, BH), 256, SAV_SMEM_BYTES>>>(QLb, Kb, Vb,
        PAC, PMX, PSM, LM, SEQ, SEQ/NCHUNK, nullptr, nullptr, nullptr);
    sav_combine<<<(BH*LM*DH)/256, 256>>>(PAC, PMX, PSM, A3V);

    // ---- join ----
    cudaStreamWaitEvent(0, evJoin, 0);
    gemm_tc<64,64,2,2,false,4><<<dim3(1, 4, BH), 128>>>(Zin, A3V, nullptr,
        LM, DH, LM, sA2, sL, sL, 1.f, 0.f, nullptr, 0.f, (float*)ZAVb);
    fused_sav<true><<<dim3(SEQ/64, 1, BH), 256, SAV_SMEM_BYTES>>>(Qb, KLb, ZAVb,
        nullptr, nullptr, nullptr, SEQ, LM, LM, Vb, conv_w, TOKb);
    gemm_bf<128,128,2,2,0><<<dim3(4, 256, 1), 128, bf_smem>>>(TOKb, WOB, out,
        NTOK, DMODEL, DMODEL, b_out, x, nullptr, nullptr, nullptr, nullptr, nullptr);
}

// round 11
// speedup vs baseline: 1.4967x; 1.0496x over previous
#include <cuda_runtime.h>
#include <cuda_bf16.h>
#include <cstdint>

// ---------------- problem constants ----------------
#define BATCH 4
#define SEQ   8192
#define DMODEL 512
#define HEADS 8
#define DH    64
#define LM    256
#define LGRP  32
#define NTOK  (BATCH*SEQ)
#define BH    (BATCH*HEADS)
#define KSZ   33
#define NCHUNK 8
#define NGRP  (NTOK/LGRP)

typedef __nv_bfloat16 bf16;
typedef __nv_bfloat162 bf162;

// ---------------- scratch ----------------
__device__ bf16  g_xnb  [(size_t)NTOK*DMODEL];
__device__ bf16  g_xnlb [(size_t)NGRP*DMODEL];
__device__ bf16  g_wqkvb[(size_t)3*DMODEL*DMODEL];
__device__ bf16  g_woutb[(size_t)DMODEL*DMODEL];
__device__ bf16  g_qb   [(size_t)BH*SEQ*DH];
__device__ bf16  g_kb   [(size_t)BH*SEQ*DH];
__device__ bf16  g_vb   [(size_t)BH*SEQ*DH];
__device__ float g_ql   [(size_t)BH*LM*DH];
__device__ float g_kl   [(size_t)BH*LM*DH];
__device__ bf16  g_qlb  [(size_t)BH*LM*DH];
__device__ bf16  g_klb  [(size_t)BH*LM*DH];
__device__ float g_attn2[(size_t)BH*LM*LM];
__device__ float g_za   [(size_t)BH*LM*LM];
__device__ float g_zb   [(size_t)BH*LM*LM];
__device__ float g_xz   [(size_t)BH*LM*LM];
__device__ float g_t1   [(size_t)BH*LM*LM];
__device__ float g_t2   [(size_t)BH*LM*LM];
__device__ float g_a3v  [(size_t)BH*LM*DH];
__device__ bf16  g_zavb [(size_t)BH*LM*DH];
__device__ bf16  g_tokb [(size_t)NTOK*DMODEL];
__device__ float g_pacc [(size_t)BH*NCHUNK*LM*DH];
__device__ float g_pmax [(size_t)BH*NCHUNK*LM];
__device__ float g_psum [(size_t)BH*NCHUNK*LM];
__device__ float g_scale[64];

// ---------------- helpers ----------------
__device__ __forceinline__ void mma_tf32(float* c, const unsigned* a, const unsigned* b) {
    asm volatile(
        "mma.sync.aligned.m16n8k8.row.col.f32.tf32.tf32.f32 "
        "{%0,%1,%2,%3},{%4,%5,%6,%7},{%8,%9},{%0,%1,%2,%3};"
        : "+f"(c[0]), "+f"(c[1]), "+f"(c[2]), "+f"(c[3])
        : "r"(a[0]), "r"(a[1]), "r"(a[2]), "r"(a[3]), "r"(b[0]), "r"(b[1]));
}
__device__ __forceinline__ void mma_bf(float* c, const unsigned* a, const unsigned* b) {
    asm volatile(
        "mma.sync.aligned.m16n8k16.row.col.f32.bf16.bf16.f32 "
        "{%0,%1,%2,%3},{%4,%5,%6,%7},{%8,%9},{%0,%1,%2,%3};"
        : "+f"(c[0]), "+f"(c[1]), "+f"(c[2]), "+f"(c[3])
        : "r"(a[0]), "r"(a[1]), "r"(a[2]), "r"(a[3]), "r"(b[0]), "r"(b[1]));
}
__device__ __forceinline__ void cpa16(void* s, const void* g) {
    unsigned sa = (unsigned)__cvta_generic_to_shared(s);
    asm volatile("cp.async.cg.shared.global [%0], [%1], 16;" :: "r"(sa), "l"(g));
}
#define CP_COMMIT() asm volatile("cp.async.commit_group;")
#define CP_WAIT1()  asm volatile("cp.async.wait_group 1;")
#define CP_WAIT0()  asm volatile("cp.async.wait_group 0;")

__device__ __forceinline__ unsigned fu(float f) { return __float_as_uint(f); }
__device__ __forceinline__ unsigned pk(float lo, float hi) {
    unsigned r;
    asm("cvt.rn.bf16x2.f32 %0, %1, %2;" : "=r"(r) : "f"(hi), "f"(lo));
    return r;
}
__device__ __forceinline__ unsigned smem_u32(const void* p) {
    return (unsigned)__cvta_generic_to_shared(p);
}
__device__ __forceinline__ void ldm_x4(unsigned* r, unsigned addr) {
    asm volatile("ldmatrix.sync.aligned.m8n8.x4.shared.b16 {%0,%1,%2,%3}, [%4];"
        : "=r"(r[0]), "=r"(r[1]), "=r"(r[2]), "=r"(r[3]) : "r"(addr));
}
__device__ __forceinline__ void ldm_x4_t(unsigned* r, unsigned addr) {
    asm volatile("ldmatrix.sync.aligned.m8n8.x4.trans.shared.b16 {%0,%1,%2,%3}, [%4];"
        : "=r"(r[0]), "=r"(r[1]), "=r"(r[2]), "=r"(r[3]) : "r"(addr));
}

// ---------------- fp32 -> bf16 convert ----------------
__global__ void cvt_bf(const float* __restrict__ src, bf16* __restrict__ dst, int n2)
{
    int i = blockIdx.x * 256 + threadIdx.x;
    if (i < n2) {
        float2 v = *(const float2*)(src + 2 * i);
        *(unsigned*)(dst + 2 * i) = pk(v.x, v.y);
    }
}

// ---------------- LayerNorm -> bf16 ----------------
__global__ void ln_kernel(const float* __restrict__ x, const float* __restrict__ w,
                          const float* __restrict__ b, bf16* __restrict__ y)
{
    int row = blockIdx.x;
    int tid = threadIdx.x;
    const float* xr = x + (long long)row * DMODEL;
    float4 v = *(const float4*)(xr + tid * 4);
    float s  = v.x + v.y + v.z + v.w;
    float s2 = v.x*v.x + v.y*v.y + v.z*v.z + v.w*v.w;
    __shared__ float r1[128], r2[128];
    r1[tid] = s; r2[tid] = s2; __syncthreads();
    for (int t = 64; t > 0; t >>= 1) {
        if (tid < t) { r1[tid] += r1[tid+t]; r2[tid] += r2[tid+t]; }
        __syncthreads();
    }
    float mean = r1[0] * (1.0f / DMODEL);
    float var  = r2[0] * (1.0f / DMODEL) - mean * mean;
    float inv  = rsqrtf(var + 1e-5f);
    float4 w4 = *(const float4*)(w + tid * 4);
    float4 b4 = *(const float4*)(b + tid * 4);
    float o0 = (v.x - mean) * inv * w4.x + b4.x;
    float o1 = (v.y - mean) * inv * w4.y + b4.y;
    float o2 = (v.z - mean) * inv * w4.z + b4.z;
    float o3 = (v.w - mean) * inv * w4.w + b4.w;
    uint2 u; u.x = pk(o0, o1); u.y = pk(o2, o3);
    *(uint2*)(y + (long long)row * DMODEL + tid * 4) = u;
}

// ---------------- group mean over 32 consecutive tokens ----------------
__global__ void group_mean(const bf16* __restrict__ xn, bf16* __restrict__ xnl)
{
    int g = blockIdx.x;
    int tid = threadIdx.x;
    const bf162* p = (const bf162*)(xn + (long long)g * LGRP * DMODEL) + tid * 2;
    float2 s0 = make_float2(0.f, 0.f), s1 = make_float2(0.f, 0.f);
#pragma unroll
    for (int i = 0; i < LGRP; ++i) {
        float2 a = __bfloat1622float2(p[(long long)i * (DMODEL/2)]);
        float2 b = __bfloat1622float2(p[(long long)i * (DMODEL/2) + 1]);
        s0.x += a.x; s0.y += a.y; s1.x += b.x; s1.y += b.y;
    }
    const float inv = 1.f / LGRP;
    uint2 u; u.x = pk(s0.x * inv, s0.y * inv); u.y = pk(s1.x * inv, s1.y * inv);
    *(uint2*)(xnl + (long long)g * DMODEL + tid * 4) = u;
}

// ---------------- bf16 tensor-core GEMM (m16n8k16), TB layout, 3-stage, BK=64,
//                  ldmatrix fragments ----
// MODE 0: C = acc + bias + resid (fp32 out)
// MODE 1: qkv split -> Qb,Kb,Vb bf16 head-major (Q x0.125)
// MODE 3: ql/kl split (N=1024) -> Qf,Kf fp32 AND Qb,Kb bf16 head-major (Q x0.125)
template<int BM, int BN, int WARPS_M, int WARPS_N, int MODE>
__global__ void __launch_bounds__(32*WARPS_M*WARPS_N) gemm_bf(
    const bf16* __restrict__ A, const bf16* __restrict__ B, float* __restrict__ C,
    int M, int N, int K,
    const float* __restrict__ bias, const float* __restrict__ resid,
    float* __restrict__ Qf, float* __restrict__ Kf,
    bf16* __restrict__ Qb, bf16* __restrict__ Kb, bf16* __restrict__ Vb)
{
    constexpr int BK  = 64;
    constexpr int NTH = 32 * WARPS_M * WARPS_N;
    constexpr int WM  = BM / WARPS_M;
    constexpr int WN  = BN / WARPS_N;
    constexpr int MT  = WM / 16;
    constexpr int NT  = WN / 8;
    constexpr int RS  = BK + 8;           // 72 bf16 row stride
    constexpr int SA  = BM * RS;
    constexpr int SB  = BN * RS;
    constexpr int CPR = BK / 8;
    constexpr int AC  = BM * CPR / NTH;
    constexpr int BC  = BN * CPR / NTH;

    extern __shared__ __align__(16) bf16 sm[];
    const unsigned smu = smem_u32(sm);

    const int tid  = threadIdx.x;
    const int w    = tid >> 5, lane = tid & 31;
    const int g    = lane >> 2, t = lane & 3;
    const int msel = lane >> 3, mrow = lane & 7;
    const int wm   = (w / WARPS_N) * WM;
    const int wn   = (w % WARPS_N) * WN;
    const int m0   = blockIdx.y * BM;
    const int n0   = blockIdx.x * BN;

    float acc[MT][NT][4];
#pragma unroll
    for (int i = 0; i < MT; i++)
#pragma unroll
        for (int j = 0; j < NT; j++)
#pragma unroll
            for (int r = 0; r < 4; r++) acc[i][j][r] = 0.f;

    auto load_stage = [&](int st, int k0) {
        bf16* as = sm + st * (SA + SB);
        bf16* bs = as + SA;
#pragma unroll
        for (int it = 0; it < AC; ++it) {
            int idx = it * NTH + tid;
            int r = idx / CPR, ch = (idx % CPR) << 3;
            cpa16(as + r * RS + ch, A + (long long)(m0 + r) * K + k0 + ch);
        }
#pragma unroll
        for (int it = 0; it < BC; ++it) {
            int idx = it * NTH + tid;
            int r = idx / CPR, ch = (idx % CPR) << 3;
            cpa16(bs + r * RS + ch, B + (long long)(n0 + r) * K + k0 + ch);
        }
    };

    const int nk = K / BK;
    load_stage(0, 0);
    CP_COMMIT();
    if (nk > 1) { load_stage(1, BK); CP_COMMIT(); }

    for (int kt = 0; kt < nk; ++kt) {
        if (kt + 2 < nk) {
            CP_WAIT1();
            __syncthreads();
            load_stage((kt + 2) % 3, (kt + 2) * BK);
            CP_COMMIT();
        } else if (kt + 1 < nk) {
            CP_WAIT1();
            __syncthreads();
        } else {
            CP_WAIT0();
            __syncthreads();
        }
        const unsigned asu = smu + (unsigned)((kt % 3) * (SA + SB)) * 2u;
        const unsigned bsu = asu + (unsigned)SA * 2u;
#pragma unroll
        for (int ks = 0; ks < 4; ++ks) {
            const int kb = ks * 16;
            unsigned af[MT][4], bfr[NT][2];
#pragma unroll
            for (int i = 0; i < MT; i++) {
                int mb = wm + i * 16;
                unsigned addr = asu + (unsigned)(((mb + ((msel & 1) << 3) + mrow) * RS)
                                + kb + ((msel >> 1) << 3)) * 2u;
                ldm_x4(af[i], addr);
            }
#pragma unroll
            for (int jp = 0; jp < NT / 2; ++jp) {
                unsigned q[4];
                unsigned addr = bsu + (unsigned)(((wn + ((jp * 2 + (msel >> 1)) << 3) + mrow) * RS)
                                + kb + ((msel & 1) << 3)) * 2u;
                ldm_x4(q, addr);
                bfr[2*jp][0]   = q[0]; bfr[2*jp][1]   = q[1];
                bfr[2*jp+1][0] = q[2]; bfr[2*jp+1][1] = q[3];
            }
#pragma unroll
            for (int i = 0; i < MT; i++)
#pragma unroll
                for (int j = 0; j < NT; j++)
                    mma_bf(acc[i][j], af[i], bfr[j]);
        }
    }

    // epilogue
#pragma unroll
    for (int i = 0; i < MT; i++) {
        int gm = m0 + wm + i * 16 + g;
#pragma unroll
        for (int j = 0; j < NT; j++) {
            int gn = n0 + wn + j * 8 + 2 * t;
            float v00 = acc[i][j][0], v01 = acc[i][j][1];
            float v10 = acc[i][j][2], v11 = acc[i][j][3];
            if (MODE == 1) {
                int which = gn >> 9;
                int h = (gn >> 6) & 7;
                int c = gn & 63;
                float sc = (which == 0) ? 0.125f : 1.f;
                bf16* tgt = (which == 0) ? Qb : ((which == 1) ? Kb : Vb);
                int b0i = gm >> 13, i0i = gm & (SEQ - 1);
                int b1i = (gm + 8) >> 13, i1i = (gm + 8) & (SEQ - 1);
                long long d0 = (((long long)(b0i * HEADS + h)) * SEQ + i0i) * DH + c;
                long long d1 = (((long long)(b1i * HEADS + h)) * SEQ + i1i) * DH + c;
                *(unsigned*)(tgt + d0) = pk(v00 * sc, v01 * sc);
                *(unsigned*)(tgt + d1) = pk(v10 * sc, v11 * sc);
            } else if (MODE == 3) {
                int which = gn >> 9;
                int h = (gn >> 6) & 7;
                int c = gn & 63;
                float sc = (which == 0) ? 0.125f : 1.f;
                float* tf = (which == 0) ? Qf : Kf;
                bf16*  tb = (which == 0) ? Qb : Kb;
                int b0i = gm >> 8, m0i = gm & 255;
                int b1i = (gm + 8) >> 8, m1i = (gm + 8) & 255;
                long long d0 = (((long long)(b0i * HEADS + h)) * LM + m0i) * DH + c;
                long long d1 = (((long long)(b1i * HEADS + h)) * LM + m1i) * DH + c;
                *(float2*)(tf + d0) = make_float2(v00 * sc, v01 * sc);
                *(float2*)(tf + d1) = make_float2(v10 * sc, v11 * sc);
                *(unsigned*)(tb + d0) = pk(v00 * sc, v01 * sc);
                *(unsigned*)(tb + d1) = pk(v10 * sc, v11 * sc);
            } else {
                if (bias) {
                    v00 += bias[gn]; v01 += bias[gn + 1];
                    v10 += bias[gn]; v11 += bias[gn + 1];
                }
                if (resid) {
                    v00 += resid[(long long)gm * N + gn];
                    v01 += resid[(long long)gm * N + gn + 1];
                    v10 += resid[(long long)(gm + 8) * N + gn];
                    v11 += resid[(long long)(gm + 8) * N + gn + 1];
                }
                *(float2*)(C + (long long)gm * N + gn)       = make_float2(v00, v01);
                *(float2*)(C + (long long)(gm + 8) * N + gn) = make_float2(v10, v11);
            }
        }
    }
}

// ---------------- tf32 tensor-core GEMM (pinv chain + attn2 + ZAV) ----------
// MODE 0: C = alpha*A@op(B) + betaI*I
// MODE 2: C = alpha*A@op(B); C2 = beta2*I - C
// MODE 4: bf16 out via Qp pointer (no C)
template<int BM, int BN, int WARPS_M, int WARPS_N, bool TB, int MODE>
__global__ void __launch_bounds__(32*WARPS_M*WARPS_N) gemm_tc(
    const float* __restrict__ A, const float* __restrict__ B, float* __restrict__ C,
    int M, int N, int K, long long sA, long long sB, long long sC,
    float alpha, float betaI, float* __restrict__ C2, float beta2,
    float* __restrict__ Qp)
{
    constexpr int BK  = 16;
    constexpr int NTH = 32 * WARPS_M * WARPS_N;
    constexpr int WM  = BM / WARPS_M;
    constexpr int WN  = BN / WARPS_N;
    constexpr int MT  = WM / 16;
    constexpr int NT  = WN / 8;
    constexpr int SA  = BM * 20;
    constexpr int SB  = TB ? BN * 20 : BK * (BN + 8);
    constexpr int AC  = BM * 4 / NTH;
    constexpr int BC  = TB ? BN * 4 / NTH : (BK * BN / 4) / NTH;

    const int z = blockIdx.z;
    A += z * sA; B += z * sB;
    if (C)  C  += z * sC;
    if (C2) C2 += z * sC;

    __shared__ float smem[3 * (SA + SB)];

    const int tid  = threadIdx.x;
    const int w    = tid >> 5, lane = tid & 31;
    const int g    = lane >> 2, t = lane & 3;
    const int wm   = (w / WARPS_N) * WM;
    const int wn   = (w % WARPS_N) * WN;
    const int m0   = blockIdx.y * BM;
    const int n0   = blockIdx.x * BN;

    float acc[MT][NT][4];
#pragma unroll
    for (int i = 0; i < MT; i++)
#pragma unroll
        for (int j = 0; j < NT; j++)
#pragma unroll
            for (int r = 0; r < 4; r++) acc[i][j][r] = 0.f;

    auto load_stage = [&](int st, int k0) {
        float* as = smem + st * (SA + SB);
        float* bs = as + SA;
#pragma unroll
        for (int it = 0; it < AC; ++it) {
            int idx = it * NTH + tid;
            int r = idx >> 2, ch = (idx & 3) << 2;
            cpa16(as + r * 20 + ch, A + (long long)(m0 + r) * K + k0 + ch);
        }
        if (TB) {
#pragma unroll
            for (int it = 0; it < BC; ++it) {
                int idx = it * NTH + tid;
                int r = idx >> 2, ch = (idx & 3) << 2;
                cpa16(bs + r * 20 + ch, B + (long long)(n0 + r) * K + k0 + ch);
            }
        } else {
#pragma unroll
            for (int it = 0; it < BC; ++it) {
                int idx = it * NTH + tid;
                int kr = idx / (BN / 4), c = (idx % (BN / 4)) << 2;
                cpa16(bs + kr * (BN + 8) + c, B + (long long)(k0 + kr) * N + n0 + c);
            }
        }
    };

    const int nk = K / BK;
    load_stage(0, 0);
    CP_COMMIT();
    if (nk > 1) { load_stage(1, BK); CP_COMMIT(); }

    for (int kt = 0; kt < nk; ++kt) {
        if (kt + 2 < nk) {
            CP_WAIT1();
            __syncthreads();
            load_stage((kt + 2) % 3, (kt + 2) * BK);
            CP_COMMIT();
        } else if (kt + 1 < nk) {
            CP_WAIT1();
            __syncthreads();
        } else {
            CP_WAIT0();
            __syncthreads();
        }
        const float* as = smem + (kt % 3) * (SA + SB);
        const float* bs = as + SA;
#pragma unroll
        for (int ks = 0; ks < 2; ++ks) {
            const int kb = ks * 8;
            unsigned af[MT][4], bfr[NT][2];
#pragma unroll
            for (int i = 0; i < MT; i++) {
                int mb = wm + i * 16;
                af[i][0] = fu(as[(mb + g) * 20 + kb + t]);
                af[i][1] = fu(as[(mb + 8 + g) * 20 + kb + t]);
                af[i][2] = fu(as[(mb + g) * 20 + kb + t + 4]);
                af[i][3] = fu(as[(mb + 8 + g) * 20 + kb + t + 4]);
            }
#pragma unroll
            for (int j = 0; j < NT; j++) {
                int nb = wn + j * 8 + g;
                if (TB) {
                    bfr[j][0] = fu(bs[nb * 20 + kb + t]);
                    bfr[j][1] = fu(bs[nb * 20 + kb + t + 4]);
                } else {
                    bfr[j][0] = fu(bs[(kb + t) * (BN + 8) + nb]);
                    bfr[j][1] = fu(bs[(kb + t + 4) * (BN + 8) + nb]);
                }
            }
#pragma unroll
            for (int i = 0; i < MT; i++)
#pragma unroll
                for (int j = 0; j < NT; j++)
                    mma_tf32(acc[i][j], af[i], bfr[j]);
        }
    }

#pragma unroll
    for (int i = 0; i < MT; i++) {
        int gm = m0 + wm + i * 16 + g;
#pragma unroll
        for (int j = 0; j < NT; j++) {
            int gn = n0 + wn + j * 8 + 2 * t;
            float v00 = alpha * acc[i][j][0];
            float v01 = alpha * acc[i][j][1];
            float v10 = alpha * acc[i][j][2];
            float v11 = alpha * acc[i][j][3];
            if (MODE == 4) {
                bf16* Cb = (bf16*)Qp + (long long)z * sC;
                *(unsigned*)(Cb + (long long)gm * N + gn)       = pk(v00, v01);
                *(unsigned*)(Cb + (long long)(gm + 8) * N + gn) = pk(v10, v11);
            } else {
                if (betaI != 0.f) {
                    if (gm == gn)         v00 += betaI;
                    if (gm == gn + 1)     v01 += betaI;
                    if (gm + 8 == gn)     v10 += betaI;
                    if (gm + 8 == gn + 1) v11 += betaI;
                }
                *(float2*)(C + (long long)gm * N + gn)       = make_float2(v00, v01);
                *(float2*)(C + (long long)(gm + 8) * N + gn) = make_float2(v10, v11);
                if (MODE == 2) {
                    float w00 = ((gm == gn)         ? beta2 : 0.f) - v00;
                    float w01 = ((gm == gn + 1)     ? beta2 : 0.f) - v01;
                    float w10 = ((gm + 8 == gn)     ? beta2 : 0.f) - v10;
                    float w11 = ((gm + 8 == gn + 1) ? beta2 : 0.f) - v11;
                    *(float2*)(C2 + (long long)gm * N + gn)       = make_float2(w00, w01);
                    *(float2*)(C2 + (long long)(gm + 8) * N + gn) = make_float2(w10, w11);
                }
            }
        }
    }
}

// ---------------- fused softmax(A@B^T)@C in bf16, ldmatrix fragments --------
// FINAL: + depthwise conv residual over Vg, writes TOK (bf16) token-major.
#define SAV_SMEM_BYTES (5*64*72*2)
template<bool FINAL>
__global__ void __launch_bounds__(256) fused_sav(
    const bf16* __restrict__ A, const bf16* __restrict__ B, const bf16* __restrict__ C,
    float* __restrict__ OUT, float* __restrict__ PMAX, float* __restrict__ PSUM,
    int M_total, int N_total, int chunk_len,
    const bf16* __restrict__ Vg, const float* __restrict__ cw, bf16* __restrict__ TOK)
{
    extern __shared__ __align__(16) char sb[];
    bf16* Qs = (bf16*)sb;
    bf16* Ks = Qs + 64*72;
    bf16* Vs = Ks + 2*64*72;
    float* macc = (float*)sb;
    float* wmax = (float*)(sb + 16384);
    float* wsum = (float*)(sb + 16896);
    bf16*  VW   = (bf16*)(sb + 17408);
    float* wsm  = (float*)(sb + 17408 + 12288);
    const unsigned sbu = smem_u32(sb);

    const int bh = blockIdx.z, mt = blockIdx.x, ck = blockIdx.y;
    const int m0 = mt * 64;
    const int tid = threadIdx.x;
    const int w = tid >> 5, lane = tid & 31;
    const int g = lane >> 2, t = lane & 3;
    const int msel = lane >> 3, mrow = lane & 7;
    const int wm = (w >> 1) * 16;
    const int wni = w & 1;
    const int wn = wni * 32;

    const bf16* Ap = A + ((long long)bh * M_total + m0) * DH;
    const bf16* Bb = B + (long long)bh * N_total * DH;
    const bf16* Cb = C + (long long)bh * N_total * DH;

#pragma unroll
    for (int it = 0; it < 2; ++it) {
        int idx = it * 256 + tid;
        int r = idx >> 3, c = (idx & 7) << 3;
        *(uint4*)(Qs + r * 72 + c) = *(const uint4*)(Ap + r * DH + c);
    }

    const int n_start = ck * chunk_len;

    auto load_kv = [&](int st, int nb) {
        const bf16* Kp = Bb + (long long)(n_start + nb) * DH;
        const bf16* Vp = Cb + (long long)(n_start + nb) * DH;
        bf16* ks = Ks + st * 64 * 72;
        bf16* vs = Vs + st * 64 * 72;
#pragma unroll
        for (int it = 0; it < 2; ++it) {
            int idx = it * 256 + tid;
            int r = idx >> 3, c = (idx & 7) << 3;
            cpa16(ks + r * 72 + c, Kp + r * DH + c);
            cpa16(vs + r * 72 + c, Vp + r * DH + c);
        }
    };

    float acc2[8][4];
#pragma unroll
    for (int nt = 0; nt < 8; ++nt)
#pragma unroll
        for (int r = 0; r < 4; ++r) acc2[nt][r] = 0.f;
    float rmax0 = -1e30f, rmax1 = -1e30f, rsum0 = 0.f, rsum1 = 0.f;

    load_kv(0, 0);
    CP_COMMIT();

    const int nt_iters = chunk_len / 64;
    for (int itn = 0; itn < nt_iters; ++itn) {
        if (itn + 1 < nt_iters) {
            load_kv((itn + 1) & 1, (itn + 1) * 64);
            CP_COMMIT();
            CP_WAIT1();
        } else {
            CP_WAIT0();
        }
        __syncthreads();
        const unsigned ksu = sbu + (unsigned)((1 + (itn & 1)) * 64 * 72) * 2u;
        const unsigned vsu = sbu + (unsigned)((3 + (itn & 1)) * 64 * 72) * 2u;

        // S = Q @ K^T  (warp tile 16 x 32)
        float sacc[4][4];
#pragma unroll
        for (int j = 0; j < 4; ++j)
#pragma unroll
            for (int r = 0; r < 4; ++r) sacc[j][r] = 0.f;
#pragma unroll
        for (int kk0 = 0; kk0 < 4; ++kk0) {
            int kb = kk0 * 16;
            unsigned af[4];
            unsigned qaddr = sbu + (unsigned)(((wm + ((msel & 1) << 3) + mrow) * 72)
                              + kb + ((msel >> 1) << 3)) * 2u;
            ldm_x4(af, qaddr);
#pragma unroll
            for (int jp = 0; jp < 2; ++jp) {
                unsigned q[4];
                unsigned kaddr = ksu + (unsigned)(((wn + ((jp * 2 + (msel >> 1)) << 3) + mrow) * 72)
                                  + kb + ((msel & 1) << 3)) * 2u;
                ldm_x4(q, kaddr);
                mma_bf(sacc[2*jp],   af, q);
                mma_bf(sacc[2*jp+1], af, q + 2);
            }
        }
        // online softmax
        float tm0 = -1e30f, tm1 = -1e30f;
#pragma unroll
        for (int j = 0; j < 4; ++j) {
            tm0 = fmaxf(tm0, fmaxf(sacc[j][0], sacc[j][1]));
            tm1 = fmaxf(tm1, fmaxf(sacc[j][2], sacc[j][3]));
        }
        tm0 = fmaxf(tm0, __shfl_xor_sync(0xffffffffu, tm0, 1));
        tm0 = fmaxf(tm0, __shfl_xor_sync(0xffffffffu, tm0, 2));
        tm1 = fmaxf(tm1, __shfl_xor_sync(0xffffffffu, tm1, 1));
        tm1 = fmaxf(tm1, __shfl_xor_sync(0xffffffffu, tm1, 2));
        float nm0 = fmaxf(rmax0, tm0), nm1 = fmaxf(rmax1, tm1);
        float sc0 = __expf(rmax0 - nm0), sc1 = __expf(rmax1 - nm1);
        float ts0 = 0.f, ts1 = 0.f;
#pragma unroll
        for (int j = 0; j < 4; ++j) {
            sacc[j][0] = __expf(sacc[j][0] - nm0);
            sacc[j][1] = __expf(sacc[j][1] - nm0);
            sacc[j][2] = __expf(sacc[j][2] - nm1);
            sacc[j][3] = __expf(sacc[j][3] - nm1);
            ts0 += sacc[j][0] + sacc[j][1];
            ts1 += sacc[j][2] + sacc[j][3];
        }
        ts0 += __shfl_xor_sync(0xffffffffu, ts0, 1);
        ts0 += __shfl_xor_sync(0xffffffffu, ts0, 2);
        ts1 += __shfl_xor_sync(0xffffffffu, ts1, 1);
        ts1 += __shfl_xor_sync(0xffffffffu, ts1, 2);
        rsum0 = rsum0 * sc0 + ts0;
        rsum1 = rsum1 * sc1 + ts1;
        rmax0 = nm0; rmax1 = nm1;
#pragma unroll
        for (int nt = 0; nt < 8; ++nt) {
            acc2[nt][0] *= sc0; acc2[nt][1] *= sc0;
            acc2[nt][2] *= sc1; acc2[nt][3] *= sc1;
        }
        // acc2 += P @ V : V fragments via ldmatrix.trans
#pragma unroll
        for (int kc = 0; kc < 2; ++kc) {
            int kb2 = wn + kc * 16;
            unsigned af2[4];
            af2[0] = pk(sacc[kc*2][0], sacc[kc*2][1]);
            af2[1] = pk(sacc[kc*2][2], sacc[kc*2][3]);
            af2[2] = pk(sacc[kc*2+1][0], sacc[kc*2+1][1]);
            af2[3] = pk(sacc[kc*2+1][2], sacc[kc*2+1][3]);
#pragma unroll
            for (int np = 0; np < 4; ++np) {
                unsigned q[4];
                unsigned vaddr = vsu + (unsigned)(((kb2 + ((msel & 1) << 3) + mrow) * 72)
                                  + np * 16 + ((msel >> 1) << 3)) * 2u;
                ldm_x4_t(q, vaddr);
                mma_bf(acc2[2*np],   af2, q);
                mma_bf(acc2[2*np+1], af2, q + 2);
            }
        }
        __syncthreads();
    }

    if (t == 0) {
        wmax[wni*64 + wm + g]     = rmax0;
        wmax[wni*64 + wm + 8 + g] = rmax1;
        wsum[wni*64 + wm + g]     = rsum0;
        wsum[wni*64 + wm + 8 + g] = rsum1;
    }
    __syncthreads();
    int other = wni ^ 1;
    float om0 = wmax[other*64 + wm + g],     os0 = wsum[other*64 + wm + g];
    float om1 = wmax[other*64 + wm + 8 + g], os1 = wsum[other*64 + wm + 8 + g];
    float gm0 = fmaxf(rmax0, om0), gm1 = fmaxf(rmax1, om1);
    float f0 = __expf(rmax0 - gm0), f1 = __expf(rmax1 - gm1);
    float gs0 = rsum0 * f0 + os0 * __expf(om0 - gm0);
    float gs1 = rsum1 * f1 + os1 * __expf(om1 - gm1);
#pragma unroll
    for (int nt = 0; nt < 8; ++nt) {
        acc2[nt][0] *= f0; acc2[nt][1] *= f0;
        acc2[nt][2] *= f1; acc2[nt][3] *= f1;
    }
    __syncthreads();
    if (wni == 1) {
#pragma unroll
        for (int nt = 0; nt < 8; ++nt) {
            *(float2*)&macc[(wm + g)*64 + nt*8 + 2*t]     = make_float2(acc2[nt][0], acc2[nt][1]);
            *(float2*)&macc[(wm + 8 + g)*64 + nt*8 + 2*t] = make_float2(acc2[nt][2], acc2[nt][3]);
        }
    }
    __syncthreads();
    if (FINAL) {
        if (wni == 0) {
            float inv0 = 1.f / gs0, inv1 = 1.f / gs1;
#pragma unroll
            for (int nt = 0; nt < 8; ++nt) {
                int cc = nt*8 + 2*t;
                float2 m0v = *(float2*)&macc[(wm + g)*64 + cc];
                float2 m1v = *(float2*)&macc[(wm + 8 + g)*64 + cc];
                *(float2*)&macc[(wm + g)*64 + cc] =
                    make_float2((acc2[nt][0] + m0v.x) * inv0, (acc2[nt][1] + m0v.y) * inv0);
                *(float2*)&macc[(wm + 8 + g)*64 + cc] =
                    make_float2((acc2[nt][2] + m1v.x) * inv1, (acc2[nt][3] + m1v.y) * inv1);
            }
        }
        __syncthreads();
        const int h = bh & 7, b = bh >> 3;
        if (tid < KSZ) wsm[tid] = cw[h * KSZ + tid];
        const bf16* Vb2 = Vg + (long long)bh * SEQ * DH;
#pragma unroll
        for (int it = 0; it < 12; ++it) {
            int pp = it * 256 + tid;
            int rr = pp >> 5, c2 = (pp & 31) << 1;
            int gi = m0 - 16 + rr;
            unsigned val = 0;
            if (gi >= 0 && gi < SEQ) val = *(const unsigned*)(Vb2 + (long long)gi * DH + c2);
            *(unsigned*)(VW + rr * 64 + c2) = val;
        }
        __syncthreads();
        int c = tid & 63, ib = tid >> 6;
#pragma unroll 4
        for (int j = 0; j < 16; ++j) {
            int il = ib * 16 + j;
            float accv = macc[il * 64 + c];
#pragma unroll
            for (int tt = 0; tt < KSZ; ++tt)
                accv += wsm[tt] * __bfloat162float(VW[(il + tt) * 64 + c]);
            long long tok = (long long)b * SEQ + m0 + il;
            TOK[tok * DMODEL + h * DH + c] = __float2bfloat16(accv);
        }
    } else {
        if (wni == 0) {
            int row0 = m0 + wm + g, row1 = row0 + 8;
            long long pb = ((long long)bh * NCHUNK + ck) * M_total;
            float* O = OUT + pb * DH;
#pragma unroll
            for (int nt = 0; nt < 8; ++nt) {
                int cc = nt*8 + 2*t;
                float2 m0v = *(float2*)&macc[(wm + g)*64 + cc];
                float2 m1v = *(float2*)&macc[(wm + 8 + g)*64 + cc];
                *(float2*)(O + (long long)row0 * DH + cc) =
                    make_float2(acc2[nt][0] + m0v.x, acc2[nt][1] + m0v.y);
                *(float2*)(O + (long long)row1 * DH + cc) =
                    make_float2(acc2[nt][2] + m1v.x, acc2[nt][3] + m1v.y);
            }
            if (t == 0) {
                PMAX[pb + row0] = gm0; PMAX[pb + row1] = gm1;
                PSUM[pb + row0] = gs0; PSUM[pb + row1] = gs1;
            }
        }
    }
}

// ---------------- combine chunk partials -> a3v ----------------
__global__ void sav_combine(const float* __restrict__ pacc, const float* __restrict__ pmax,
                            const float* __restrict__ psum, float* __restrict__ out)
{
    int idx = blockIdx.x * 256 + threadIdx.x;
    int d = idx & 63;
    int m = (idx >> 6) & (LM - 1);
    int bh = idx >> 14;
    float gmax = -1e30f;
#pragma unroll
    for (int ck = 0; ck < NCHUNK; ++ck)
        gmax = fmaxf(gmax, pmax[((long long)bh * NCHUNK + ck) * LM + m]);
    float gsum = 0.f, val = 0.f;
#pragma unroll
    for (int ck = 0; ck < NCHUNK; ++ck) {
        long long pb = ((long long)bh * NCHUNK + ck) * LM + m;
        float f = __expf(pmax[pb] - gmax);
        gsum += psum[pb] * f;
        val  += pacc[pb * DH + d] * f;
    }
    out[idx] = val / gsum;
}

// ---------------- row softmax ----------------
__global__ void softmax_rows(float* __restrict__ S)
{
    float* row = S + (long long)blockIdx.x * 256;
    int tid = threadIdx.x;
    float v = row[tid];
    __shared__ float red[256];
    red[tid] = v; __syncthreads();
    for (int t = 128; t > 0; t >>= 1) {
        if (tid < t) red[tid] = fmaxf(red[tid], red[tid + t]);
        __syncthreads();
    }
    float mx = red[0]; __syncthreads();
    v = __expf(v - mx);
    red[tid] = v; __syncthreads();
    for (int t = 128; t > 0; t >>= 1) {
        if (tid < t) red[tid] += red[tid + t];
        __syncthreads();
    }
    row[tid] = v / red[0];
}

// ---------------- pinv scale ----------------
__global__ void colrow_max(const float* __restrict__ A2, float* __restrict__ s)
{
    int bh = blockIdx.x, j = threadIdx.x;
    const float* X = A2 + (long long)bh * LM * LM;
    float cs = 0.f, rs = 0.f;
    for (int i = 0; i < LM; ++i) {
        cs += fabsf(X[i * LM + j]);
        rs += fabsf(X[j * LM + i]);
    }
    __shared__ float r1[256], r2[256];
    r1[j] = cs; r2[j] = rs; __syncthreads();
    for (int t = 128; t > 0; t >>= 1) {
        if (j < t) { r1[j] = fmaxf(r1[j], r1[j+t]); r2[j] = fmaxf(r2[j], r2[j+t]); }
        __syncthreads();
    }
    if (j == 0) { s[bh] = r1[0]; s[32 + bh] = r2[0]; }
}

__global__ void make_z0(const float* __restrict__ A2, const float* __restrict__ s,
                        float* __restrict__ Z)
{
    __shared__ float red[64];
    int tid = threadIdx.x;
    if (tid < 64) red[tid] = s[tid];
    __syncthreads();
    float cm = red[0], rm = red[32];
#pragma unroll
    for (int i = 1; i < 32; ++i) { cm = fmaxf(cm, red[i]); rm = fmaxf(rm, red[32 + i]); }
    float inv = 1.f / (cm * rm);
    long long idx = (long long)blockIdx.x * 256 + tid;
    int c  = idx & 255;
    int r  = (int)((idx >> 8) & 255);
    int bh = (int)(idx >> 16);
    Z[idx] = A2[(long long)bh * LM * LM + (long long)c * LM + r] * inv;
}

// ---------------- host driver ----------------
extern "C" void kernel_launch(void* const* d_in, const int* in_sizes, int n_in,
                              void* d_out, int out_size)
{
    const float* x      = (const float*)d_in[0];
    const float* ln_w   = (const float*)d_in[1];
    const float* ln_b   = (const float*)d_in[2];
    const float* w_qkv  = (const float*)d_in[3];
    const float* w_out  = (const float*)d_in[4];
    const float* b_out  = (const float*)d_in[5];
    const float* conv_w = (const float*)d_in[6];
    float* out = (float*)d_out;

    static cudaStream_t s1 = nullptr;
    static cudaEvent_t evFork = nullptr, evJoin = nullptr;
    if (s1 == nullptr) {
        cudaStreamCreateWithFlags(&s1, cudaStreamNonBlocking);
        cudaEventCreateWithFlags(&evFork, cudaEventDisableTiming);
        cudaEventCreateWithFlags(&evJoin, cudaEventDisableTiming);
    }

    void *p;
    cudaGetSymbolAddress(&p, g_xnb);   bf16* XNB = (bf16*)p;
    cudaGetSymbolAddress(&p, g_xnlb);  bf16* XNLB= (bf16*)p;
    cudaGetSymbolAddress(&p, g_wqkvb); bf16* WQB = (bf16*)p;
    cudaGetSymbolAddress(&p, g_woutb); bf16* WOB = (bf16*)p;
    cudaGetSymbolAddress(&p, g_qb);    bf16* Qb  = (bf16*)p;
    cudaGetSymbolAddress(&p, g_kb);    bf16* Kb  = (bf16*)p;
    cudaGetSymbolAddress(&p, g_vb);    bf16* Vb  = (bf16*)p;
    cudaGetSymbolAddress(&p, g_ql);    float* QL = (float*)p;
    cudaGetSymbolAddress(&p, g_kl);    float* KL = (float*)p;
    cudaGetSymbolAddress(&p, g_qlb);   bf16* QLb = (bf16*)p;
    cudaGetSymbolAddress(&p, g_klb);   bf16* KLb = (bf16*)p;
    cudaGetSymbolAddress(&p, g_attn2); float* A2 = (float*)p;
    cudaGetSymbolAddress(&p, g_za);    float* ZA = (float*)p;
    cudaGetSymbolAddress(&p, g_zb);    float* ZB = (float*)p;
    cudaGetSymbolAddress(&p, g_xz);    float* XZ = (float*)p;
    cudaGetSymbolAddress(&p, g_t1);    float* T1 = (float*)p;
    cudaGetSymbolAddress(&p, g_t2);    float* T2 = (float*)p;
    cudaGetSymbolAddress(&p, g_a3v);   float* A3V= (float*)p;
    cudaGetSymbolAddress(&p, g_zavb);  bf16* ZAVb= (bf16*)p;
    cudaGetSymbolAddress(&p, g_tokb);  bf16* TOKb= (bf16*)p;
    cudaGetSymbolAddress(&p, g_pacc);  float* PAC= (float*)p;
    cudaGetSymbolAddress(&p, g_pmax);  float* PMX= (float*)p;
    cudaGetSymbolAddress(&p, g_psum);  float* PSM= (float*)p;
    cudaGetSymbolAddress(&p, g_scale); float* S  = (float*)p;

    const long long sL  = (long long)LM * DH;
    const long long sA2 = (long long)LM * LM;

    const int bf_smem = 3 * (128*72 + 128*72) * 2;   // 110592
    cudaFuncSetAttribute(gemm_bf<128,128,2,2,0>, cudaFuncAttributeMaxDynamicSharedMemorySize, bf_smem);
    cudaFuncSetAttribute(gemm_bf<128,128,2,2,1>, cudaFuncAttributeMaxDynamicSharedMemorySize, bf_smem);
    cudaFuncSetAttribute(gemm_bf<128,128,2,2,3>, cudaFuncAttributeMaxDynamicSharedMemorySize, bf_smem);
    cudaFuncSetAttribute(fused_sav<true>,  cudaFuncAttributeMaxDynamicSharedMemorySize, SAV_SMEM_BYTES);
    cudaFuncSetAttribute(fused_sav<false>, cudaFuncAttributeMaxDynamicSharedMemorySize, SAV_SMEM_BYTES);

    // ---- prefix (stream 0) ----
    cvt_bf<<<(3*DMODEL*DMODEL/2 + 255)/256, 256>>>(w_qkv, WQB, 3*DMODEL*DMODEL/2);
    cvt_bf<<<(DMODEL*DMODEL/2 + 255)/256, 256>>>(w_out, WOB, DMODEL*DMODEL/2);
    ln_kernel<<<NTOK, 128>>>(x, ln_w, ln_b, XNB);
    group_mean<<<NGRP, 128>>>(XNB, XNLB);
    gemm_bf<128,128,2,2,3><<<dim3(8, 8, 1), 128, bf_smem>>>(XNLB, WQB, nullptr,
        NGRP, 2*DMODEL, DMODEL, nullptr, nullptr, QL, KL, QLb, KLb, nullptr);

    // ---- fork: branch A (serial pinv chain, tf32) on s1 ----
    cudaEventRecord(evFork, 0);
    cudaStreamWaitEvent(s1, evFork, 0);
    gemm_tc<64,64,2,2,true,0><<<dim3(4, 4, BH), 128, 0, s1>>>(QL, KL, A2,
        LM, LM, DH, sL, sL, sA2, 1.f, 0.f, nullptr, 0.f, nullptr);
    softmax_rows<<<BH*LM, 256, 0, s1>>>(A2);
    colrow_max<<<BH, 256, 0, s1>>>(A2, S);
    make_z0<<<(BH*LM*LM)/256, 256, 0, s1>>>(A2, S, ZA);
    float* Zin = ZA; float* Zout = ZB;
    for (int it = 0; it < 6; ++it) {
        gemm_tc<64,64,2,2,false,2><<<dim3(4,4,BH), 128, 0, s1>>>(A2, Zin, XZ,
            LM, LM, LM, sA2, sA2, sA2, 1.f, 0.f, T1, 7.f, nullptr);
        gemm_tc<64,64,2,2,false,0><<<dim3(4,4,BH), 128, 0, s1>>>(XZ, T1, T2,
            LM, LM, LM, sA2, sA2, sA2, -1.f, 15.f, nullptr, 0.f, nullptr);
        gemm_tc<64,64,2,2,false,0><<<dim3(4,4,BH), 128, 0, s1>>>(XZ, T2, T1,
            LM, LM, LM, sA2, sA2, sA2, -1.f, 13.f, nullptr, 0.f, nullptr);
        gemm_tc<64,64,2,2,false,0><<<dim3(4,4,BH), 128, 0, s1>>>(Zin, T1, Zout,
            LM, LM, LM, sA2, sA2, sA2, 0.25f, 0.f, nullptr, 0.f, nullptr);
        float* tmp = Zin; Zin = Zout; Zout = tmp;
    }
    cudaEventRecord(evJoin, s1);

    // ---- branch B (bf16, throughput-bound) on stream 0 ----
    gemm_bf<128,128,2,2,1><<<dim3(12, 256, 1), 128, bf_smem>>>(XNB, WQB, nullptr,
        NTOK, 3*DMODEL, DMODEL, nullptr, nullptr, nullptr, nullptr, Qb, Kb, Vb);
    fused_sav<false><<<dim3(LM/64, NCHUNK, BH), 256, SAV_SMEM_BYTES>>>(QLb, Kb, Vb,
        PAC, PMX, PSM, LM, SEQ, SEQ/NCHUNK, nullptr, nullptr, nullptr);
    sav_combine<<<(BH*LM*DH)/256, 256>>>(PAC, PMX, PSM, A3V);

    // ---- join ----
    cudaStreamWaitEvent(0, evJoin, 0);
    gemm_tc<64,64,2,2,false,4><<<dim3(1, 4, BH), 128>>>(Zin, A3V, nullptr,
        LM, DH, LM, sA2, sL, sL, 1.f, 0.f, nullptr, 0.f, (float*)ZAVb);
    fused_sav<true><<<dim3(SEQ/64, 1, BH), 256, SAV_SMEM_BYTES>>>(Qb, KLb, ZAVb,
        nullptr, nullptr, nullptr, SEQ, LM, LM, Vb, conv_w, TOKb);
    gemm_bf<128,128,2,2,0><<<dim3(4, 256, 1), 128, bf_smem>>>(TOKb, WOB, out,
        NTOK, DMODEL, DMODEL, b_out, x, nullptr, nullptr, nullptr, nullptr, nullptr);
}

// round 12
// speedup vs baseline: 1.7079x; 1.1411x over previous
#include <cuda_runtime.h>
#include <cuda_bf16.h>
#include <cstdint>

// ---------------- problem constants ----------------
#define BATCH 4
#define SEQ   8192
#define DMODEL 512
#define HEADS 8
#define DH    64
#define LM    256
#define LGRP  32
#define NTOK  (BATCH*SEQ)
#define BH    (BATCH*HEADS)
#define KSZ   33
#define NCHUNK 8
#define NGRP  (NTOK/LGRP)

typedef __nv_bfloat16 bf16;
typedef __nv_bfloat162 bf162;

// ---------------- scratch ----------------
__device__ bf16  g_xnb  [(size_t)NTOK*DMODEL];
__device__ bf16  g_xnlb [(size_t)NGRP*DMODEL];
__device__ bf16  g_wqkvb[(size_t)3*DMODEL*DMODEL];
__device__ bf16  g_woutb[(size_t)DMODEL*DMODEL];
__device__ bf16  g_qb   [(size_t)BH*SEQ*DH];
__device__ bf16  g_kb   [(size_t)BH*SEQ*DH];
__device__ bf16  g_vb   [(size_t)BH*SEQ*DH];
__device__ float g_ql   [(size_t)BH*LM*DH];
__device__ float g_kl   [(size_t)BH*LM*DH];
__device__ bf16  g_qlb  [(size_t)BH*LM*DH];
__device__ bf16  g_klb  [(size_t)BH*LM*DH];
__device__ float g_attn2[(size_t)BH*LM*LM];
__device__ float g_za   [(size_t)BH*LM*LM];
__device__ float g_zb   [(size_t)BH*LM*LM];
__device__ float g_xz   [(size_t)BH*LM*LM];
__device__ float g_t1   [(size_t)BH*LM*LM];
__device__ float g_t2   [(size_t)BH*LM*LM];
__device__ float g_a3v  [(size_t)BH*LM*DH];
__device__ bf16  g_zavb [(size_t)BH*LM*DH];
__device__ bf16  g_tokb [(size_t)NTOK*DMODEL];
__device__ float g_pacc [(size_t)BH*NCHUNK*LM*DH];
__device__ float g_pmax [(size_t)BH*NCHUNK*LM];
__device__ float g_psum [(size_t)BH*NCHUNK*LM];
__device__ float g_scale[64];

// ---------------- helpers ----------------
__device__ __forceinline__ void mma_tf32(float* c, const unsigned* a, const unsigned* b) {
    asm volatile(
        "mma.sync.aligned.m16n8k8.row.col.f32.tf32.tf32.f32 "
        "{%0,%1,%2,%3},{%4,%5,%6,%7},{%8,%9},{%0,%1,%2,%3};"
        : "+f"(c[0]), "+f"(c[1]), "+f"(c[2]), "+f"(c[3])
        : "r"(a[0]), "r"(a[1]), "r"(a[2]), "r"(a[3]), "r"(b[0]), "r"(b[1]));
}
__device__ __forceinline__ void mma_bf(float* c, const unsigned* a, const unsigned* b) {
    asm volatile(
        "mma.sync.aligned.m16n8k16.row.col.f32.bf16.bf16.f32 "
        "{%0,%1,%2,%3},{%4,%5,%6,%7},{%8,%9},{%0,%1,%2,%3};"
        : "+f"(c[0]), "+f"(c[1]), "+f"(c[2]), "+f"(c[3])
        : "r"(a[0]), "r"(a[1]), "r"(a[2]), "r"(a[3]), "r"(b[0]), "r"(b[1]));
}
__device__ __forceinline__ void cpa16(void* s, const void* g) {
    unsigned sa = (unsigned)__cvta_generic_to_shared(s);
    asm volatile("cp.async.cg.shared.global [%0], [%1], 16;" :: "r"(sa), "l"(g));
}
#define CP_COMMIT() asm volatile("cp.async.commit_group;")
#define CP_WAIT1()  asm volatile("cp.async.wait_group 1;")
#define CP_WAIT0()  asm volatile("cp.async.wait_group 0;")

__device__ __forceinline__ unsigned fu(float f) { return __float_as_uint(f); }
__device__ __forceinline__ unsigned pk(float lo, float hi) {
    unsigned r;
    asm("cvt.rn.bf16x2.f32 %0, %1, %2;" : "=r"(r) : "f"(hi), "f"(lo));
    return r;
}
__device__ __forceinline__ unsigned smem_u32(const void* p) {
    return (unsigned)__cvta_generic_to_shared(p);
}
__device__ __forceinline__ void ldm_x4(unsigned* r, unsigned addr) {
    asm volatile("ldmatrix.sync.aligned.m8n8.x4.shared.b16 {%0,%1,%2,%3}, [%4];"
        : "=r"(r[0]), "=r"(r[1]), "=r"(r[2]), "=r"(r[3]) : "r"(addr));
}
__device__ __forceinline__ void ldm_x4_t(unsigned* r, unsigned addr) {
    asm volatile("ldmatrix.sync.aligned.m8n8.x4.trans.shared.b16 {%0,%1,%2,%3}, [%4];"
        : "=r"(r[0]), "=r"(r[1]), "=r"(r[2]), "=r"(r[3]) : "r"(addr));
}

// ---------------- fp32 -> bf16 convert ----------------
__global__ void cvt_bf(const float* __restrict__ src, bf16* __restrict__ dst, int n2)
{
    int i = blockIdx.x * 256 + threadIdx.x;
    if (i < n2) {
        float2 v = *(const float2*)(src + 2 * i);
        *(unsigned*)(dst + 2 * i) = pk(v.x, v.y);
    }
}

// ---------------- fused LayerNorm + group mean -> bf16 ----------------
// One block per landmark group (32 rows). 8 warps, warp w handles rows w, w+8, w+16, w+24.
__global__ void __launch_bounds__(256) ln_group(
    const float* __restrict__ x, const float* __restrict__ wln,
    const float* __restrict__ bln, bf16* __restrict__ y, bf16* __restrict__ xnl)
{
    __shared__ float gsm[8][DMODEL];
    const int grp = blockIdx.x;
    const int tid = threadIdx.x;
    const int w = tid >> 5, lane = tid & 31;

    float w4[4][4], b4[4][4];
#pragma unroll
    for (int kk = 0; kk < 4; ++kk) {
        *(float4*)w4[kk] = *(const float4*)(wln + kk * 128 + lane * 4);
        *(float4*)b4[kk] = *(const float4*)(bln + kk * 128 + lane * 4);
    }
    float gacc[4][4];
#pragma unroll
    for (int kk = 0; kk < 4; ++kk)
#pragma unroll
        for (int e = 0; e < 4; ++e) gacc[kk][e] = 0.f;

#pragma unroll
    for (int rr = 0; rr < 4; ++rr) {
        int row = grp * LGRP + w + rr * 8;
        const float* xr = x + (long long)row * DMODEL;
        float v[4][4];
        float s = 0.f, s2 = 0.f;
#pragma unroll
        for (int kk = 0; kk < 4; ++kk) {
            *(float4*)v[kk] = *(const float4*)(xr + kk * 128 + lane * 4);
#pragma unroll
            for (int e = 0; e < 4; ++e) { s += v[kk][e]; s2 += v[kk][e] * v[kk][e]; }
        }
#pragma unroll
        for (int o = 16; o > 0; o >>= 1) {
            s  += __shfl_xor_sync(0xffffffffu, s, o);
            s2 += __shfl_xor_sync(0xffffffffu, s2, o);
        }
        float mean = s * (1.f / DMODEL);
        float var  = s2 * (1.f / DMODEL) - mean * mean;
        float inv  = rsqrtf(var + 1e-5f);
        bf16* yr = y + (long long)row * DMODEL;
#pragma unroll
        for (int kk = 0; kk < 4; ++kk) {
            float o0 = (v[kk][0] - mean) * inv * w4[kk][0] + b4[kk][0];
            float o1 = (v[kk][1] - mean) * inv * w4[kk][1] + b4[kk][1];
            float o2 = (v[kk][2] - mean) * inv * w4[kk][2] + b4[kk][2];
            float o3 = (v[kk][3] - mean) * inv * w4[kk][3] + b4[kk][3];
            uint2 u; u.x = pk(o0, o1); u.y = pk(o2, o3);
            *(uint2*)(yr + kk * 128 + lane * 4) = u;
            gacc[kk][0] += o0; gacc[kk][1] += o1; gacc[kk][2] += o2; gacc[kk][3] += o3;
        }
    }
#pragma unroll
    for (int kk = 0; kk < 4; ++kk)
        *(float4*)&gsm[w][kk * 128 + lane * 4] = *(float4*)gacc[kk];
    __syncthreads();
    // reduce 8 warps, write xnl: thread handles 2 cols
    int c = tid * 2;
    float a0 = 0.f, a1 = 0.f;
#pragma unroll
    for (int ww = 0; ww < 8; ++ww) { a0 += gsm[ww][c]; a1 += gsm[ww][c + 1]; }
    *(unsigned*)(xnl + (long long)grp * DMODEL + c) = pk(a0 * (1.f / LGRP), a1 * (1.f / LGRP));
}

// ---------------- bf16 tensor-core GEMM (m16n8k16), TB layout, 3-stage, BK=64,
//                  ldmatrix fragments ----
template<int BM, int BN, int WARPS_M, int WARPS_N, int MODE>
__global__ void __launch_bounds__(32*WARPS_M*WARPS_N) gemm_bf(
    const bf16* __restrict__ A, const bf16* __restrict__ B, float* __restrict__ C,
    int M, int N, int K,
    const float* __restrict__ bias, const float* __restrict__ resid,
    float* __restrict__ Qf, float* __restrict__ Kf,
    bf16* __restrict__ Qb, bf16* __restrict__ Kb, bf16* __restrict__ Vb)
{
    constexpr int BK  = 64;
    constexpr int NTH = 32 * WARPS_M * WARPS_N;
    constexpr int WM  = BM / WARPS_M;
    constexpr int WN  = BN / WARPS_N;
    constexpr int MT  = WM / 16;
    constexpr int NT  = WN / 8;
    constexpr int RS  = BK + 8;
    constexpr int SA  = BM * RS;
    constexpr int SB  = BN * RS;
    constexpr int CPR = BK / 8;
    constexpr int AC  = BM * CPR / NTH;
    constexpr int BC  = BN * CPR / NTH;

    extern __shared__ __align__(16) bf16 sm[];
    const unsigned smu = smem_u32(sm);

    const int tid  = threadIdx.x;
    const int w    = tid >> 5, lane = tid & 31;
    const int g    = lane >> 2, t = lane & 3;
    const int msel = lane >> 3, mrow = lane & 7;
    const int wm   = (w / WARPS_N) * WM;
    const int wn   = (w % WARPS_N) * WN;
    const int m0   = blockIdx.y * BM;
    const int n0   = blockIdx.x * BN;

    float acc[MT][NT][4];
#pragma unroll
    for (int i = 0; i < MT; i++)
#pragma unroll
        for (int j = 0; j < NT; j++)
#pragma unroll
            for (int r = 0; r < 4; r++) acc[i][j][r] = 0.f;

    auto load_stage = [&](int st, int k0) {
        bf16* as = sm + st * (SA + SB);
        bf16* bs = as + SA;
#pragma unroll
        for (int it = 0; it < AC; ++it) {
            int idx = it * NTH + tid;
            int r = idx / CPR, ch = (idx % CPR) << 3;
            cpa16(as + r * RS + ch, A + (long long)(m0 + r) * K + k0 + ch);
        }
#pragma unroll
        for (int it = 0; it < BC; ++it) {
            int idx = it * NTH + tid;
            int r = idx / CPR, ch = (idx % CPR) << 3;
            cpa16(bs + r * RS + ch, B + (long long)(n0 + r) * K + k0 + ch);
        }
    };

    const int nk = K / BK;
    load_stage(0, 0);
    CP_COMMIT();
    if (nk > 1) { load_stage(1, BK); CP_COMMIT(); }

    for (int kt = 0; kt < nk; ++kt) {
        if (kt + 2 < nk) {
            CP_WAIT1();
            __syncthreads();
            load_stage((kt + 2) % 3, (kt + 2) * BK);
            CP_COMMIT();
        } else if (kt + 1 < nk) {
            CP_WAIT1();
            __syncthreads();
        } else {
            CP_WAIT0();
            __syncthreads();
        }
        const unsigned asu = smu + (unsigned)((kt % 3) * (SA + SB)) * 2u;
        const unsigned bsu = asu + (unsigned)SA * 2u;
#pragma unroll
        for (int ks = 0; ks < 4; ++ks) {
            const int kb = ks * 16;
            unsigned af[MT][4], bfr[NT][2];
#pragma unroll
            for (int i = 0; i < MT; i++) {
                int mb = wm + i * 16;
                unsigned addr = asu + (unsigned)(((mb + ((msel & 1) << 3) + mrow) * RS)
                                + kb + ((msel >> 1) << 3)) * 2u;
                ldm_x4(af[i], addr);
            }
#pragma unroll
            for (int jp = 0; jp < NT / 2; ++jp) {
                unsigned q[4];
                unsigned addr = bsu + (unsigned)(((wn + ((jp * 2 + (msel >> 1)) << 3) + mrow) * RS)
                                + kb + ((msel & 1) << 3)) * 2u;
                ldm_x4(q, addr);
                bfr[2*jp][0]   = q[0]; bfr[2*jp][1]   = q[1];
                bfr[2*jp+1][0] = q[2]; bfr[2*jp+1][1] = q[3];
            }
#pragma unroll
            for (int i = 0; i < MT; i++)
#pragma unroll
                for (int j = 0; j < NT; j++)
                    mma_bf(acc[i][j], af[i], bfr[j]);
        }
    }

    // epilogue
#pragma unroll
    for (int i = 0; i < MT; i++) {
        int gm = m0 + wm + i * 16 + g;
#pragma unroll
        for (int j = 0; j < NT; j++) {
            int gn = n0 + wn + j * 8 + 2 * t;
            float v00 = acc[i][j][0], v01 = acc[i][j][1];
            float v10 = acc[i][j][2], v11 = acc[i][j][3];
            if (MODE == 1) {
                int which = gn >> 9;
                int h = (gn >> 6) & 7;
                int c = gn & 63;
                float sc = (which == 0) ? 0.125f : 1.f;
                bf16* tgt = (which == 0) ? Qb : ((which == 1) ? Kb : Vb);
                int b0i = gm >> 13, i0i = gm & (SEQ - 1);
                int b1i = (gm + 8) >> 13, i1i = (gm + 8) & (SEQ - 1);
                long long d0 = (((long long)(b0i * HEADS + h)) * SEQ + i0i) * DH + c;
                long long d1 = (((long long)(b1i * HEADS + h)) * SEQ + i1i) * DH + c;
                *(unsigned*)(tgt + d0) = pk(v00 * sc, v01 * sc);
                *(unsigned*)(tgt + d1) = pk(v10 * sc, v11 * sc);
            } else if (MODE == 3) {
                int which = gn >> 9;
                int h = (gn >> 6) & 7;
                int c = gn & 63;
                float sc = (which == 0) ? 0.125f : 1.f;
                float* tf = (which == 0) ? Qf : Kf;
                bf16*  tb = (which == 0) ? Qb : Kb;
                int b0i = gm >> 8, m0i = gm & 255;
                int b1i = (gm + 8) >> 8, m1i = (gm + 8) & 255;
                long long d0 = (((long long)(b0i * HEADS + h)) * LM + m0i) * DH + c;
                long long d1 = (((long long)(b1i * HEADS + h)) * LM + m1i) * DH + c;
                *(float2*)(tf + d0) = make_float2(v00 * sc, v01 * sc);
                *(float2*)(tf + d1) = make_float2(v10 * sc, v11 * sc);
                *(unsigned*)(tb + d0) = pk(v00 * sc, v01 * sc);
                *(unsigned*)(tb + d1) = pk(v10 * sc, v11 * sc);
            } else {
                if (bias) {
                    v00 += bias[gn]; v01 += bias[gn + 1];
                    v10 += bias[gn]; v11 += bias[gn + 1];
                }
                if (resid) {
                    v00 += resid[(long long)gm * N + gn];
                    v01 += resid[(long long)gm * N + gn + 1];
                    v10 += resid[(long long)(gm + 8) * N + gn];
                    v11 += resid[(long long)(gm + 8) * N + gn + 1];
                }
                *(float2*)(C + (long long)gm * N + gn)       = make_float2(v00, v01);
                *(float2*)(C + (long long)(gm + 8) * N + gn) = make_float2(v10, v11);
            }
        }
    }
}

// ---------------- tf32 tensor-core GEMM (pinv chain + attn2 + ZAV) ----------
template<int BM, int BN, int WARPS_M, int WARPS_N, bool TB, int MODE>
__global__ void __launch_bounds__(32*WARPS_M*WARPS_N) gemm_tc(
    const float* __restrict__ A, const float* __restrict__ B, float* __restrict__ C,
    int M, int N, int K, long long sA, long long sB, long long sC,
    float alpha, float betaI, float* __restrict__ C2, float beta2,
    float* __restrict__ Qp)
{
    constexpr int BK  = 16;
    constexpr int NTH = 32 * WARPS_M * WARPS_N;
    constexpr int WM  = BM / WARPS_M;
    constexpr int WN  = BN / WARPS_N;
    constexpr int MT  = WM / 16;
    constexpr int NT  = WN / 8;
    constexpr int SA  = BM * 20;
    constexpr int SB  = TB ? BN * 20 : BK * (BN + 8);
    constexpr int AC  = BM * 4 / NTH;
    constexpr int BC  = TB ? BN * 4 / NTH : (BK * BN / 4) / NTH;

    const int z = blockIdx.z;
    A += z * sA; B += z * sB;
    if (C)  C  += z * sC;
    if (C2) C2 += z * sC;

    __shared__ float smem[3 * (SA + SB)];

    const int tid  = threadIdx.x;
    const int w    = tid >> 5, lane = tid & 31;
    const int g    = lane >> 2, t = lane & 3;
    const int wm   = (w / WARPS_N) * WM;
    const int wn   = (w % WARPS_N) * WN;
    const int m0   = blockIdx.y * BM;
    const int n0   = blockIdx.x * BN;

    float acc[MT][NT][4];
#pragma unroll
    for (int i = 0; i < MT; i++)
#pragma unroll
        for (int j = 0; j < NT; j++)
#pragma unroll
            for (int r = 0; r < 4; r++) acc[i][j][r] = 0.f;

    auto load_stage = [&](int st, int k0) {
        float* as = smem + st * (SA + SB);
        float* bs = as + SA;
#pragma unroll
        for (int it = 0; it < AC; ++it) {
            int idx = it * NTH + tid;
            int r = idx >> 2, ch = (idx & 3) << 2;
            cpa16(as + r * 20 + ch, A + (long long)(m0 + r) * K + k0 + ch);
        }
        if (TB) {
#pragma unroll
            for (int it = 0; it < BC; ++it) {
                int idx = it * NTH + tid;
                int r = idx >> 2, ch = (idx & 3) << 2;
                cpa16(bs + r * 20 + ch, B + (long long)(n0 + r) * K + k0 + ch);
            }
        } else {
#pragma unroll
            for (int it = 0; it < BC; ++it) {
                int idx = it * NTH + tid;
                int kr = idx / (BN / 4), c = (idx % (BN / 4)) << 2;
                cpa16(bs + kr * (BN + 8) + c, B + (long long)(k0 + kr) * N + n0 + c);
            }
        }
    };

    const int nk = K / BK;
    load_stage(0, 0);
    CP_COMMIT();
    if (nk > 1) { load_stage(1, BK); CP_COMMIT(); }

    for (int kt = 0; kt < nk; ++kt) {
        if (kt + 2 < nk) {
            CP_WAIT1();
            __syncthreads();
            load_stage((kt + 2) % 3, (kt + 2) * BK);
            CP_COMMIT();
        } else if (kt + 1 < nk) {
            CP_WAIT1();
            __syncthreads();
        } else {
            CP_WAIT0();
            __syncthreads();
        }
        const float* as = smem + (kt % 3) * (SA + SB);
        const float* bs = as + SA;
#pragma unroll
        for (int ks = 0; ks < 2; ++ks) {
            const int kb = ks * 8;
            unsigned af[MT][4], bfr[NT][2];
#pragma unroll
            for (int i = 0; i < MT; i++) {
                int mb = wm + i * 16;
                af[i][0] = fu(as[(mb + g) * 20 + kb + t]);
                af[i][1] = fu(as[(mb + 8 + g) * 20 + kb + t]);
                af[i][2] = fu(as[(mb + g) * 20 + kb + t + 4]);
                af[i][3] = fu(as[(mb + 8 + g) * 20 + kb + t + 4]);
            }
#pragma unroll
            for (int j = 0; j < NT; j++) {
                int nb = wn + j * 8 + g;
                if (TB) {
                    bfr[j][0] = fu(bs[nb * 20 + kb + t]);
                    bfr[j][1] = fu(bs[nb * 20 + kb + t + 4]);
                } else {
                    bfr[j][0] = fu(bs[(kb + t) * (BN + 8) + nb]);
                    bfr[j][1] = fu(bs[(kb + t + 4) * (BN + 8) + nb]);
                }
            }
#pragma unroll
            for (int i = 0; i < MT; i++)
#pragma unroll
                for (int j = 0; j < NT; j++)
                    mma_tf32(acc[i][j], af[i], bfr[j]);
        }
    }

#pragma unroll
    for (int i = 0; i < MT; i++) {
        int gm = m0 + wm + i * 16 + g;
#pragma unroll
        for (int j = 0; j < NT; j++) {
            int gn = n0 + wn + j * 8 + 2 * t;
            float v00 = alpha * acc[i][j][0];
            float v01 = alpha * acc[i][j][1];
            float v10 = alpha * acc[i][j][2];
            float v11 = alpha * acc[i][j][3];
            if (MODE == 4) {
                bf16* Cb = (bf16*)Qp + (long long)z * sC;
                *(unsigned*)(Cb + (long long)gm * N + gn)       = pk(v00, v01);
                *(unsigned*)(Cb + (long long)(gm + 8) * N + gn) = pk(v10, v11);
            } else {
                if (betaI != 0.f) {
                    if (gm == gn)         v00 += betaI;
                    if (gm == gn + 1)     v01 += betaI;
                    if (gm + 8 == gn)     v10 += betaI;
                    if (gm + 8 == gn + 1) v11 += betaI;
                }
                *(float2*)(C + (long long)gm * N + gn)       = make_float2(v00, v01);
                *(float2*)(C + (long long)(gm + 8) * N + gn) = make_float2(v10, v11);
                if (MODE == 2) {
                    float w00 = ((gm == gn)         ? beta2 : 0.f) - v00;
                    float w01 = ((gm == gn + 1)     ? beta2 : 0.f) - v01;
                    float w10 = ((gm + 8 == gn)     ? beta2 : 0.f) - v10;
                    float w11 = ((gm + 8 == gn + 1) ? beta2 : 0.f) - v11;
                    *(float2*)(C2 + (long long)gm * N + gn)       = make_float2(w00, w01);
                    *(float2*)(C2 + (long long)(gm + 8) * N + gn) = make_float2(w10, w11);
                }
            }
        }
    }
}

// ---------------- fused softmax(A@B^T)@C in bf16, ldmatrix fragments --------
#define SAV_SMEM_BYTES (5*64*72*2)
template<bool FINAL>
__global__ void __launch_bounds__(256) fused_sav(
    const bf16* __restrict__ A, const bf16* __restrict__ B, const bf16* __restrict__ C,
    float* __restrict__ OUT, float* __restrict__ PMAX, float* __restrict__ PSUM,
    int M_total, int N_total, int chunk_len,
    const bf16* __restrict__ Vg, const float* __restrict__ cw, bf16* __restrict__ TOK)
{
    extern __shared__ __align__(16) char sb[];
    bf16* Qs = (bf16*)sb;
    bf16* Ks = Qs + 64*72;
    bf16* Vs = Ks + 2*64*72;
    float* macc = (float*)sb;
    float* wmax = (float*)(sb + 16384);
    float* wsum = (float*)(sb + 16896);
    bf16*  VW   = (bf16*)(sb + 17408);
    float* wsm  = (float*)(sb + 17408 + 12288);
    const unsigned sbu = smem_u32(sb);

    const int bh = blockIdx.z, mt = blockIdx.x, ck = blockIdx.y;
    const int m0 = mt * 64;
    const int tid = threadIdx.x;
    const int w = tid >> 5, lane = tid & 31;
    const int g = lane >> 2, t = lane & 3;
    const int msel = lane >> 3, mrow = lane & 7;
    const int wm = (w >> 1) * 16;
    const int wni = w & 1;
    const int wn = wni * 32;

    const bf16* Ap = A + ((long long)bh * M_total + m0) * DH;
    const bf16* Bb = B + (long long)bh * N_total * DH;
    const bf16* Cb = C + (long long)bh * N_total * DH;

#pragma unroll
    for (int it = 0; it < 2; ++it) {
        int idx = it * 256 + tid;
        int r = idx >> 3, c = (idx & 7) << 3;
        *(uint4*)(Qs + r * 72 + c) = *(const uint4*)(Ap + r * DH + c);
    }

    const int n_start = ck * chunk_len;

    auto load_kv = [&](int st, int nb) {
        const bf16* Kp = Bb + (long long)(n_start + nb) * DH;
        const bf16* Vp = Cb + (long long)(n_start + nb) * DH;
        bf16* ks = Ks + st * 64 * 72;
        bf16* vs = Vs + st * 64 * 72;
#pragma unroll
        for (int it = 0; it < 2; ++it) {
            int idx = it * 256 + tid;
            int r = idx >> 3, c = (idx & 7) << 3;
            cpa16(ks + r * 72 + c, Kp + r * DH + c);
            cpa16(vs + r * 72 + c, Vp + r * DH + c);
        }
    };

    float acc2[8][4];
#pragma unroll
    for (int nt = 0; nt < 8; ++nt)
#pragma unroll
        for (int r = 0; r < 4; ++r) acc2[nt][r] = 0.f;
    float rmax0 = -1e30f, rmax1 = -1e30f, rsum0 = 0.f, rsum1 = 0.f;

    load_kv(0, 0);
    CP_COMMIT();

    const int nt_iters = chunk_len / 64;
    for (int itn = 0; itn < nt_iters; ++itn) {
        if (itn + 1 < nt_iters) {
            load_kv((itn + 1) & 1, (itn + 1) * 64);
            CP_COMMIT();
            CP_WAIT1();
        } else {
            CP_WAIT0();
        }
        __syncthreads();
        const unsigned ksu = sbu + (unsigned)((1 + (itn & 1)) * 64 * 72) * 2u;
        const unsigned vsu = sbu + (unsigned)((3 + (itn & 1)) * 64 * 72) * 2u;

        float sacc[4][4];
#pragma unroll
        for (int j = 0; j < 4; ++j)
#pragma unroll
            for (int r = 0; r < 4; ++r) sacc[j][r] = 0.f;
#pragma unroll
        for (int kk0 = 0; kk0 < 4; ++kk0) {
            int kb = kk0 * 16;
            unsigned af[4];
            unsigned qaddr = sbu + (unsigned)(((wm + ((msel & 1) << 3) + mrow) * 72)
                              + kb + ((msel >> 1) << 3)) * 2u;
            ldm_x4(af, qaddr);
#pragma unroll
            for (int jp = 0; jp < 2; ++jp) {
                unsigned q[4];
                unsigned kaddr = ksu + (unsigned)(((wn + ((jp * 2 + (msel >> 1)) << 3) + mrow) * 72)
                                  + kb + ((msel & 1) << 3)) * 2u;
                ldm_x4(q, kaddr);
                mma_bf(sacc[2*jp],   af, q);
                mma_bf(sacc[2*jp+1], af, q + 2);
            }
        }
        float tm0 = -1e30f, tm1 = -1e30f;
#pragma unroll
        for (int j = 0; j < 4; ++j) {
            tm0 = fmaxf(tm0, fmaxf(sacc[j][0], sacc[j][1]));
            tm1 = fmaxf(tm1, fmaxf(sacc[j][2], sacc[j][3]));
        }
        tm0 = fmaxf(tm0, __shfl_xor_sync(0xffffffffu, tm0, 1));
        tm0 = fmaxf(tm0, __shfl_xor_sync(0xffffffffu, tm0, 2));
        tm1 = fmaxf(tm1, __shfl_xor_sync(0xffffffffu, tm1, 1));
        tm1 = fmaxf(tm1, __shfl_xor_sync(0xffffffffu, tm1, 2));
        float nm0 = fmaxf(rmax0, tm0), nm1 = fmaxf(rmax1, tm1);
        float sc0 = __expf(rmax0 - nm0), sc1 = __expf(rmax1 - nm1);
        float ts0 = 0.f, ts1 = 0.f;
#pragma unroll
        for (int j = 0; j < 4; ++j) {
            sacc[j][0] = __expf(sacc[j][0] - nm0);
            sacc[j][1] = __expf(sacc[j][1] - nm0);
            sacc[j][2] = __expf(sacc[j][2] - nm1);
            sacc[j][3] = __expf(sacc[j][3] - nm1);
            ts0 += sacc[j][0] + sacc[j][1];
            ts1 += sacc[j][2] + sacc[j][3];
        }
        ts0 += __shfl_xor_sync(0xffffffffu, ts0, 1);
        ts0 += __shfl_xor_sync(0xffffffffu, ts0, 2);
        ts1 += __shfl_xor_sync(0xffffffffu, ts1, 1);
        ts1 += __shfl_xor_sync(0xffffffffu, ts1, 2);
        rsum0 = rsum0 * sc0 + ts0;
        rsum1 = rsum1 * sc1 + ts1;
        rmax0 = nm0; rmax1 = nm1;
#pragma unroll
        for (int nt = 0; nt < 8; ++nt) {
            acc2[nt][0] *= sc0; acc2[nt][1] *= sc0;
            acc2[nt][2] *= sc1; acc2[nt][3] *= sc1;
        }
#pragma unroll
        for (int kc = 0; kc < 2; ++kc) {
            int kb2 = wn + kc * 16;
            unsigned af2[4];
            af2[0] = pk(sacc[kc*2][0], sacc[kc*2][1]);
            af2[1] = pk(sacc[kc*2][2], sacc[kc*2][3]);
            af2[2] = pk(sacc[kc*2+1][0], sacc[kc*2+1][1]);
            af2[3] = pk(sacc[kc*2+1][2], sacc[kc*2+1][3]);
#pragma unroll
            for (int np = 0; np < 4; ++np) {
                unsigned q[4];
                unsigned vaddr = vsu + (unsigned)(((kb2 + ((msel & 1) << 3) + mrow) * 72)
                                  + np * 16 + ((msel >> 1) << 3)) * 2u;
                ldm_x4_t(q, vaddr);
                mma_bf(acc2[2*np],   af2, q);
                mma_bf(acc2[2*np+1], af2, q + 2);
            }
        }
        __syncthreads();
    }

    if (t == 0) {
        wmax[wni*64 + wm + g]     = rmax0;
        wmax[wni*64 + wm + 8 + g] = rmax1;
        wsum[wni*64 + wm + g]     = rsum0;
        wsum[wni*64 + wm + 8 + g] = rsum1;
    }
    __syncthreads();
    int other = wni ^ 1;
    float om0 = wmax[other*64 + wm + g],     os0 = wsum[other*64 + wm + g];
    float om1 = wmax[other*64 + wm + 8 + g], os1 = wsum[other*64 + wm + 8 + g];
    float gm0 = fmaxf(rmax0, om0), gm1 = fmaxf(rmax1, om1);
    float f0 = __expf(rmax0 - gm0), f1 = __expf(rmax1 - gm1);
    float gs0 = rsum0 * f0 + os0 * __expf(om0 - gm0);
    float gs1 = rsum1 * f1 + os1 * __expf(om1 - gm1);
#pragma unroll
    for (int nt = 0; nt < 8; ++nt) {
        acc2[nt][0] *= f0; acc2[nt][1] *= f0;
        acc2[nt][2] *= f1; acc2[nt][3] *= f1;
    }
    __syncthreads();
    if (wni == 1) {
#pragma unroll
        for (int nt = 0; nt < 8; ++nt) {
            *(float2*)&macc[(wm + g)*64 + nt*8 + 2*t]     = make_float2(acc2[nt][0], acc2[nt][1]);
            *(float2*)&macc[(wm + 8 + g)*64 + nt*8 + 2*t] = make_float2(acc2[nt][2], acc2[nt][3]);
        }
    }
    __syncthreads();
    if (FINAL) {
        if (wni == 0) {
            float inv0 = 1.f / gs0, inv1 = 1.f / gs1;
#pragma unroll
            for (int nt = 0; nt < 8; ++nt) {
                int cc = nt*8 + 2*t;
                float2 m0v = *(float2*)&macc[(wm + g)*64 + cc];
                float2 m1v = *(float2*)&macc[(wm + 8 + g)*64 + cc];
                *(float2*)&macc[(wm + g)*64 + cc] =
                    make_float2((acc2[nt][0] + m0v.x) * inv0, (acc2[nt][1] + m0v.y) * inv0);
                *(float2*)&macc[(wm + 8 + g)*64 + cc] =
                    make_float2((acc2[nt][2] + m1v.x) * inv1, (acc2[nt][3] + m1v.y) * inv1);
            }
        }
        __syncthreads();
        const int h = bh & 7, b = bh >> 3;
        if (tid < KSZ) wsm[tid] = cw[h * KSZ + tid];
        const bf16* Vb2 = Vg + (long long)bh * SEQ * DH;
#pragma unroll
        for (int it = 0; it < 12; ++it) {
            int pp = it * 256 + tid;
            int rr = pp >> 5, c2 = (pp & 31) << 1;
            int gi = m0 - 16 + rr;
            unsigned val = 0;
            if (gi >= 0 && gi < SEQ) val = *(const unsigned*)(Vb2 + (long long)gi * DH + c2);
            *(unsigned*)(VW + rr * 64 + c2) = val;
        }
        __syncthreads();
        // conv via 48-entry register sliding window
        int c = tid & 63, ib = tid >> 6;
        float win[48];
#pragma unroll
        for (int tt = 0; tt < 48; ++tt)
            win[tt] = __bfloat162float(VW[(ib * 16 + tt) * 64 + c]);
#pragma unroll
        for (int j = 0; j < 16; ++j) {
            int il = ib * 16 + j;
            float accv = macc[il * 64 + c];
#pragma unroll
            for (int tt = 0; tt < KSZ; ++tt)
                accv += wsm[tt] * win[j + tt];
            long long tok = (long long)b * SEQ + m0 + il;
            TOK[tok * DMODEL + h * DH + c] = __float2bfloat16(accv);
        }
    } else {
        if (wni == 0) {
            int row0 = m0 + wm + g, row1 = row0 + 8;
            long long pb = ((long long)bh * NCHUNK + ck) * M_total;
            float* O = OUT + pb * DH;
#pragma unroll
            for (int nt = 0; nt < 8; ++nt) {
                int cc = nt*8 + 2*t;
                float2 m0v = *(float2*)&macc[(wm + g)*64 + cc];
                float2 m1v = *(float2*)&macc[(wm + 8 + g)*64 + cc];
                *(float2*)(O + (long long)row0 * DH + cc) =
                    make_float2(acc2[nt][0] + m0v.x, acc2[nt][1] + m0v.y);
                *(float2*)(O + (long long)row1 * DH + cc) =
                    make_float2(acc2[nt][2] + m1v.x, acc2[nt][3] + m1v.y);
            }
            if (t == 0) {
                PMAX[pb + row0] = gm0; PMAX[pb + row1] = gm1;
                PSUM[pb + row0] = gs0; PSUM[pb + row1] = gs1;
            }
        }
    }
}

// ---------------- combine chunk partials -> a3v ----------------
__global__ void sav_combine(const float* __restrict__ pacc, const float* __restrict__ pmax,
                            const float* __restrict__ psum, float* __restrict__ out)
{
    int idx = blockIdx.x * 256 + threadIdx.x;
    int d = idx & 63;
    int m = (idx >> 6) & (LM - 1);
    int bh = idx >> 14;
    float gmax = -1e30f;
#pragma unroll
    for (int ck = 0; ck < NCHUNK; ++ck)
        gmax = fmaxf(gmax, pmax[((long long)bh * NCHUNK + ck) * LM + m]);
    float gsum = 0.f, val = 0.f;
#pragma unroll
    for (int ck = 0; ck < NCHUNK; ++ck) {
        long long pb = ((long long)bh * NCHUNK + ck) * LM + m;
        float f = __expf(pmax[pb] - gmax);
        gsum += psum[pb] * f;
        val  += pacc[pb * DH + d] * f;
    }
    out[idx] = val / gsum;
}

// ---------------- row softmax ----------------
__global__ void softmax_rows(float* __restrict__ S)
{
    float* row = S + (long long)blockIdx.x * 256;
    int tid = threadIdx.x;
    float v = row[tid];
    __shared__ float red[256];
    red[tid] = v; __syncthreads();
    for (int t = 128; t > 0; t >>= 1) {
        if (tid < t) red[tid] = fmaxf(red[tid], red[tid + t]);
        __syncthreads();
    }
    float mx = red[0]; __syncthreads();
    v = __expf(v - mx);
    red[tid] = v; __syncthreads();
    for (int t = 128; t > 0; t >>= 1) {
        if (tid < t) red[tid] += red[tid + t];
        __syncthreads();
    }
    row[tid] = v / red[0];
}

// ---------------- pinv scale: row-sums of softmax are exactly 1, only cols --
__global__ void col_max(const float* __restrict__ A2, float* __restrict__ s)
{
    int bh = blockIdx.x, j = threadIdx.x;
    const float* X = A2 + (long long)bh * LM * LM;
    float cs = 0.f;
    for (int i = 0; i < LM; ++i) cs += X[i * LM + j];   // softmax entries positive
    __shared__ float r1[256];
    r1[j] = cs; __syncthreads();
    for (int t = 128; t > 0; t >>= 1) {
        if (j < t) r1[j] = fmaxf(r1[j], r1[j + t]);
        __syncthreads();
    }
    if (j == 0) s[bh] = r1[0];
}

__global__ void make_z0(const float* __restrict__ A2, const float* __restrict__ s,
                        float* __restrict__ Z)
{
    __shared__ float red[32];
    int tid = threadIdx.x;
    if (tid < 32) red[tid] = s[tid];
    __syncthreads();
    float cm = red[0];
#pragma unroll
    for (int i = 1; i < 32; ++i) cm = fmaxf(cm, red[i]);
    float inv = 1.f / cm;              // rowmax == 1 exactly
    long long idx = (long long)blockIdx.x * 256 + tid;
    int c  = idx & 255;
    int r  = (int)((idx >> 8) & 255);
    int bh = (int)(idx >> 16);
    Z[idx] = A2[(long long)bh * LM * LM + (long long)c * LM + r] * inv;
}

// ---------------- host driver ----------------
extern "C" void kernel_launch(void* const* d_in, const int* in_sizes, int n_in,
                              void* d_out, int out_size)
{
    const float* x      = (const float*)d_in[0];
    const float* ln_w   = (const float*)d_in[1];
    const float* ln_b   = (const float*)d_in[2];
    const float* w_qkv  = (const float*)d_in[3];
    const float* w_out  = (const float*)d_in[4];
    const float* b_out  = (const float*)d_in[5];
    const float* conv_w = (const float*)d_in[6];
    float* out = (float*)d_out;

    static cudaStream_t s1 = nullptr;
    static cudaEvent_t evFork = nullptr, evJoin = nullptr;
    if (s1 == nullptr) {
        cudaStreamCreateWithFlags(&s1, cudaStreamNonBlocking);
        cudaEventCreateWithFlags(&evFork, cudaEventDisableTiming);
        cudaEventCreateWithFlags(&evJoin, cudaEventDisableTiming);
    }

    void *p;
    cudaGetSymbolAddress(&p, g_xnb);   bf16* XNB = (bf16*)p;
    cudaGetSymbolAddress(&p, g_xnlb);  bf16* XNLB= (bf16*)p;
    cudaGetSymbolAddress(&p, g_wqkvb); bf16* WQB = (bf16*)p;
    cudaGetSymbolAddress(&p, g_woutb); bf16* WOB = (bf16*)p;
    cudaGetSymbolAddress(&p, g_qb);    bf16* Qb  = (bf16*)p;
    cudaGetSymbolAddress(&p, g_kb);    bf16* Kb  = (bf16*)p;
    cudaGetSymbolAddress(&p, g_vb);    bf16* Vb  = (bf16*)p;
    cudaGetSymbolAddress(&p, g_ql);    float* QL = (float*)p;
    cudaGetSymbolAddress(&p, g_kl);    float* KL = (float*)p;
    cudaGetSymbolAddress(&p, g_qlb);   bf16* QLb = (bf16*)p;
    cudaGetSymbolAddress(&p, g_klb);   bf16* KLb = (bf16*)p;
    cudaGetSymbolAddress(&p, g_attn2); float* A2 = (float*)p;
    cudaGetSymbolAddress(&p, g_za);    float* ZA = (float*)p;
    cudaGetSymbolAddress(&p, g_zb);    float* ZB = (float*)p;
    cudaGetSymbolAddress(&p, g_xz);    float* XZ = (float*)p;
    cudaGetSymbolAddress(&p, g_t1);    float* T1 = (float*)p;
    cudaGetSymbolAddress(&p, g_t2);    float* T2 = (float*)p;
    cudaGetSymbolAddress(&p, g_a3v);   float* A3V= (float*)p;
    cudaGetSymbolAddress(&p, g_zavb);  bf16* ZAVb= (bf16*)p;
    cudaGetSymbolAddress(&p, g_tokb);  bf16* TOKb= (bf16*)p;
    cudaGetSymbolAddress(&p, g_pacc);  float* PAC= (float*)p;
    cudaGetSymbolAddress(&p, g_pmax);  float* PMX= (float*)p;
    cudaGetSymbolAddress(&p, g_psum);  float* PSM= (float*)p;
    cudaGetSymbolAddress(&p, g_scale); float* S  = (float*)p;

    const long long sL  = (long long)LM * DH;
    const long long sA2 = (long long)LM * LM;

    const int bf_smem = 3 * (128*72 + 128*72) * 2;
    cudaFuncSetAttribute(gemm_bf<128,128,2,2,0>, cudaFuncAttributeMaxDynamicSharedMemorySize, bf_smem);
    cudaFuncSetAttribute(gemm_bf<128,128,2,2,1>, cudaFuncAttributeMaxDynamicSharedMemorySize, bf_smem);
    cudaFuncSetAttribute(gemm_bf<128,128,2,2,3>, cudaFuncAttributeMaxDynamicSharedMemorySize, bf_smem);
    cudaFuncSetAttribute(fused_sav<true>,  cudaFuncAttributeMaxDynamicSharedMemorySize, SAV_SMEM_BYTES);
    cudaFuncSetAttribute(fused_sav<false>, cudaFuncAttributeMaxDynamicSharedMemorySize, SAV_SMEM_BYTES);

    // ---- prefix (stream 0) ----
    cvt_bf<<<(3*DMODEL*DMODEL/2 + 255)/256, 256>>>(w_qkv, WQB, 3*DMODEL*DMODEL/2);
    cvt_bf<<<(DMODEL*DMODEL/2 + 255)/256, 256>>>(w_out, WOB, DMODEL*DMODEL/2);
    ln_group<<<NGRP, 256>>>(x, ln_w, ln_b, XNB, XNLB);
    gemm_bf<128,128,2,2,3><<<dim3(8, 8, 1), 128, bf_smem>>>(XNLB, WQB, nullptr,
        NGRP, 2*DMODEL, DMODEL, nullptr, nullptr, QL, KL, QLb, KLb, nullptr);

    // ---- fork: branch A (serial pinv chain, tf32) on s1 ----
    cudaEventRecord(evFork, 0);
    cudaStreamWaitEvent(s1, evFork, 0);
    gemm_tc<64,64,2,2,true,0><<<dim3(4, 4, BH), 128, 0, s1>>>(QL, KL, A2,
        LM, LM, DH, sL, sL, sA2, 1.f, 0.f, nullptr, 0.f, nullptr);
    softmax_rows<<<BH*LM, 256, 0, s1>>>(A2);
    col_max<<<BH, 256, 0, s1>>>(A2, S);
    make_z0<<<(BH*LM*LM)/256, 256, 0, s1>>>(A2, S, ZA);
    float* Zin = ZA; float* Zout = ZB;
    for (int it = 0; it < 6; ++it) {
        gemm_tc<64,64,2,2,false,2><<<dim3(4,4,BH), 128, 0, s1>>>(A2, Zin, XZ,
            LM, LM, LM, sA2, sA2, sA2, 1.f, 0.f, T1, 7.f, nullptr);
        gemm_tc<64,64,2,2,false,0><<<dim3(4,4,BH), 128, 0, s1>>>(XZ, T1, T2,
            LM, LM, LM, sA2, sA2, sA2, -1.f, 15.f, nullptr, 0.f, nullptr);
        gemm_tc<64,64,2,2,false,0><<<dim3(4,4,BH), 128, 0, s1>>>(XZ, T2, T1,
            LM, LM, LM, sA2, sA2, sA2, -1.f, 13.f, nullptr, 0.f, nullptr);
        gemm_tc<64,64,2,2,false,0><<<dim3(4,4,BH), 128, 0, s1>>>(Zin, T1, Zout,
            LM, LM, LM, sA2, sA2, sA2, 0.25f, 0.f, nullptr, 0.f, nullptr);
        float* tmp = Zin; Zin = Zout; Zout = tmp;
    }
    cudaEventRecord(evJoin, s1);

    // ---- branch B (bf16, throughput-bound) on stream 0 ----
    gemm_bf<128,128,2,2,1><<<dim3(12, 256, 1), 128, bf_smem>>>(XNB, WQB, nullptr,
        NTOK, 3*DMODEL, DMODEL, nullptr, nullptr, nullptr, nullptr, Qb, Kb, Vb);
    fused_sav<false><<<dim3(LM/64, NCHUNK, BH), 256, SAV_SMEM_BYTES>>>(QLb, Kb, Vb,
        PAC, PMX, PSM, LM, SEQ, SEQ/NCHUNK, nullptr, nullptr, nullptr);
    sav_combine<<<(BH*LM*DH)/256, 256>>>(PAC, PMX, PSM, A3V);

    // ---- join ----
    cudaStreamWaitEvent(0, evJoin, 0);
    gemm_tc<64,64,2,2,false,4><<<dim3(1, 4, BH), 128>>>(Zin, A3V, nullptr,
        LM, DH, LM, sA2, sL, sL, 1.f, 0.f, nullptr, 0.f, (float*)ZAVb);
    fused_sav<true><<<dim3(SEQ/64, 1, BH), 256, SAV_SMEM_BYTES>>>(Qb, KLb, ZAVb,
        nullptr, nullptr, nullptr, SEQ, LM, LM, Vb, conv_w, TOKb);
    gemm_bf<128,128,2,2,0><<<dim3(4, 256, 1), 128, bf_smem>>>(TOKb, WOB, out,
        NTOK, DMODEL, DMODEL, b_out, x, nullptr, nullptr, nullptr, nullptr, nullptr);
}

// round 14
// speedup vs baseline: 1.7303x; 1.0131x over previous
#include <cuda_runtime.h>
#include <cuda_bf16.h>
#include <cstdint>

// ---------------- problem constants ----------------
#define BATCH 4
#define SEQ   8192
#define DMODEL 512
#define HEADS 8
#define DH    64
#define LM    256
#define LGRP  32
#define NTOK  (BATCH*SEQ)
#define BH    (BATCH*HEADS)
#define KSZ   33
#define NCHUNK 8
#define NGRP  (NTOK/LGRP)

typedef __nv_bfloat16 bf16;
typedef __nv_bfloat162 bf162;

// ---------------- scratch ----------------
__device__ bf16  g_xnb  [(size_t)NTOK*DMODEL];
__device__ bf16  g_xnlb [(size_t)NGRP*DMODEL];
__device__ bf16  g_wqkvb[(size_t)3*DMODEL*DMODEL];
__device__ bf16  g_woutb[(size_t)DMODEL*DMODEL];
__device__ bf16  g_qb   [(size_t)BH*SEQ*DH];
__device__ bf16  g_kb   [(size_t)BH*SEQ*DH];
__device__ bf16  g_vb   [(size_t)BH*SEQ*DH];
__device__ float g_ql   [(size_t)BH*LM*DH];
__device__ float g_kl   [(size_t)BH*LM*DH];
__device__ bf16  g_qlb  [(size_t)BH*LM*DH];
__device__ bf16  g_klb  [(size_t)BH*LM*DH];
__device__ float g_attn2[(size_t)BH*LM*LM];
__device__ float g_za   [(size_t)BH*LM*LM];
__device__ float g_zb   [(size_t)BH*LM*LM];
__device__ float g_xz   [(size_t)BH*LM*LM];
__device__ float g_t1   [(size_t)BH*LM*LM];
__device__ float g_t2   [(size_t)BH*LM*LM];
__device__ float g_a3v  [(size_t)BH*LM*DH];
__device__ bf16  g_zavb [(size_t)BH*LM*DH];
__device__ bf16  g_tokb [(size_t)NTOK*DMODEL];
__device__ float g_pacc [(size_t)BH*NCHUNK*LM*DH];
__device__ float g_pmax [(size_t)BH*NCHUNK*LM];
__device__ float g_psum [(size_t)BH*NCHUNK*LM];
__device__ float g_scale[64];

// ---------------- helpers ----------------
__device__ __forceinline__ void mma_tf32(float* c, const unsigned* a, const unsigned* b) {
    asm volatile(
        "mma.sync.aligned.m16n8k8.row.col.f32.tf32.tf32.f32 "
        "{%0,%1,%2,%3},{%4,%5,%6,%7},{%8,%9},{%0,%1,%2,%3};"
        : "+f"(c[0]), "+f"(c[1]), "+f"(c[2]), "+f"(c[3])
        : "r"(a[0]), "r"(a[1]), "r"(a[2]), "r"(a[3]), "r"(b[0]), "r"(b[1]));
}
__device__ __forceinline__ void mma_bf(float* c, const unsigned* a, const unsigned* b) {
    asm volatile(
        "mma.sync.aligned.m16n8k16.row.col.f32.bf16.bf16.f32 "
        "{%0,%1,%2,%3},{%4,%5,%6,%7},{%8,%9},{%0,%1,%2,%3};"
        : "+f"(c[0]), "+f"(c[1]), "+f"(c[2]), "+f"(c[3])
        : "r"(a[0]), "r"(a[1]), "r"(a[2]), "r"(a[3]), "r"(b[0]), "r"(b[1]));
}
__device__ __forceinline__ void cpa16(void* s, const void* g) {
    unsigned sa = (unsigned)__cvta_generic_to_shared(s);
    asm volatile("cp.async.cg.shared.global [%0], [%1], 16;" :: "r"(sa), "l"(g));
}
#define CP_COMMIT() asm volatile("cp.async.commit_group;")
#define CP_WAIT1()  asm volatile("cp.async.wait_group 1;")
#define CP_WAIT0()  asm volatile("cp.async.wait_group 0;")

__device__ __forceinline__ unsigned fu(float f) { return __float_as_uint(f); }
__device__ __forceinline__ unsigned pk(float lo, float hi) {
    unsigned r;
    asm("cvt.rn.bf16x2.f32 %0, %1, %2;" : "=r"(r) : "f"(hi), "f"(lo));
    return r;
}
__device__ __forceinline__ unsigned smem_u32(const void* p) {
    return (unsigned)__cvta_generic_to_shared(p);
}
__device__ __forceinline__ void ldm_x4(unsigned* r, unsigned addr) {
    asm volatile("ldmatrix.sync.aligned.m8n8.x4.shared.b16 {%0,%1,%2,%3}, [%4];"
        : "=r"(r[0]), "=r"(r[1]), "=r"(r[2]), "=r"(r[3]) : "r"(addr));
}
__device__ __forceinline__ void ldm_x4_t(unsigned* r, unsigned addr) {
    asm volatile("ldmatrix.sync.aligned.m8n8.x4.trans.shared.b16 {%0,%1,%2,%3}, [%4];"
        : "=r"(r[0]), "=r"(r[1]), "=r"(r[2]), "=r"(r[3]) : "r"(addr));
}

// ---------------- fp32 -> bf16 convert ----------------
__global__ void cvt_bf(const float* __restrict__ src, bf16* __restrict__ dst, int n2)
{
    int i = blockIdx.x * 256 + threadIdx.x;
    if (i < n2) {
        float2 v = *(const float2*)(src + 2 * i);
        *(unsigned*)(dst + 2 * i) = pk(v.x, v.y);
    }
}

// ---------------- fused LayerNorm + group mean -> bf16 ----------------
__global__ void __launch_bounds__(256) ln_group(
    const float* __restrict__ x, const float* __restrict__ wln,
    const float* __restrict__ bln, bf16* __restrict__ y, bf16* __restrict__ xnl)
{
    __shared__ float gsm[8][DMODEL];
    const int grp = blockIdx.x;
    const int tid = threadIdx.x;
    const int w = tid >> 5, lane = tid & 31;

    float w4[4][4], b4[4][4];
#pragma unroll
    for (int kk = 0; kk < 4; ++kk) {
        *(float4*)w4[kk] = *(const float4*)(wln + kk * 128 + lane * 4);
        *(float4*)b4[kk] = *(const float4*)(bln + kk * 128 + lane * 4);
    }
    float gacc[4][4];
#pragma unroll
    for (int kk = 0; kk < 4; ++kk)
#pragma unroll
        for (int e = 0; e < 4; ++e) gacc[kk][e] = 0.f;

#pragma unroll
    for (int rr = 0; rr < 4; ++rr) {
        int row = grp * LGRP + w + rr * 8;
        const float* xr = x + (long long)row * DMODEL;
        float v[4][4];
        float s = 0.f, s2 = 0.f;
#pragma unroll
        for (int kk = 0; kk < 4; ++kk) {
            *(float4*)v[kk] = *(const float4*)(xr + kk * 128 + lane * 4);
#pragma unroll
            for (int e = 0; e < 4; ++e) { s += v[kk][e]; s2 += v[kk][e] * v[kk][e]; }
        }
#pragma unroll
        for (int o = 16; o > 0; o >>= 1) {
            s  += __shfl_xor_sync(0xffffffffu, s, o);
            s2 += __shfl_xor_sync(0xffffffffu, s2, o);
        }
        float mean = s * (1.f / DMODEL);
        float var  = s2 * (1.f / DMODEL) - mean * mean;
        float inv  = rsqrtf(var + 1e-5f);
        bf16* yr = y + (long long)row * DMODEL;
#pragma unroll
        for (int kk = 0; kk < 4; ++kk) {
            float o0 = (v[kk][0] - mean) * inv * w4[kk][0] + b4[kk][0];
            float o1 = (v[kk][1] - mean) * inv * w4[kk][1] + b4[kk][1];
            float o2 = (v[kk][2] - mean) * inv * w4[kk][2] + b4[kk][2];
            float o3 = (v[kk][3] - mean) * inv * w4[kk][3] + b4[kk][3];
            uint2 u; u.x = pk(o0, o1); u.y = pk(o2, o3);
            *(uint2*)(yr + kk * 128 + lane * 4) = u;
            gacc[kk][0] += o0; gacc[kk][1] += o1; gacc[kk][2] += o2; gacc[kk][3] += o3;
        }
    }
#pragma unroll
    for (int kk = 0; kk < 4; ++kk)
        *(float4*)&gsm[w][kk * 128 + lane * 4] = *(float4*)gacc[kk];
    __syncthreads();
    int c = tid * 2;
    float a0 = 0.f, a1 = 0.f;
#pragma unroll
    for (int ww = 0; ww < 8; ++ww) { a0 += gsm[ww][c]; a1 += gsm[ww][c + 1]; }
    *(unsigned*)(xnl + (long long)grp * DMODEL + c) = pk(a0 * (1.f / LGRP), a1 * (1.f / LGRP));
}

// ---------------- bf16 tensor-core GEMM, BK=64, ldmatrix, 8 warps ----------
template<int BM, int BN, int WARPS_M, int WARPS_N, int MODE>
__global__ void __launch_bounds__(32*WARPS_M*WARPS_N, 2) gemm_bf(
    const bf16* __restrict__ A, const bf16* __restrict__ B, float* __restrict__ C,
    int M, int N, int K,
    const float* __restrict__ bias, const float* __restrict__ resid,
    float* __restrict__ Qf, float* __restrict__ Kf,
    bf16* __restrict__ Qb, bf16* __restrict__ Kb, bf16* __restrict__ Vb)
{
    constexpr int BK  = 64;
    constexpr int NTH = 32 * WARPS_M * WARPS_N;
    constexpr int WM  = BM / WARPS_M;
    constexpr int WN  = BN / WARPS_N;
    constexpr int MT  = WM / 16;
    constexpr int NT  = WN / 8;
    constexpr int RS  = BK + 8;
    constexpr int SA  = BM * RS;
    constexpr int SB  = BN * RS;
    constexpr int CPR = BK / 8;
    constexpr int AC  = BM * CPR / NTH;
    constexpr int BC  = BN * CPR / NTH;

    extern __shared__ __align__(16) bf16 sm[];
    const unsigned smu = smem_u32(sm);

    const int tid  = threadIdx.x;
    const int w    = tid >> 5, lane = tid & 31;
    const int g    = lane >> 2, t = lane & 3;
    const int msel = lane >> 3, mrow = lane & 7;
    const int wm   = (w / WARPS_N) * WM;
    const int wn   = (w % WARPS_N) * WN;
    const int m0   = blockIdx.y * BM;
    const int n0   = blockIdx.x * BN;

    float acc[MT][NT][4];
#pragma unroll
    for (int i = 0; i < MT; i++)
#pragma unroll
        for (int j = 0; j < NT; j++)
#pragma unroll
            for (int r = 0; r < 4; r++) acc[i][j][r] = 0.f;

    auto load_stage = [&](int st, int k0) {
        bf16* as = sm + st * (SA + SB);
        bf16* bs = as + SA;
#pragma unroll
        for (int it = 0; it < AC; ++it) {
            int idx = it * NTH + tid;
            int r = idx / CPR, ch = (idx % CPR) << 3;
            cpa16(as + r * RS + ch, A + (long long)(m0 + r) * K + k0 + ch);
        }
#pragma unroll
        for (int it = 0; it < BC; ++it) {
            int idx = it * NTH + tid;
            int r = idx / CPR, ch = (idx % CPR) << 3;
            cpa16(bs + r * RS + ch, B + (long long)(n0 + r) * K + k0 + ch);
        }
    };

    const int nk = K / BK;
    load_stage(0, 0);
    CP_COMMIT();
    if (nk > 1) { load_stage(1, BK); CP_COMMIT(); }

    for (int kt = 0; kt < nk; ++kt) {
        if (kt + 2 < nk) {
            CP_WAIT1();
            __syncthreads();
            load_stage((kt + 2) % 3, (kt + 2) * BK);
            CP_COMMIT();
        } else if (kt + 1 < nk) {
            CP_WAIT1();
            __syncthreads();
        } else {
            CP_WAIT0();
            __syncthreads();
        }
        const unsigned asu = smu + (unsigned)((kt % 3) * (SA + SB)) * 2u;
        const unsigned bsu = asu + (unsigned)SA * 2u;
#pragma unroll
        for (int ks = 0; ks < 4; ++ks) {
            const int kb = ks * 16;
            unsigned af[MT][4], bfr[NT][2];
#pragma unroll
            for (int i = 0; i < MT; i++) {
                int mb = wm + i * 16;
                unsigned addr = asu + (unsigned)(((mb + ((msel & 1) << 3) + mrow) * RS)
                                + kb + ((msel >> 1) << 3)) * 2u;
                ldm_x4(af[i], addr);
            }
#pragma unroll
            for (int jp = 0; jp < NT / 2; ++jp) {
                unsigned q[4];
                unsigned addr = bsu + (unsigned)(((wn + ((jp * 2 + (msel >> 1)) << 3) + mrow) * RS)
                                + kb + ((msel & 1) << 3)) * 2u;
                ldm_x4(q, addr);
                bfr[2*jp][0]   = q[0]; bfr[2*jp][1]   = q[1];
                bfr[2*jp+1][0] = q[2]; bfr[2*jp+1][1] = q[3];
            }
#pragma unroll
            for (int i = 0; i < MT; i++)
#pragma unroll
                for (int j = 0; j < NT; j++)
                    mma_bf(acc[i][j], af[i], bfr[j]);
        }
    }

    // epilogue
#pragma unroll
    for (int i = 0; i < MT; i++) {
        int gm = m0 + wm + i * 16 + g;
#pragma unroll
        for (int j = 0; j < NT; j++) {
            int gn = n0 + wn + j * 8 + 2 * t;
            float v00 = acc[i][j][0], v01 = acc[i][j][1];
            float v10 = acc[i][j][2], v11 = acc[i][j][3];
            if (MODE == 1) {
                int which = gn >> 9;
                int h = (gn >> 6) & 7;
                int c = gn & 63;
                float sc = (which == 0) ? 0.125f : 1.f;
                bf16* tgt = (which == 0) ? Qb : ((which == 1) ? Kb : Vb);
                int b0i = gm >> 13, i0i = gm & (SEQ - 1);
                int b1i = (gm + 8) >> 13, i1i = (gm + 8) & (SEQ - 1);
                long long d0 = (((long long)(b0i * HEADS + h)) * SEQ + i0i) * DH + c;
                long long d1 = (((long long)(b1i * HEADS + h)) * SEQ + i1i) * DH + c;
                *(unsigned*)(tgt + d0) = pk(v00 * sc, v01 * sc);
                *(unsigned*)(tgt + d1) = pk(v10 * sc, v11 * sc);
            } else if (MODE == 3) {
                int which = gn >> 9;
                int h = (gn >> 6) & 7;
                int c = gn & 63;
                float sc = (which == 0) ? 0.125f : 1.f;
                float* tf = (which == 0) ? Qf : Kf;
                bf16*  tb = (which == 0) ? Qb : Kb;
                int b0i = gm >> 8, m0i = gm & 255;
                int b1i = (gm + 8) >> 8, m1i = (gm + 8) & 255;
                long long d0 = (((long long)(b0i * HEADS + h)) * LM + m0i) * DH + c;
                long long d1 = (((long long)(b1i * HEADS + h)) * LM + m1i) * DH + c;
                *(float2*)(tf + d0) = make_float2(v00 * sc, v01 * sc);
                *(float2*)(tf + d1) = make_float2(v10 * sc, v11 * sc);
                *(unsigned*)(tb + d0) = pk(v00 * sc, v01 * sc);
                *(unsigned*)(tb + d1) = pk(v10 * sc, v11 * sc);
            } else {
                if (bias) {
                    v00 += bias[gn]; v01 += bias[gn + 1];
                    v10 += bias[gn]; v11 += bias[gn + 1];
                }
                if (resid) {
                    v00 += resid[(long long)gm * N + gn];
                    v01 += resid[(long long)gm * N + gn + 1];
                    v10 += resid[(long long)(gm + 8) * N + gn];
                    v11 += resid[(long long)(gm + 8) * N + gn + 1];
                }
                *(float2*)(C + (long long)gm * N + gn)       = make_float2(v00, v01);
                *(float2*)(C + (long long)(gm + 8) * N + gn) = make_float2(v10, v11);
            }
        }
    }
}

// ---------------- tf32 tensor-core GEMM (pinv chain + attn2 + ZAV) ----------
template<int BM, int BN, int WARPS_M, int WARPS_N, bool TB, int MODE>
__global__ void __launch_bounds__(32*WARPS_M*WARPS_N) gemm_tc(
    const float* __restrict__ A, const float* __restrict__ B, float* __restrict__ C,
    int M, int N, int K, long long sA, long long sB, long long sC,
    float alpha, float betaI, float* __restrict__ C2, float beta2,
    float* __restrict__ Qp)
{
    constexpr int BK  = 16;
    constexpr int NTH = 32 * WARPS_M * WARPS_N;
    constexpr int WM  = BM / WARPS_M;
    constexpr int WN  = BN / WARPS_N;
    constexpr int MT  = WM / 16;
    constexpr int NT  = WN / 8;
    constexpr int SA  = BM * 20;
    constexpr int SB  = TB ? BN * 20 : BK * (BN + 8);
    constexpr int AC  = BM * 4 / NTH;
    constexpr int BC  = TB ? BN * 4 / NTH : (BK * BN / 4) / NTH;

    const int z = blockIdx.z;
    A += z * sA; B += z * sB;
    if (C)  C  += z * sC;
    if (C2) C2 += z * sC;

    __shared__ float smem[3 * (SA + SB)];

    const int tid  = threadIdx.x;
    const int w    = tid >> 5, lane = tid & 31;
    const int g    = lane >> 2, t = lane & 3;
    const int wm   = (w / WARPS_N) * WM;
    const int wn   = (w % WARPS_N) * WN;
    const int m0   = blockIdx.y * BM;
    const int n0   = blockIdx.x * BN;

    float acc[MT][NT][4];
#pragma unroll
    for (int i = 0; i < MT; i++)
#pragma unroll
        for (int j = 0; j < NT; j++)
#pragma unroll
            for (int r = 0; r < 4; r++) acc[i][j][r] = 0.f;

    auto load_stage = [&](int st, int k0) {
        float* as = smem + st * (SA + SB);
        float* bs = as + SA;
#pragma unroll
        for (int it = 0; it < AC; ++it) {
            int idx = it * NTH + tid;
            int r = idx >> 2, ch = (idx & 3) << 2;
            cpa16(as + r * 20 + ch, A + (long long)(m0 + r) * K + k0 + ch);
        }
        if (TB) {
#pragma unroll
            for (int it = 0; it < BC; ++it) {
                int idx = it * NTH + tid;
                int r = idx >> 2, ch = (idx & 3) << 2;
                cpa16(bs + r * 20 + ch, B + (long long)(n0 + r) * K + k0 + ch);
            }
        } else {
#pragma unroll
            for (int it = 0; it < BC; ++it) {
                int idx = it * NTH + tid;
                int kr = idx / (BN / 4), c = (idx % (BN / 4)) << 2;
                cpa16(bs + kr * (BN + 8) + c, B + (long long)(k0 + kr) * N + n0 + c);
            }
        }
    };

    const int nk = K / BK;
    load_stage(0, 0);
    CP_COMMIT();
    if (nk > 1) { load_stage(1, BK); CP_COMMIT(); }

    for (int kt = 0; kt < nk; ++kt) {
        if (kt + 2 < nk) {
            CP_WAIT1();
            __syncthreads();
            load_stage((kt + 2) % 3, (kt + 2) * BK);
            CP_COMMIT();
        } else if (kt + 1 < nk) {
            CP_WAIT1();
            __syncthreads();
        } else {
            CP_WAIT0();
            __syncthreads();
        }
        const float* as = smem + (kt % 3) * (SA + SB);
        const float* bs = as + SA;
#pragma unroll
        for (int ks = 0; ks < 2; ++ks) {
            const int kb = ks * 8;
            unsigned af[MT][4], bfr[NT][2];
#pragma unroll
            for (int i = 0; i < MT; i++) {
                int mb = wm + i * 16;
                af[i][0] = fu(as[(mb + g) * 20 + kb + t]);
                af[i][1] = fu(as[(mb + 8 + g) * 20 + kb + t]);
                af[i][2] = fu(as[(mb + g) * 20 + kb + t + 4]);
                af[i][3] = fu(as[(mb + 8 + g) * 20 + kb + t + 4]);
            }
#pragma unroll
            for (int j = 0; j < NT; j++) {
                int nb = wn + j * 8 + g;
                if (TB) {
                    bfr[j][0] = fu(bs[nb * 20 + kb + t]);
                    bfr[j][1] = fu(bs[nb * 20 + kb + t + 4]);
                } else {
                    bfr[j][0] = fu(bs[(kb + t) * (BN + 8) + nb]);
                    bfr[j][1] = fu(bs[(kb + t + 4) * (BN + 8) + nb]);
                }
            }
#pragma unroll
            for (int i = 0; i < MT; i++)
#pragma unroll
                for (int j = 0; j < NT; j++)
                    mma_tf32(acc[i][j], af[i], bfr[j]);
        }
    }

#pragma unroll
    for (int i = 0; i < MT; i++) {
        int gm = m0 + wm + i * 16 + g;
#pragma unroll
        for (int j = 0; j < NT; j++) {
            int gn = n0 + wn + j * 8 + 2 * t;
            float v00 = alpha * acc[i][j][0];
            float v01 = alpha * acc[i][j][1];
            float v10 = alpha * acc[i][j][2];
            float v11 = alpha * acc[i][j][3];
            if (MODE == 4) {
                bf16* Cb = (bf16*)Qp + (long long)z * sC;
                *(unsigned*)(Cb + (long long)gm * N + gn)       = pk(v00, v01);
                *(unsigned*)(Cb + (long long)(gm + 8) * N + gn) = pk(v10, v11);
            } else {
                if (betaI != 0.f) {
                    if (gm == gn)         v00 += betaI;
                    if (gm == gn + 1)     v01 += betaI;
                    if (gm + 8 == gn)     v10 += betaI;
                    if (gm + 8 == gn + 1) v11 += betaI;
                }
                *(float2*)(C + (long long)gm * N + gn)       = make_float2(v00, v01);
                *(float2*)(C + (long long)(gm + 8) * N + gn) = make_float2(v10, v11);
                if (MODE == 2) {
                    float w00 = ((gm == gn)         ? beta2 : 0.f) - v00;
                    float w01 = ((gm == gn + 1)     ? beta2 : 0.f) - v01;
                    float w10 = ((gm + 8 == gn)     ? beta2 : 0.f) - v10;
                    float w11 = ((gm + 8 == gn + 1) ? beta2 : 0.f) - v11;
                    *(float2*)(C2 + (long long)gm * N + gn)       = make_float2(w00, w01);
                    *(float2*)(C2 + (long long)(gm + 8) * N + gn) = make_float2(w10, w11);
                }
            }
        }
    }
}

// ---------------- fused softmax(A@B^T)@C in bf16, ldmatrix fragments --------
#define SAV_SMEM_BYTES (5*64*72*2)
template<bool FINAL>
__global__ void __launch_bounds__(256) fused_sav(
    const bf16* __restrict__ A, const bf16* __restrict__ B, const bf16* __restrict__ C,
    float* __restrict__ OUT, float* __restrict__ PMAX, float* __restrict__ PSUM,
    int M_total, int N_total, int chunk_len,
    const bf16* __restrict__ Vg, const float* __restrict__ cw, bf16* __restrict__ TOK)
{
    extern __shared__ __align__(16) char sb[];
    bf16* Qs = (bf16*)sb;
    bf16* Ks = Qs + 64*72;
    bf16* Vs = Ks + 2*64*72;
    float* macc = (float*)sb;
    float* wmax = (float*)(sb + 16384);
    float* wsum = (float*)(sb + 16896);
    bf16*  VW   = (bf16*)(sb + 17408);
    float* wsm  = (float*)(sb + 17408 + 12288);
    const unsigned sbu = smem_u32(sb);

    const int bh = blockIdx.z, mt = blockIdx.x, ck = blockIdx.y;
    const int m0 = mt * 64;
    const int tid = threadIdx.x;
    const int w = tid >> 5, lane = tid & 31;
    const int g = lane >> 2, t = lane & 3;
    const int msel = lane >> 3, mrow = lane & 7;
    const int wm = (w >> 1) * 16;
    const int wni = w & 1;
    const int wn = wni * 32;

    const bf16* Ap = A + ((long long)bh * M_total + m0) * DH;
    const bf16* Bb = B + (long long)bh * N_total * DH;
    const bf16* Cb = C + (long long)bh * N_total * DH;

#pragma unroll
    for (int it = 0; it < 2; ++it) {
        int idx = it * 256 + tid;
        int r = idx >> 3, c = (idx & 7) << 3;
        *(uint4*)(Qs + r * 72 + c) = *(const uint4*)(Ap + r * DH + c);
    }

    const int n_start = ck * chunk_len;

    auto load_kv = [&](int st, int nb) {
        const bf16* Kp = Bb + (long long)(n_start + nb) * DH;
        const bf16* Vp = Cb + (long long)(n_start + nb) * DH;
        bf16* ks = Ks + st * 64 * 72;
        bf16* vs = Vs + st * 64 * 72;
#pragma unroll
        for (int it = 0; it < 2; ++it) {
            int idx = it * 256 + tid;
            int r = idx >> 3, c = (idx & 7) << 3;
            cpa16(ks + r * 72 + c, Kp + r * DH + c);
            cpa16(vs + r * 72 + c, Vp + r * DH + c);
        }
    };

    float acc2[8][4];
#pragma unroll
    for (int nt = 0; nt < 8; ++nt)
#pragma unroll
        for (int r = 0; r < 4; ++r) acc2[nt][r] = 0.f;
    float rmax0 = -1e30f, rmax1 = -1e30f, rsum0 = 0.f, rsum1 = 0.f;

    load_kv(0, 0);
    CP_COMMIT();

    const int nt_iters = chunk_len / 64;
    for (int itn = 0; itn < nt_iters; ++itn) {
        if (itn + 1 < nt_iters) {
            load_kv((itn + 1) & 1, (itn + 1) * 64);
            CP_COMMIT();
            CP_WAIT1();
        } else {
            CP_WAIT0();
        }
        __syncthreads();
        const unsigned ksu = sbu + (unsigned)((1 + (itn & 1)) * 64 * 72) * 2u;
        const unsigned vsu = sbu + (unsigned)((3 + (itn & 1)) * 64 * 72) * 2u;

        float sacc[4][4];
#pragma unroll
        for (int j = 0; j < 4; ++j)
#pragma unroll
            for (int r = 0; r < 4; ++r) sacc[j][r] = 0.f;
#pragma unroll
        for (int kk0 = 0; kk0 < 4; ++kk0) {
            int kb = kk0 * 16;
            unsigned af[4];
            unsigned qaddr = sbu + (unsigned)(((wm + ((msel & 1) << 3) + mrow) * 72)
                              + kb + ((msel >> 1) << 3)) * 2u;
            ldm_x4(af, qaddr);
#pragma unroll
            for (int jp = 0; jp < 2; ++jp) {
                unsigned q[4];
                unsigned kaddr = ksu + (unsigned)(((wn + ((jp * 2 + (msel >> 1)) << 3) + mrow) * 72)
                                  + kb + ((msel & 1) << 3)) * 2u;
                ldm_x4(q, kaddr);
                mma_bf(sacc[2*jp],   af, q);
                mma_bf(sacc[2*jp+1], af, q + 2);
            }
        }
        float tm0 = -1e30f, tm1 = -1e30f;
#pragma unroll
        for (int j = 0; j < 4; ++j) {
            tm0 = fmaxf(tm0, fmaxf(sacc[j][0], sacc[j][1]));
            tm1 = fmaxf(tm1, fmaxf(sacc[j][2], sacc[j][3]));
        }
        tm0 = fmaxf(tm0, __shfl_xor_sync(0xffffffffu, tm0, 1));
        tm0 = fmaxf(tm0, __shfl_xor_sync(0xffffffffu, tm0, 2));
        tm1 = fmaxf(tm1, __shfl_xor_sync(0xffffffffu, tm1, 1));
        tm1 = fmaxf(tm1, __shfl_xor_sync(0xffffffffu, tm1, 2));
        float nm0 = fmaxf(rmax0, tm0), nm1 = fmaxf(rmax1, tm1);
        float sc0 = __expf(rmax0 - nm0), sc1 = __expf(rmax1 - nm1);
        float ts0 = 0.f, ts1 = 0.f;
#pragma unroll
        for (int j = 0; j < 4; ++j) {
            sacc[j][0] = __expf(sacc[j][0] - nm0);
            sacc[j][1] = __expf(sacc[j][1] - nm0);
            sacc[j][2] = __expf(sacc[j][2] - nm1);
            sacc[j][3] = __expf(sacc[j][3] - nm1);
            ts0 += sacc[j][0] + sacc[j][1];
            ts1 += sacc[j][2] + sacc[j][3];
        }
        ts0 += __shfl_xor_sync(0xffffffffu, ts0, 1);
        ts0 += __shfl_xor_sync(0xffffffffu, ts0, 2);
        ts1 += __shfl_xor_sync(0xffffffffu, ts1, 1);
        ts1 += __shfl_xor_sync(0xffffffffu, ts1, 2);
        rsum0 = rsum0 * sc0 + ts0;
        rsum1 = rsum1 * sc1 + ts1;
        rmax0 = nm0; rmax1 = nm1;
#pragma unroll
        for (int nt = 0; nt < 8; ++nt) {
            acc2[nt][0] *= sc0; acc2[nt][1] *= sc0;
            acc2[nt][2] *= sc1; acc2[nt][3] *= sc1;
        }
#pragma unroll
        for (int kc = 0; kc < 2; ++kc) {
            int kb2 = wn + kc * 16;
            unsigned af2[4];
            af2[0] = pk(sacc[kc*2][0], sacc[kc*2][1]);
            af2[1] = pk(sacc[kc*2][2], sacc[kc*2][3]);
            af2[2] = pk(sacc[kc*2+1][0], sacc[kc*2+1][1]);
            af2[3] = pk(sacc[kc*2+1][2], sacc[kc*2+1][3]);
#pragma unroll
            for (int np = 0; np < 4; ++np) {
                unsigned q[4];
                unsigned vaddr = vsu + (unsigned)(((kb2 + ((msel & 1) << 3) + mrow) * 72)
                                  + np * 16 + ((msel >> 1) << 3)) * 2u;
                ldm_x4_t(q, vaddr);
                mma_bf(acc2[2*np],   af2, q);
                mma_bf(acc2[2*np+1], af2, q + 2);
            }
        }
        __syncthreads();
    }

    if (t == 0) {
        wmax[wni*64 + wm + g]     = rmax0;
        wmax[wni*64 + wm + 8 + g] = rmax1;
        wsum[wni*64 + wm + g]     = rsum0;
        wsum[wni*64 + wm + 8 + g] = rsum1;
    }
    __syncthreads();
    int other = wni ^ 1;
    float om0 = wmax[other*64 + wm + g],     os0 = wsum[other*64 + wm + g];
    float om1 = wmax[other*64 + wm + 8 + g], os1 = wsum[other*64 + wm + 8 + g];
    float gm0 = fmaxf(rmax0, om0), gm1 = fmaxf(rmax1, om1);
    float f0 = __expf(rmax0 - gm0), f1 = __expf(rmax1 - gm1);
    float gs0 = rsum0 * f0 + os0 * __expf(om0 - gm0);
    float gs1 = rsum1 * f1 + os1 * __expf(om1 - gm1);
#pragma unroll
    for (int nt = 0; nt < 8; ++nt) {
        acc2[nt][0] *= f0; acc2[nt][1] *= f0;
        acc2[nt][2] *= f1; acc2[nt][3] *= f1;
    }
    __syncthreads();
    if (wni == 1) {
#pragma unroll
        for (int nt = 0; nt < 8; ++nt) {
            *(float2*)&macc[(wm + g)*64 + nt*8 + 2*t]     = make_float2(acc2[nt][0], acc2[nt][1]);
            *(float2*)&macc[(wm + 8 + g)*64 + nt*8 + 2*t] = make_float2(acc2[nt][2], acc2[nt][3]);
        }
    }
    __syncthreads();
    if (FINAL) {
        if (wni == 0) {
            float inv0 = 1.f / gs0, inv1 = 1.f / gs1;
#pragma unroll
            for (int nt = 0; nt < 8; ++nt) {
                int cc = nt*8 + 2*t;
                float2 m0v = *(float2*)&macc[(wm + g)*64 + cc];
                float2 m1v = *(float2*)&macc[(wm + 8 + g)*64 + cc];
                *(float2*)&macc[(wm + g)*64 + cc] =
                    make_float2((acc2[nt][0] + m0v.x) * inv0, (acc2[nt][1] + m0v.y) * inv0);
                *(float2*)&macc[(wm + 8 + g)*64 + cc] =
                    make_float2((acc2[nt][2] + m1v.x) * inv1, (acc2[nt][3] + m1v.y) * inv1);
            }
        }
        __syncthreads();
        const int h = bh & 7, b = bh >> 3;
        if (tid < KSZ) wsm[tid] = cw[h * KSZ + tid];
        const bf16* Vb2 = Vg + (long long)bh * SEQ * DH;
#pragma unroll
        for (int it = 0; it < 12; ++it) {
            int pp = it * 256 + tid;
            int rr = pp >> 5, c2 = (pp & 31) << 1;
            int gi = m0 - 16 + rr;
            unsigned val = 0;
            if (gi >= 0 && gi < SEQ) val = *(const unsigned*)(Vb2 + (long long)gi * DH + c2);
            *(unsigned*)(VW + rr * 64 + c2) = val;
        }
        __syncthreads();
        int c = tid & 63, ib = tid >> 6;
        float win[48];
#pragma unroll
        for (int tt = 0; tt < 48; ++tt)
            win[tt] = __bfloat162float(VW[(ib * 16 + tt) * 64 + c]);
#pragma unroll
        for (int j = 0; j < 16; ++j) {
            int il = ib * 16 + j;
            float accv = macc[il * 64 + c];
#pragma unroll
            for (int tt = 0; tt < KSZ; ++tt)
                accv += wsm[tt] * win[j + tt];
            long long tok = (long long)b * SEQ + m0 + il;
            TOK[tok * DMODEL + h * DH + c] = __float2bfloat16(accv);
        }
    } else {
        if (wni == 0) {
            int row0 = m0 + wm + g, row1 = row0 + 8;
            long long pb = ((long long)bh * NCHUNK + ck) * M_total;
            float* O = OUT + pb * DH;
#pragma unroll
            for (int nt = 0; nt < 8; ++nt) {
                int cc = nt*8 + 2*t;
                float2 m0v = *(float2*)&macc[(wm + g)*64 + cc];
                float2 m1v = *(float2*)&macc[(wm + 8 + g)*64 + cc];
                *(float2*)(O + (long long)row0 * DH + cc) =
                    make_float2(acc2[nt][0] + m0v.x, acc2[nt][1] + m0v.y);
                *(float2*)(O + (long long)row1 * DH + cc) =
                    make_float2(acc2[nt][2] + m1v.x, acc2[nt][3] + m1v.y);
            }
            if (t == 0) {
                PMAX[pb + row0] = gm0; PMAX[pb + row1] = gm1;
                PSUM[pb + row0] = gs0; PSUM[pb + row1] = gs1;
            }
        }
    }
}

// ---------------- combine chunk partials -> a3v ----------------
__global__ void sav_combine(const float* __restrict__ pacc, const float* __restrict__ pmax,
                            const float* __restrict__ psum, float* __restrict__ out)
{
    int idx = blockIdx.x * 256 + threadIdx.x;
    int d = idx & 63;
    int m = (idx >> 6) & (LM - 1);
    int bh = idx >> 14;
    float gmax = -1e30f;
#pragma unroll
    for (int ck = 0; ck < NCHUNK; ++ck)
        gmax = fmaxf(gmax, pmax[((long long)bh * NCHUNK + ck) * LM + m]);
    float gsum = 0.f, val = 0.f;
#pragma unroll
    for (int ck = 0; ck < NCHUNK; ++ck) {
        long long pb = ((long long)bh * NCHUNK + ck) * LM + m;
        float f = __expf(pmax[pb] - gmax);
        gsum += psum[pb] * f;
        val  += pacc[pb * DH + d] * f;
    }
    out[idx] = val / gsum;
}

// ---------------- row softmax ----------------
__global__ void softmax_rows(float* __restrict__ S)
{
    float* row = S + (long long)blockIdx.x * 256;
    int tid = threadIdx.x;
    float v = row[tid];
    __shared__ float red[256];
    red[tid] = v; __syncthreads();
    for (int t = 128; t > 0; t >>= 1) {
        if (tid < t) red[tid] = fmaxf(red[tid], red[tid + t]);
        __syncthreads();
    }
    float mx = red[0]; __syncthreads();
    v = __expf(v - mx);
    red[tid] = v; __syncthreads();
    for (int t = 128; t > 0; t >>= 1) {
        if (tid < t) red[tid] += red[tid + t];
        __syncthreads();
    }
    row[tid] = v / red[0];
}

// ---------------- pinv scale ----------------
__global__ void col_max(const float* __restrict__ A2, float* __restrict__ s)
{
    int bh = blockIdx.x, j = threadIdx.x;
    const float* X = A2 + (long long)bh * LM * LM;
    float cs = 0.f;
    for (int i = 0; i < LM; ++i) cs += X[i * LM + j];
    __shared__ float r1[256];
    r1[j] = cs; __syncthreads();
    for (int t = 128; t > 0; t >>= 1) {
        if (j < t) r1[j] = fmaxf(r1[j], r1[j + t]);
        __syncthreads();
    }
    if (j == 0) s[bh] = r1[0];
}

__global__ void make_z0(const float* __restrict__ A2, const float* __restrict__ s,
                        float* __restrict__ Z)
{
    __shared__ float red[32];
    int tid = threadIdx.x;
    if (tid < 32) red[tid] = s[tid];
    __syncthreads();
    float cm = red[0];
#pragma unroll
    for (int i = 1; i < 32; ++i) cm = fmaxf(cm, red[i]);
    float inv = 1.f / cm;
    long long idx = (long long)blockIdx.x * 256 + tid;
    int c  = idx & 255;
    int r  = (int)((idx >> 8) & 255);
    int bh = (int)(idx >> 16);
    Z[idx] = A2[(long long)bh * LM * LM + (long long)c * LM + r] * inv;
}

// ---------------- host driver ----------------
extern "C" void kernel_launch(void* const* d_in, const int* in_sizes, int n_in,
                              void* d_out, int out_size)
{
    const float* x      = (const float*)d_in[0];
    const float* ln_w   = (const float*)d_in[1];
    const float* ln_b   = (const float*)d_in[2];
    const float* w_qkv  = (const float*)d_in[3];
    const float* w_out  = (const float*)d_in[4];
    const float* b_out  = (const float*)d_in[5];
    const float* conv_w = (const float*)d_in[6];
    float* out = (float*)d_out;

    static cudaStream_t s1 = nullptr;
    static cudaEvent_t evFork0 = nullptr, evFork = nullptr, evJoin = nullptr, evCvt = nullptr;
    if (s1 == nullptr) {
        cudaStreamCreateWithFlags(&s1, cudaStreamNonBlocking);
        cudaEventCreateWithFlags(&evFork0, cudaEventDisableTiming);
        cudaEventCreateWithFlags(&evFork, cudaEventDisableTiming);
        cudaEventCreateWithFlags(&evJoin, cudaEventDisableTiming);
        cudaEventCreateWithFlags(&evCvt, cudaEventDisableTiming);
    }

    void *p;
    cudaGetSymbolAddress(&p, g_xnb);   bf16* XNB = (bf16*)p;
    cudaGetSymbolAddress(&p, g_xnlb);  bf16* XNLB= (bf16*)p;
    cudaGetSymbolAddress(&p, g_wqkvb); bf16* WQB = (bf16*)p;
    cudaGetSymbolAddress(&p, g_woutb); bf16* WOB = (bf16*)p;
    cudaGetSymbolAddress(&p, g_qb);    bf16* Qb  = (bf16*)p;
    cudaGetSymbolAddress(&p, g_kb);    bf16* Kb  = (bf16*)p;
    cudaGetSymbolAddress(&p, g_vb);    bf16* Vb  = (bf16*)p;
    cudaGetSymbolAddress(&p, g_ql);    float* QL = (float*)p;
    cudaGetSymbolAddress(&p, g_kl);    float* KL = (float*)p;
    cudaGetSymbolAddress(&p, g_qlb);   bf16* QLb = (bf16*)p;
    cudaGetSymbolAddress(&p, g_klb);   bf16* KLb = (bf16*)p;
    cudaGetSymbolAddress(&p, g_attn2); float* A2 = (float*)p;
    cudaGetSymbolAddress(&p, g_za);    float* ZA = (float*)p;
    cudaGetSymbolAddress(&p, g_zb);    float* ZB = (float*)p;
    cudaGetSymbolAddress(&p, g_xz);    float* XZ = (float*)p;
    cudaGetSymbolAddress(&p, g_t1);    float* T1 = (float*)p;
    cudaGetSymbolAddress(&p, g_t2);    float* T2 = (float*)p;
    cudaGetSymbolAddress(&p, g_a3v);   float* A3V= (float*)p;
    cudaGetSymbolAddress(&p, g_zavb);  bf16* ZAVb= (bf16*)p;
    cudaGetSymbolAddress(&p, g_tokb);  bf16* TOKb= (bf16*)p;
    cudaGetSymbolAddress(&p, g_pacc);  float* PAC= (float*)p;
    cudaGetSymbolAddress(&p, g_pmax);  float* PMX= (float*)p;
    cudaGetSymbolAddress(&p, g_psum);  float* PSM= (float*)p;
    cudaGetSymbolAddress(&p, g_scale); float* S  = (float*)p;

    const long long sL  = (long long)LM * DH;
    const long long sA2 = (long long)LM * LM;

    const int bf_smem = 3 * (128*72 + 128*72) * 2;
    cudaFuncSetAttribute(gemm_bf<128,128,2,4,0>, cudaFuncAttributeMaxDynamicSharedMemorySize, bf_smem);
    cudaFuncSetAttribute(gemm_bf<128,128,2,4,1>, cudaFuncAttributeMaxDynamicSharedMemorySize, bf_smem);
    cudaFuncSetAttribute(gemm_bf<128,128,2,4,3>, cudaFuncAttributeMaxDynamicSharedMemorySize, bf_smem);
    cudaFuncSetAttribute(fused_sav<true>,  cudaFuncAttributeMaxDynamicSharedMemorySize, SAV_SMEM_BYTES);
    cudaFuncSetAttribute(fused_sav<false>, cudaFuncAttributeMaxDynamicSharedMemorySize, SAV_SMEM_BYTES);

    // ---- prefix: fork s1 first (capture-legal), converts overlap LN ----
    cudaEventRecord(evFork0, 0);
    cudaStreamWaitEvent(s1, evFork0, 0);
    cvt_bf<<<(3*DMODEL*DMODEL/2 + 255)/256, 256, 0, s1>>>(w_qkv, WQB, 3*DMODEL*DMODEL/2);
    cvt_bf<<<(DMODEL*DMODEL/2 + 255)/256, 256, 0, s1>>>(w_out, WOB, DMODEL*DMODEL/2);
    cudaEventRecord(evCvt, s1);
    ln_group<<<NGRP, 256>>>(x, ln_w, ln_b, XNB, XNLB);
    cudaStreamWaitEvent(0, evCvt, 0);
    gemm_bf<128,128,2,4,3><<<dim3(8, 8, 1), 256, bf_smem>>>(XNLB, WQB, nullptr,
        NGRP, 2*DMODEL, DMODEL, nullptr, nullptr, QL, KL, QLb, KLb, nullptr);

    // ---- fork: branch A (serial pinv chain, tf32) on s1 ----
    cudaEventRecord(evFork, 0);
    cudaStreamWaitEvent(s1, evFork, 0);
    gemm_tc<64,64,2,2,true,0><<<dim3(4, 4, BH), 128, 0, s1>>>(QL, KL, A2,
        LM, LM, DH, sL, sL, sA2, 1.f, 0.f, nullptr, 0.f, nullptr);
    softmax_rows<<<BH*LM, 256, 0, s1>>>(A2);
    col_max<<<BH, 256, 0, s1>>>(A2, S);
    make_z0<<<(BH*LM*LM)/256, 256, 0, s1>>>(A2, S, ZA);
    float* Zin = ZA; float* Zout = ZB;
    for (int it = 0; it < 6; ++it) {
        gemm_tc<64,64,2,2,false,2><<<dim3(4,4,BH), 128, 0, s1>>>(A2, Zin, XZ,
            LM, LM, LM, sA2, sA2, sA2, 1.f, 0.f, T1, 7.f, nullptr);
        gemm_tc<64,64,2,2,false,0><<<dim3(4,4,BH), 128, 0, s1>>>(XZ, T1, T2,
            LM, LM, LM, sA2, sA2, sA2, -1.f, 15.f, nullptr, 0.f, nullptr);
        gemm_tc<64,64,2,2,false,0><<<dim3(4,4,BH), 128, 0, s1>>>(XZ, T2, T1,
            LM, LM, LM, sA2, sA2, sA2, -1.f, 13.f, nullptr, 0.f, nullptr);
        gemm_tc<64,64,2,2,false,0><<<dim3(4,4,BH), 128, 0, s1>>>(Zin, T1, Zout,
            LM, LM, LM, sA2, sA2, sA2, 0.25f, 0.f, nullptr, 0.f, nullptr);
        float* tmp = Zin; Zin = Zout; Zout = tmp;
    }
    cudaEventRecord(evJoin, s1);

    // ---- branch B (bf16, throughput-bound) on stream 0 ----
    gemm_bf<128,128,2,4,1><<<dim3(12, 256, 1), 256, bf_smem>>>(XNB, WQB, nullptr,
        NTOK, 3*DMODEL, DMODEL, nullptr, nullptr, nullptr, nullptr, Qb, Kb, Vb);
    fused_sav<false><<<dim3(LM/64, NCHUNK, BH), 256, SAV_SMEM_BYTES>>>(QLb, Kb, Vb,
        PAC, PMX, PSM, LM, SEQ, SEQ/NCHUNK, nullptr, nullptr, nullptr);
    sav_combine<<<(BH*LM*DH)/256, 256>>>(PAC, PMX, PSM, A3V);

    // ---- join ----
    cudaStreamWaitEvent(0, evJoin, 0);
    gemm_tc<64,64,2,2,false,4><<<dim3(1, 4, BH), 128>>>(Zin, A3V, nullptr,
        LM, DH, LM, sA2, sL, sL, 1.f, 0.f, nullptr, 0.f, (float*)ZAVb);
    fused_sav<true><<<dim3(SEQ/64, 1, BH), 256, SAV_SMEM_BYTES>>>(Qb, KLb, ZAVb,
        nullptr, nullptr, nullptr, SEQ, LM, LM, Vb, conv_w, TOKb);
    gemm_bf<128,128,2,4,0><<<dim3(4, 256, 1), 256, bf_smem>>>(TOKb, WOB, out,
        NTOK, DMODEL, DMODEL, b_out, x, nullptr, nullptr, nullptr, nullptr, nullptr);
}